// round 4
// baseline (speedup 1.0000x reference)
#include <cuda_runtime.h>
#include <cuda_bf16.h>
#include <float.h>
#include <math.h>

#define BB   2
#define NN   4096
#define DD   384
#define HH   6
#define KNN  8
#define CH   387
#define ROWS (BB*NN)

typedef unsigned long long u64;

// ------------------------- scratch (static device mem) ----------------------
__device__ float g_tmp  [ROWS*DD];
__device__ float g_nf   [ROWS*DD];
__device__ float g_qkv  [ROWS*3*DD];
__device__ float g_s    [201326592];   // B*H*N*N scores
__device__ float g_attn [ROWS*DD];
__device__ float g_attnp[ROWS*DD];
__device__ float g_ka   [ROWS*2*DD];   // [ U=nf@Wtop | C=nf@(Wbot-Wtop)+b ]
__device__ float g_geom [ROWS*DD];
__device__ float g_m    [ROWS*DD];
__device__ float g_y    [ROWS*DD];
__device__ float g_h    [ROWS*2*DD];
__device__ float g_fout [ROWS*DD];
__device__ float g_wc   [DD*2*DD];
__device__ float g_kbias[2*DD];
__device__ float g_sq   [ROWS];
__device__ int   g_idx  [ROWS*KNN];

// ------------------------------ helpers -------------------------------------
__device__ __forceinline__ u64 pack2(float lo, float hi){
    u64 r; asm("mov.b64 %0, {%1, %2};" : "=l"(r) : "f"(lo), "f"(hi)); return r;
}
__device__ __forceinline__ void ffma2(u64 &d, u64 a, u64 b){
    asm("fma.rn.f32x2 %0, %1, %2, %0;" : "+l"(d) : "l"(a), "l"(b));
}
__device__ __forceinline__ float2 unpack2(u64 v){
    float lo, hi; asm("mov.b64 {%0, %1}, %2;" : "=f"(lo), "=f"(hi) : "l"(v));
    return make_float2(lo, hi);
}
__device__ __forceinline__ float block_sum(float v, float* sb){
    #pragma unroll
    for (int o=16;o>0;o>>=1) v += __shfl_xor_sync(0xffffffffu, v, o);
    int lane = threadIdx.x & 31, w = threadIdx.x >> 5, nw = blockDim.x >> 5;
    if (lane==0) sb[w] = v;
    __syncthreads();
    if (w==0){
        float x = (lane < nw) ? sb[lane] : 0.f;
        #pragma unroll
        for (int o=16;o>0;o>>=1) x += __shfl_xor_sync(0xffffffffu, x, o);
        if (lane==0) sb[0] = x;
    }
    __syncthreads();
    float r = sb[0]; __syncthreads(); return r;
}
__device__ __forceinline__ float block_max(float v, float* sb){
    #pragma unroll
    for (int o=16;o>0;o>>=1) v = fmaxf(v, __shfl_xor_sync(0xffffffffu, v, o));
    int lane = threadIdx.x & 31, w = threadIdx.x >> 5, nw = blockDim.x >> 5;
    if (lane==0) sb[w] = v;
    __syncthreads();
    if (w==0){
        float x = (lane < nw) ? sb[lane] : -FLT_MAX;
        #pragma unroll
        for (int o=16;o>0;o>>=1) x = fmaxf(x, __shfl_xor_sync(0xffffffffu, x, o));
        if (lane==0) sb[0] = x;
    }
    __syncthreads();
    float r = sb[0]; __syncthreads(); return r;
}

// ------------------------------ prep / misc ----------------------------------
__global__ void copy_coords(const float* __restrict__ pts, float* __restrict__ outp){
    int i = blockIdx.x*blockDim.x + threadIdx.x;
    if (i < BB*3*NN){
        int b = i / (3*NN), r = i % (3*NN);
        outp[(size_t)b*CH*NN + r] = pts[(size_t)b*CH*NN + r];
    }
}
__global__ void prep_kernel(const float* __restrict__ knn_w, const float* __restrict__ knn_b){
    int i = blockIdx.x*blockDim.x + threadIdx.x;
    if (i < DD*2*DD){
        int r = i / (2*DD), c = i % (2*DD);
        float v;
        if (c < DD) v = knn_w[r*DD + c];
        else { int cc = c - DD; v = knn_w[(DD + r)*DD + cc] - knn_w[r*DD + cc]; }
        g_wc[i] = v;
    }
    if (i < 2*DD) g_kbias[i] = (i < DD) ? 0.f : knn_b[i-DD];
}
__global__ void sq_kernel(const float* __restrict__ pts){
    int i = blockIdx.x*blockDim.x + threadIdx.x;
    if (i < ROWS){
        int b = i >> 12, n = i & 4095;
        const float* base = pts + (size_t)b*CH*NN;
        float x = base[n], y = base[NN+n], z = base[2*NN+n];
        g_sq[i] = x*x + y*y + z*z;
    }
}
__global__ void transpose_in(const float* __restrict__ pts, float* __restrict__ dst){
    __shared__ float tile[32][33];
    int b = blockIdx.z, n0 = blockIdx.x*32, d0 = blockIdx.y*32;
    const float* src = pts + (size_t)b*CH*NN;
    for (int r = threadIdx.y; r < 32; r += 8)
        tile[r][threadIdx.x] = src[(size_t)(3+d0+r)*NN + n0 + threadIdx.x];
    __syncthreads();
    float* o = dst + (size_t)b*NN*DD;
    for (int r = threadIdx.y; r < 32; r += 8)
        o[(size_t)(n0+r)*DD + d0 + threadIdx.x] = tile[threadIdx.x][r];
}
__global__ void transpose_out(const float* __restrict__ fin, float* __restrict__ outp){
    __shared__ float tile[32][33];
    int b = blockIdx.z, n0 = blockIdx.x*32, d0 = blockIdx.y*32;
    const float* src = fin + (size_t)b*NN*DD;
    for (int r = threadIdx.y; r < 32; r += 8)
        tile[r][threadIdx.x] = src[(size_t)(n0+r)*DD + d0 + threadIdx.x];
    __syncthreads();
    float* dst = outp + (size_t)b*CH*NN;
    for (int r = threadIdx.y; r < 32; r += 8)
        dst[(size_t)(3+d0+r)*NN + n0 + threadIdx.x] = tile[threadIdx.x][r];
}
__global__ void ln_rows(const float* __restrict__ in,
                        const float* __restrict__ gam, const float* __restrict__ bet,
                        float* __restrict__ outp){
    __shared__ float sb[8];
    int row = blockIdx.x, tid = threadIdx.x;   // 128 threads
    const float* x = in + (size_t)row*DD;
    float v[3]; float s = 0.f;
    #pragma unroll
    for (int i=0;i<3;i++){ v[i] = x[tid + i*128]; s += v[i]; }
    s = block_sum(s, sb);
    float mean = s * (1.0f/DD), q = 0.f;
    #pragma unroll
    for (int i=0;i<3;i++){ float c = v[i]-mean; q += c*c; }
    q = block_sum(q, sb);
    float rinv = rsqrtf(q*(1.0f/DD) + 1e-5f);
    #pragma unroll
    for (int i=0;i<3;i++){
        int d = tid + i*128;
        outp[(size_t)row*DD + d] = (v[i]-mean)*rinv*gam[d] + bet[d];
    }
}

// ------------------------------ SGEMM ----------------------------------------
// C = scale*(A@B) [+bias][+gelu][+res].  A split at ksplit (A0|A1), row-major.
// EPI: 0 none, 1 bias, 2 bias+gelu, 3 bias+res
template<int BM,int BN,int BK,int TM,int TN,bool TRANSB,int EPI>
__global__ void __launch_bounds__(256)
sgemm_k(const float* __restrict__ A0, const float* __restrict__ A1, int ksplit,
        const float* __restrict__ Bm, float* __restrict__ Cm,
        const float* __restrict__ bias, const float* __restrict__ res,
        int Kk, int lda, int ldb, int ldc, int Hdiv,
        long long saB, long long saH, long long sbB, long long sbH,
        long long scB, long long scH, float scale)
{
    constexpr int NTX = BN/TN;
    __shared__ __align__(16) float As[BK][BM];
    __shared__ __align__(16) float Bs[BK][BN];

    int z  = blockIdx.z;
    int zb = z / Hdiv, zh = z - zb*Hdiv;
    A0 += zb*saB + zh*saH;  A1 += zb*saB + zh*saH;
    Bm += zb*sbB + zh*sbH;  Cm += zb*scB + zh*scH;

    int m0 = blockIdx.y * BM, n0 = blockIdx.x * BN;
    int tid = threadIdx.x;
    int tx = tid % NTX, ty = tid / NTX;

    u64 acc[TM/2][TN];
    #pragma unroll
    for (int i=0;i<TM/2;i++)
        #pragma unroll
        for (int j=0;j<TN;j++) acc[i][j] = 0ull;

    int arow = tid >> 2, acol = (tid & 3) << 2;

    for (int k0 = 0; k0 < Kk; k0 += BK){
        #pragma unroll
        for (int p=0; p<BM/64; p++){
            int r  = arow + p*64, kg = k0 + acol;
            const float* src = (kg < ksplit)
                ? A0 + (size_t)(m0+r)*lda + kg
                : A1 + (size_t)(m0+r)*lda + (kg - ksplit);
            float4 va = *(const float4*)src;
            As[acol+0][r]=va.x; As[acol+1][r]=va.y;
            As[acol+2][r]=va.z; As[acol+3][r]=va.w;
        }
        if (!TRANSB){
            constexpr int RP = 256/(BN/4);
            int bk = tid / (BN/4), bn = (tid % (BN/4))*4;
            #pragma unroll
            for (int p=0;p<BK/RP;p++){
                int r = bk + p*RP;
                float4 vb = *(const float4*)(Bm + (size_t)(k0+r)*ldb + n0 + bn);
                Bs[r][bn+0]=vb.x; Bs[r][bn+1]=vb.y;
                Bs[r][bn+2]=vb.z; Bs[r][bn+3]=vb.w;
            }
        } else {
            int bn = tid >> 2, bkc = (tid & 3) << 2;
            #pragma unroll
            for (int p=0;p<BN/64;p++){
                int r = bn + p*64;
                float4 vb = *(const float4*)(Bm + (size_t)(n0+r)*ldb + k0 + bkc);
                Bs[bkc+0][r]=vb.x; Bs[bkc+1][r]=vb.y;
                Bs[bkc+2][r]=vb.z; Bs[bkc+3][r]=vb.w;
            }
        }
        __syncthreads();

        #pragma unroll
        for (int k=0;k<BK;k++){
            u64 ra[TM/2];
            const u64* As2 = (const u64*)&As[k][ty*TM];
            #pragma unroll
            for (int i=0;i<TM/2;i++) ra[i] = As2[i];
            float rbf[TN];
            const float4* Bs4 = (const float4*)&Bs[k][tx*TN];
            #pragma unroll
            for (int j=0;j<TN/4;j++){
                float4 t = Bs4[j];
                rbf[j*4+0]=t.x; rbf[j*4+1]=t.y; rbf[j*4+2]=t.z; rbf[j*4+3]=t.w;
            }
            #pragma unroll
            for (int j=0;j<TN;j++){
                u64 rb = pack2(rbf[j], rbf[j]);
                #pragma unroll
                for (int i=0;i<TM/2;i++) ffma2(acc[i][j], ra[i], rb);
            }
        }
        __syncthreads();
    }

    float cv[TM][TN];
    #pragma unroll
    for (int i=0;i<TM/2;i++)
        #pragma unroll
        for (int j=0;j<TN;j++){
            float2 t = unpack2(acc[i][j]);
            cv[2*i][j]   = t.x*scale;
            cv[2*i+1][j] = t.y*scale;
        }
    #pragma unroll
    for (int i=0;i<TM;i++){
        int row = m0 + ty*TM + i;
        #pragma unroll
        for (int j=0;j<TN;j+=4){
            int col = n0 + tx*TN + j;
            float vv[4];
            #pragma unroll
            for (int q=0;q<4;q++){
                float v = cv[i][j+q];
                if (EPI >= 1) v += bias[col+q];
                if (EPI == 2) v = 0.5f*v*(1.0f + erff(v*0.70710678118654752f));
                vv[q] = v;
            }
            if (EPI == 3){
                float4 rr = *(const float4*)(res + (size_t)row*ldc + col);
                vv[0]+=rr.x; vv[1]+=rr.y; vv[2]+=rr.z; vv[3]+=rr.w;
            }
            float4 o; o.x=vv[0]; o.y=vv[1]; o.z=vv[2]; o.w=vv[3];
            *(float4*)(Cm + (size_t)row*ldc + col) = o;
        }
    }
}

// ------------------------------ softmax --------------------------------------
__global__ void __launch_bounds__(256) softmax_rows(float* __restrict__ S){
    __shared__ float sb[8];
    size_t row = blockIdx.x;
    float* p = S + row*(size_t)NN;
    int tid = threadIdx.x;
    float v[16]; float mx = -FLT_MAX;
    #pragma unroll
    for (int i=0;i<16;i++){ v[i] = p[tid + i*256]; mx = fmaxf(mx, v[i]); }
    mx = block_max(mx, sb);
    float s = 0.f;
    #pragma unroll
    for (int i=0;i<16;i++){ v[i] = __expf(v[i]-mx); s += v[i]; }
    s = block_sum(s, sb);
    float inv = 1.0f/s;
    #pragma unroll
    for (int i=0;i<16;i++) p[tid + i*256] = v[i]*inv;
}

// ------------------------------ KNN (top-8) ----------------------------------
__global__ void __launch_bounds__(256)
knn_kernel(const float* __restrict__ pts){
    __shared__ u64 sk[256*KNN];
    int row = blockIdx.x;
    int b = row >> 12, n = row & 4095;
    const float* base = pts + (size_t)b*CH*NN;
    float qx = base[n], qy = base[NN+n], qz = base[2*NN+n];
    float sqn = g_sq[row];
    const float* sqb = g_sq + (size_t)b*NN;

    u64 key[KNN];
    #pragma unroll
    for (int j=0;j<KNN;j++) key[j] = ~0ull;

    for (int m = threadIdx.x; m < NN; m += 256){
        float d2 = sqn + sqb[m]
                 - 2.0f*(qx*base[m] + qy*base[NN+m] + qz*base[2*NN+m]);
        d2 = fmaxf(d2, 0.0f);
        u64 kk = ((u64)__float_as_uint(d2) << 32) | (unsigned)m;
        if (kk < key[KNN-1]){
            key[KNN-1] = kk;
            #pragma unroll
            for (int j=KNN-1;j>0;j--){
                u64 a = key[j-1], c = key[j];
                key[j-1] = (c < a) ? c : a;
                key[j]   = (c < a) ? a : c;
            }
        }
    }
    #pragma unroll
    for (int j=0;j<KNN;j++) sk[threadIdx.x*KNN+j] = key[j];

    for (int s=128; s>0; s>>=1){
        __syncthreads();
        if ((int)threadIdx.x < s){
            int pa = threadIdx.x*KNN, pb = (threadIdx.x+s)*KNN;
            u64 outk[KNN]; int ia=0, ib=0;
            #pragma unroll
            for (int r=0;r<KNN;r++){
                u64 va = sk[pa+ia], vb = sk[pb+ib];
                if (va <= vb){ outk[r]=va; ia++; } else { outk[r]=vb; ib++; }
            }
            #pragma unroll
            for (int r=0;r<KNN;r++) sk[pa+r] = outk[r];
        }
    }
    __syncthreads();
    if (threadIdx.x < KNN)
        g_idx[(size_t)row*KNN + threadIdx.x] = (int)(unsigned)(sk[threadIdx.x] & 0xffffffffu);
}

// ------------------------- gather + lrelu + max ------------------------------
__global__ void __launch_bounds__(128) geom_kernel(void){
    __shared__ int sidx[KNN];
    int row = blockIdx.x, tid = threadIdx.x;
    int gb = row >> 12;
    if (tid < KNN) sidx[tid] = gb*NN + g_idx[(size_t)row*KNN + tid];
    __syncthreads();
    #pragma unroll
    for (int i=0;i<3;i++){
        int d = tid + i*128;
        float c = g_ka[(size_t)row*(2*DD) + DD + d];
        float mx = -FLT_MAX;
        #pragma unroll
        for (int k=0;k<KNN;k++){
            float v = g_ka[(size_t)sidx[k]*(2*DD) + d] + c;
            v = (v > 0.f) ? v : 0.2f*v;
            mx = fmaxf(mx, v);
        }
        g_geom[(size_t)row*DD + d] = mx;
    }
}

// ------------------------------ launch ---------------------------------------
extern "C" void kernel_launch(void* const* d_in, const int* in_sizes, int n_in,
                              void* d_out, int out_size) {
    const float* pts        = (const float*)d_in[0];
    const float* ln1_g      = (const float*)d_in[1];
    const float* ln1_b      = (const float*)d_in[2];
    const float* qkv_w      = (const float*)d_in[3];
    const float* attn_out_w = (const float*)d_in[4];
    const float* attn_out_b = (const float*)d_in[5];
    const float* knn_w      = (const float*)d_in[6];
    const float* knn_b      = (const float*)d_in[7];
    const float* merge_w    = (const float*)d_in[8];
    const float* merge_b    = (const float*)d_in[9];
    const float* ln2_g      = (const float*)d_in[10];
    const float* ln2_b      = (const float*)d_in[11];
    const float* ff1_w      = (const float*)d_in[12];
    const float* ff1_b      = (const float*)d_in[13];
    const float* ff2_w      = (const float*)d_in[14];
    const float* ff2_b      = (const float*)d_in[15];
    float* outp = (float*)d_out;

    float *p_tmp,*p_nf,*p_qkv,*p_s,*p_attn,*p_attnp,*p_ka,*p_geom,*p_m,*p_y,*p_h,*p_fout,*p_wc,*p_kb;
    cudaGetSymbolAddress((void**)&p_tmp,  g_tmp);
    cudaGetSymbolAddress((void**)&p_nf,   g_nf);
    cudaGetSymbolAddress((void**)&p_qkv,  g_qkv);
    cudaGetSymbolAddress((void**)&p_s,    g_s);
    cudaGetSymbolAddress((void**)&p_attn, g_attn);
    cudaGetSymbolAddress((void**)&p_attnp,g_attnp);
    cudaGetSymbolAddress((void**)&p_ka,   g_ka);
    cudaGetSymbolAddress((void**)&p_geom, g_geom);
    cudaGetSymbolAddress((void**)&p_m,    g_m);
    cudaGetSymbolAddress((void**)&p_y,    g_y);
    cudaGetSymbolAddress((void**)&p_h,    g_h);
    cudaGetSymbolAddress((void**)&p_fout, g_fout);
    cudaGetSymbolAddress((void**)&p_wc,   g_wc);
    cudaGetSymbolAddress((void**)&p_kb,   g_kbias);

    dim3 t328(32,8);
    // feats transpose + LN1
    transpose_in<<<dim3(NN/32, DD/32, BB), t328>>>(pts, p_tmp);
    ln_rows<<<ROWS,128>>>(p_tmp, ln1_g, ln1_b, p_nf);
    prep_kernel<<<(DD*2*DD+255)/256,256>>>(knn_w, knn_b);
    sq_kernel<<<(ROWS+255)/256,256>>>(pts);

    // QKV: (8192x384)@(384x1152)
    sgemm_k<128,128,16,8,8,false,0><<<dim3(9,64,1),256>>>(
        p_nf,p_nf,DD, qkv_w, p_qkv, nullptr,nullptr,
        DD, DD, 3*DD, 3*DD, 1, 0,0, 0,0, 0,0, 1.0f);

    // scores = Q K^T / 8   per (b,h)
    sgemm_k<128,128,16,8,8,true,0><<<dim3(32,32,BB*HH),256>>>(
        p_qkv, p_qkv, 64, p_qkv + DD, p_s, nullptr,nullptr,
        64, 3*DD, 3*DD, NN, HH,
        (long long)NN*3*DD, 64, (long long)NN*3*DD, 64,
        (long long)HH*NN*NN, (long long)NN*NN, 0.125f);

    softmax_rows<<<BB*HH*NN,256>>>(p_s);

    // attn = S @ V  per (b,h), write head-merged (b,n,384)
    sgemm_k<128,64,16,8,4,false,0><<<dim3(1,32,BB*HH),256>>>(
        p_s, p_s, NN, p_qkv + 2*DD, p_attn, nullptr,nullptr,
        NN, NN, 3*DD, DD, HH,
        (long long)HH*NN*NN, (long long)NN*NN,
        (long long)NN*3*DD, 64,
        (long long)NN*DD, 64, 1.0f);

    // attn projection
    sgemm_k<128,128,16,8,8,false,1><<<dim3(3,64,1),256>>>(
        p_attn,p_attn,DD, attn_out_w, p_attnp, attn_out_b,nullptr,
        DD, DD, DD, DD, 1, 0,0, 0,0, 0,0, 1.0f);

    // KNN + factored edge-MLP
    knn_kernel<<<ROWS,256>>>(pts);
    sgemm_k<128,128,16,8,8,false,1><<<dim3(6,64,1),256>>>(
        p_nf,p_nf,DD, p_wc, p_ka, p_kb,nullptr,
        DD, DD, 2*DD, 2*DD, 1, 0,0, 0,0, 0,0, 1.0f);
    geom_kernel<<<ROWS,128>>>();

    // merge: concat([attnp, geom]) @ merge_w + b + attnp
    sgemm_k<128,128,16,8,8,false,3><<<dim3(3,64,1),256>>>(
        p_attnp, p_geom, DD, merge_w, p_m, merge_b, p_attnp,
        2*DD, DD, DD, DD, 1, 0,0, 0,0, 0,0, 1.0f);

    // LN2
    ln_rows<<<ROWS,128>>>(p_m, ln2_g, ln2_b, p_y);

    // FFN
    sgemm_k<128,128,16,8,8,false,2><<<dim3(6,64,1),256>>>(
        p_y,p_y,DD, ff1_w, p_h, ff1_b,nullptr,
        DD, DD, 2*DD, 2*DD, 1, 0,0, 0,0, 0,0, 1.0f);
    sgemm_k<128,128,16,8,8,false,3><<<dim3(3,64,1),256>>>(
        p_h,p_h,2*DD, ff2_w, p_fout, ff2_b, p_y,
        2*DD, 2*DD, DD, DD, 1, 0,0, 0,0, 0,0, 1.0f);

    // assemble output
    copy_coords<<<(BB*3*NN+255)/256,256>>>(pts, outp);
    transpose_out<<<dim3(NN/32, DD/32, BB), t328>>>(p_fout, outp);
}

// round 5
// speedup vs baseline: 1.0605x; 1.0605x over previous
#include <cuda_runtime.h>
#include <cuda_bf16.h>
#include <float.h>
#include <math.h>

#define BB   2
#define NN   4096
#define DD   384
#define HH   6
#define KNN  8
#define CH   387
#define ROWS (BB*NN)

typedef unsigned long long u64;
typedef unsigned int u32;

// ------------------------- scratch (static device mem) ----------------------
__device__ float g_tmp  [ROWS*DD];
__device__ float g_nf   [ROWS*DD];
__device__ float g_qkv  [ROWS*3*DD];
__device__ float g_s    [201326592];   // B*H*N*N scores
__device__ float g_attn [ROWS*DD];
__device__ float g_attnp[ROWS*DD];
__device__ float g_ka   [ROWS*2*DD];
__device__ float g_geom [ROWS*DD];
__device__ float g_m    [ROWS*DD];
__device__ float g_y    [ROWS*DD];
__device__ float g_h    [ROWS*2*DD];
__device__ float g_fout [ROWS*DD];
__device__ float g_wc   [DD*2*DD];
__device__ float g_kbias[2*DD];
__device__ float g_sq   [ROWS];
__device__ int   g_idx  [ROWS*KNN];

// ------------------------------ helpers -------------------------------------
__device__ __forceinline__ float block_sum(float v, float* sb){
    #pragma unroll
    for (int o=16;o>0;o>>=1) v += __shfl_xor_sync(0xffffffffu, v, o);
    int lane = threadIdx.x & 31, w = threadIdx.x >> 5, nw = blockDim.x >> 5;
    if (lane==0) sb[w] = v;
    __syncthreads();
    if (w==0){
        float x = (lane < nw) ? sb[lane] : 0.f;
        #pragma unroll
        for (int o=16;o>0;o>>=1) x += __shfl_xor_sync(0xffffffffu, x, o);
        if (lane==0) sb[0] = x;
    }
    __syncthreads();
    float r = sb[0]; __syncthreads(); return r;
}
__device__ __forceinline__ float block_max(float v, float* sb){
    #pragma unroll
    for (int o=16;o>0;o>>=1) v = fmaxf(v, __shfl_xor_sync(0xffffffffu, v, o));
    int lane = threadIdx.x & 31, w = threadIdx.x >> 5, nw = blockDim.x >> 5;
    if (lane==0) sb[w] = v;
    __syncthreads();
    if (w==0){
        float x = (lane < nw) ? sb[lane] : -FLT_MAX;
        #pragma unroll
        for (int o=16;o>0;o>>=1) x = fmaxf(x, __shfl_xor_sync(0xffffffffu, x, o));
        if (lane==0) sb[0] = x;
    }
    __syncthreads();
    float r = sb[0]; __syncthreads(); return r;
}
__device__ __forceinline__ u32 pk(__nv_bfloat16 a, __nv_bfloat16 b){
    return ((u32)__bfloat16_as_ushort(b) << 16) | (u32)__bfloat16_as_ushort(a);
}
__device__ __forceinline__ void mma16816(float* c, const u32* a, const u32* b){
    asm volatile(
        "mma.sync.aligned.m16n8k16.row.col.f32.bf16.bf16.f32 "
        "{%0,%1,%2,%3}, {%4,%5,%6,%7}, {%8,%9}, {%0,%1,%2,%3};"
        : "+f"(c[0]), "+f"(c[1]), "+f"(c[2]), "+f"(c[3])
        : "r"(a[0]), "r"(a[1]), "r"(a[2]), "r"(a[3]), "r"(b[0]), "r"(b[1]));
}

// ------------------------------ prep / misc ----------------------------------
__global__ void copy_coords(const float* __restrict__ pts, float* __restrict__ outp){
    int i = blockIdx.x*blockDim.x + threadIdx.x;
    if (i < BB*3*NN){
        int b = i / (3*NN), r = i % (3*NN);
        outp[(size_t)b*CH*NN + r] = pts[(size_t)b*CH*NN + r];
    }
}
__global__ void prep_kernel(const float* __restrict__ knn_w, const float* __restrict__ knn_b){
    int i = blockIdx.x*blockDim.x + threadIdx.x;
    if (i < DD*2*DD){
        int r = i / (2*DD), c = i % (2*DD);
        float v;
        if (c < DD) v = knn_w[r*DD + c];
        else { int cc = c - DD; v = knn_w[(DD + r)*DD + cc] - knn_w[r*DD + cc]; }
        g_wc[i] = v;
    }
    if (i < 2*DD) g_kbias[i] = (i < DD) ? 0.f : knn_b[i-DD];
}
__global__ void sq_kernel(const float* __restrict__ pts){
    int i = blockIdx.x*blockDim.x + threadIdx.x;
    if (i < ROWS){
        int b = i >> 12, n = i & 4095;
        const float* base = pts + (size_t)b*CH*NN;
        float x = base[n], y = base[NN+n], z = base[2*NN+n];
        g_sq[i] = x*x + y*y + z*z;
    }
}
__global__ void transpose_in(const float* __restrict__ pts, float* __restrict__ dst){
    __shared__ float tile[32][33];
    int b = blockIdx.z, n0 = blockIdx.x*32, d0 = blockIdx.y*32;
    const float* src = pts + (size_t)b*CH*NN;
    for (int r = threadIdx.y; r < 32; r += 8)
        tile[r][threadIdx.x] = src[(size_t)(3+d0+r)*NN + n0 + threadIdx.x];
    __syncthreads();
    float* o = dst + (size_t)b*NN*DD;
    for (int r = threadIdx.y; r < 32; r += 8)
        o[(size_t)(n0+r)*DD + d0 + threadIdx.x] = tile[threadIdx.x][r];
}
__global__ void transpose_out(const float* __restrict__ fin, float* __restrict__ outp){
    __shared__ float tile[32][33];
    int b = blockIdx.z, n0 = blockIdx.x*32, d0 = blockIdx.y*32;
    const float* src = fin + (size_t)b*NN*DD;
    for (int r = threadIdx.y; r < 32; r += 8)
        tile[r][threadIdx.x] = src[(size_t)(n0+r)*DD + d0 + threadIdx.x];
    __syncthreads();
    float* dst = outp + (size_t)b*CH*NN;
    for (int r = threadIdx.y; r < 32; r += 8)
        dst[(size_t)(3+d0+r)*NN + n0 + threadIdx.x] = tile[threadIdx.x][r];
}
__global__ void ln_rows(const float* __restrict__ in,
                        const float* __restrict__ gam, const float* __restrict__ bet,
                        float* __restrict__ outp){
    __shared__ float sb[8];
    int row = blockIdx.x, tid = threadIdx.x;   // 128 threads
    const float* x = in + (size_t)row*DD;
    float v[3]; float s = 0.f;
    #pragma unroll
    for (int i=0;i<3;i++){ v[i] = x[tid + i*128]; s += v[i]; }
    s = block_sum(s, sb);
    float mean = s * (1.0f/DD), q = 0.f;
    #pragma unroll
    for (int i=0;i<3;i++){ float c = v[i]-mean; q += c*c; }
    q = block_sum(q, sb);
    float rinv = rsqrtf(q*(1.0f/DD) + 1e-5f);
    #pragma unroll
    for (int i=0;i<3;i++){
        int d = tid + i*128;
        outp[(size_t)row*DD + d] = (v[i]-mean)*rinv*gam[d] + bet[d];
    }
}

// --------------------- bf16 split-precision tensor GEMM ----------------------
// C = scale*(A@B)[+bias][+gelu][+res].  A row-major split at ksplit (A0|A1).
// TRANSB: B accessed [n][k] (k contiguous); else [k][n].
// hi/lo split: acc += Ah*Bh + Ah*Bl + Al*Bh  (lo*lo dropped, ~2^-16 rel err).
// EPI: 0 none, 1 bias, 2 bias+gelu, 3 bias+res
template<int BM,int BN,bool TRANSB,int EPI>
__global__ void __launch_bounds__(256)
bgemm_k(const float* __restrict__ A0, const float* __restrict__ A1, int ksplit,
        const float* __restrict__ Bm, float* __restrict__ Cm,
        const float* __restrict__ bias, const float* __restrict__ res,
        int Kk, int lda, int ldb, int ldc, int Hdiv,
        long long saB, long long saH, long long sbB, long long sbH,
        long long scB, long long scH, float scale)
{
    constexpr int BK = 32, BKP = 40;      // +8 pad -> conflict-free frag LDS
    constexpr int TWM = 32, TWN = BN/2;   // warp grid 4(M) x 2(N)
    constexpr int FM = 2, FN = TWN/8;

    __shared__ __align__(16) __nv_bfloat16 Ah[BM*BKP], Al[BM*BKP];
    __shared__ __align__(16) __nv_bfloat16 Bh[BN*BKP], Bl[BN*BKP];

    int z  = blockIdx.z, zb = z / Hdiv, zh = z - zb*Hdiv;
    A0 += zb*saB + zh*saH;  A1 += zb*saB + zh*saH;
    Bm += zb*sbB + zh*sbH;  Cm += zb*scB + zh*scH;

    int m0 = blockIdx.y*BM, n0 = blockIdx.x*BN;
    int tid = threadIdx.x, lane = tid & 31, warp = tid >> 5;
    int wm = warp & 3, wn = warp >> 2;
    int g = lane >> 2, t4 = lane & 3;

    float acc[FM][FN][4];
    #pragma unroll
    for (int i=0;i<FM;i++)
        #pragma unroll
        for (int j=0;j<FN;j++)
            #pragma unroll
            for (int q=0;q<4;q++) acc[i][j][q] = 0.f;

    for (int k0 = 0; k0 < Kk; k0 += BK){
        // ---- A tile: BM x 32 fp32 -> bf16 hi/lo planes [m][k] ----
        {
            int r0 = tid >> 3, c4 = (tid & 7) * 4;
            #pragma unroll
            for (int p=0; p<BM/32; p++){
                int r = r0 + p*32, kg = k0 + c4;
                const float* src = (kg < ksplit)
                    ? A0 + (size_t)(m0+r)*lda + kg
                    : A1 + (size_t)(m0+r)*lda + (kg - ksplit);
                float4 v = *(const float4*)src;
                __nv_bfloat16 hx=__float2bfloat16(v.x), hy=__float2bfloat16(v.y);
                __nv_bfloat16 hz=__float2bfloat16(v.z), hw=__float2bfloat16(v.w);
                __nv_bfloat16 lx=__float2bfloat16(v.x-__bfloat162float(hx));
                __nv_bfloat16 ly=__float2bfloat16(v.y-__bfloat162float(hy));
                __nv_bfloat16 lz=__float2bfloat16(v.z-__bfloat162float(hz));
                __nv_bfloat16 lw=__float2bfloat16(v.w-__bfloat162float(hw));
                int base = r*BKP + c4;
                *(u32*)&Ah[base]   = pk(hx,hy);  *(u32*)&Ah[base+2] = pk(hz,hw);
                *(u32*)&Al[base]   = pk(lx,ly);  *(u32*)&Al[base+2] = pk(lz,lw);
            }
        }
        // ---- B tile -> bf16 hi/lo planes [n][k] ----
        if (TRANSB){
            int r0 = tid >> 3, c4 = (tid & 7) * 4;
            #pragma unroll
            for (int p=0; p<BN/32; p++){
                int r = r0 + p*32;
                float4 v = *(const float4*)(Bm + (size_t)(n0+r)*ldb + k0 + c4);
                __nv_bfloat16 hx=__float2bfloat16(v.x), hy=__float2bfloat16(v.y);
                __nv_bfloat16 hz=__float2bfloat16(v.z), hw=__float2bfloat16(v.w);
                __nv_bfloat16 lx=__float2bfloat16(v.x-__bfloat162float(hx));
                __nv_bfloat16 ly=__float2bfloat16(v.y-__bfloat162float(hy));
                __nv_bfloat16 lz=__float2bfloat16(v.z-__bfloat162float(hz));
                __nv_bfloat16 lw=__float2bfloat16(v.w-__bfloat162float(hw));
                int base = r*BKP + c4;
                *(u32*)&Bh[base]   = pk(hx,hy);  *(u32*)&Bh[base+2] = pk(hz,hw);
                *(u32*)&Bl[base]   = pk(lx,ly);  *(u32*)&Bl[base+2] = pk(lz,lw);
            }
        } else {
            constexpr int NB4 = BN/4, ITER = (BK*NB4)/256;
            #pragma unroll
            for (int it=0; it<ITER; it++){
                int idx = it*256 + tid;
                int kr = idx / NB4, n4 = (idx % NB4) * 4;
                float4 v = *(const float4*)(Bm + (size_t)(k0+kr)*ldb + n0 + n4);
                float vv[4] = {v.x, v.y, v.z, v.w};
                #pragma unroll
                for (int j=0;j<4;j++){
                    __nv_bfloat16 h = __float2bfloat16(vv[j]);
                    __nv_bfloat16 l = __float2bfloat16(vv[j] - __bfloat162float(h));
                    Bh[(n4+j)*BKP + kr] = h;
                    Bl[(n4+j)*BKP + kr] = l;
                }
            }
        }
        __syncthreads();

        #pragma unroll
        for (int kk=0; kk<BK; kk+=16){
            u32 ah[FM][4], al[FM][4], bh[FN][2], bl[FN][2];
            #pragma unroll
            for (int fm=0; fm<FM; fm++){
                int rb = (wm*TWM + fm*16 + g)*BKP + kk + 2*t4;
                ah[fm][0]=*(const u32*)&Ah[rb];
                ah[fm][1]=*(const u32*)&Ah[rb + 8*BKP];
                ah[fm][2]=*(const u32*)&Ah[rb + 8];
                ah[fm][3]=*(const u32*)&Ah[rb + 8*BKP + 8];
                al[fm][0]=*(const u32*)&Al[rb];
                al[fm][1]=*(const u32*)&Al[rb + 8*BKP];
                al[fm][2]=*(const u32*)&Al[rb + 8];
                al[fm][3]=*(const u32*)&Al[rb + 8*BKP + 8];
            }
            #pragma unroll
            for (int fn=0; fn<FN; fn++){
                int nb = (wn*TWN + fn*8 + g)*BKP + kk + 2*t4;
                bh[fn][0]=*(const u32*)&Bh[nb];
                bh[fn][1]=*(const u32*)&Bh[nb + 8];
                bl[fn][0]=*(const u32*)&Bl[nb];
                bl[fn][1]=*(const u32*)&Bl[nb + 8];
            }
            #pragma unroll
            for (int fm=0; fm<FM; fm++)
                #pragma unroll
                for (int fn=0; fn<FN; fn++){
                    mma16816(acc[fm][fn], ah[fm], bh[fn]);
                    mma16816(acc[fm][fn], ah[fm], bl[fn]);
                    mma16816(acc[fm][fn], al[fm], bh[fn]);
                }
        }
        __syncthreads();
    }

    // ---- epilogue ----
    #pragma unroll
    for (int fm=0; fm<FM; fm++){
        #pragma unroll
        for (int fn=0; fn<FN; fn++){
            int col = n0 + wn*TWN + fn*8 + 2*t4;
            #pragma unroll
            for (int half=0; half<2; half++){
                int row = m0 + wm*TWM + fm*16 + g + half*8;
                float v0 = acc[fm][fn][2*half+0]*scale;
                float v1 = acc[fm][fn][2*half+1]*scale;
                if (EPI >= 1){ v0 += bias[col]; v1 += bias[col+1]; }
                if (EPI == 2){
                    v0 = 0.5f*v0*(1.0f + erff(v0*0.70710678118654752f));
                    v1 = 0.5f*v1*(1.0f + erff(v1*0.70710678118654752f));
                }
                if (EPI == 3){
                    float2 rr = *(const float2*)(res + (size_t)row*ldc + col);
                    v0 += rr.x; v1 += rr.y;
                }
                float2 o; o.x=v0; o.y=v1;
                *(float2*)(Cm + (size_t)row*ldc + col) = o;
            }
        }
    }
}

// ------------------------------ softmax --------------------------------------
__global__ void __launch_bounds__(256) softmax_rows(float* __restrict__ S){
    __shared__ float sb[8];
    size_t row = blockIdx.x;
    float* p = S + row*(size_t)NN;
    int tid = threadIdx.x;
    float v[16]; float mx = -FLT_MAX;
    #pragma unroll
    for (int i=0;i<16;i++){ v[i] = p[tid + i*256]; mx = fmaxf(mx, v[i]); }
    mx = block_max(mx, sb);
    float s = 0.f;
    #pragma unroll
    for (int i=0;i<16;i++){ v[i] = __expf(v[i]-mx); s += v[i]; }
    s = block_sum(s, sb);
    float inv = 1.0f/s;
    #pragma unroll
    for (int i=0;i<16;i++) p[tid + i*256] = v[i]*inv;
}

// ------------------------------ KNN (top-8) ----------------------------------
__global__ void __launch_bounds__(256)
knn_kernel(const float* __restrict__ pts){
    __shared__ u64 sk[256*KNN];
    int row = blockIdx.x;
    int b = row >> 12, n = row & 4095;
    const float* base = pts + (size_t)b*CH*NN;
    float qx = base[n], qy = base[NN+n], qz = base[2*NN+n];
    float sqn = g_sq[row];
    const float* sqb = g_sq + (size_t)b*NN;

    u64 key[KNN];
    #pragma unroll
    for (int j=0;j<KNN;j++) key[j] = ~0ull;

    for (int m = threadIdx.x; m < NN; m += 256){
        float d2 = sqn + sqb[m]
                 - 2.0f*(qx*base[m] + qy*base[NN+m] + qz*base[2*NN+m]);
        d2 = fmaxf(d2, 0.0f);
        u64 kk = ((u64)__float_as_uint(d2) << 32) | (unsigned)m;
        if (kk < key[KNN-1]){
            key[KNN-1] = kk;
            #pragma unroll
            for (int j=KNN-1;j>0;j--){
                u64 a = key[j-1], c = key[j];
                key[j-1] = (c < a) ? c : a;
                key[j]   = (c < a) ? a : c;
            }
        }
    }
    #pragma unroll
    for (int j=0;j<KNN;j++) sk[threadIdx.x*KNN+j] = key[j];

    for (int s=128; s>0; s>>=1){
        __syncthreads();
        if ((int)threadIdx.x < s){
            int pa = threadIdx.x*KNN, pb = (threadIdx.x+s)*KNN;
            u64 outk[KNN]; int ia=0, ib=0;
            #pragma unroll
            for (int r=0;r<KNN;r++){
                u64 va = sk[pa+ia], vb = sk[pb+ib];
                if (va <= vb){ outk[r]=va; ia++; } else { outk[r]=vb; ib++; }
            }
            #pragma unroll
            for (int r=0;r<KNN;r++) sk[pa+r] = outk[r];
        }
    }
    __syncthreads();
    if (threadIdx.x < KNN)
        g_idx[(size_t)row*KNN + threadIdx.x] = (int)(unsigned)(sk[threadIdx.x] & 0xffffffffu);
}

// ------------------------- gather + lrelu + max ------------------------------
__global__ void __launch_bounds__(128) geom_kernel(void){
    __shared__ int sidx[KNN];
    int row = blockIdx.x, tid = threadIdx.x;
    int gb = row >> 12;
    if (tid < KNN) sidx[tid] = gb*NN + g_idx[(size_t)row*KNN + tid];
    __syncthreads();
    #pragma unroll
    for (int i=0;i<3;i++){
        int d = tid + i*128;
        float c = g_ka[(size_t)row*(2*DD) + DD + d];
        float mx = -FLT_MAX;
        #pragma unroll
        for (int k=0;k<KNN;k++){
            float v = g_ka[(size_t)sidx[k]*(2*DD) + d] + c;
            v = (v > 0.f) ? v : 0.2f*v;
            mx = fmaxf(mx, v);
        }
        g_geom[(size_t)row*DD + d] = mx;
    }
}

// ------------------------------ launch ---------------------------------------
extern "C" void kernel_launch(void* const* d_in, const int* in_sizes, int n_in,
                              void* d_out, int out_size) {
    const float* pts        = (const float*)d_in[0];
    const float* ln1_g      = (const float*)d_in[1];
    const float* ln1_b      = (const float*)d_in[2];
    const float* qkv_w      = (const float*)d_in[3];
    const float* attn_out_w = (const float*)d_in[4];
    const float* attn_out_b = (const float*)d_in[5];
    const float* knn_w      = (const float*)d_in[6];
    const float* knn_b      = (const float*)d_in[7];
    const float* merge_w    = (const float*)d_in[8];
    const float* merge_b    = (const float*)d_in[9];
    const float* ln2_g      = (const float*)d_in[10];
    const float* ln2_b      = (const float*)d_in[11];
    const float* ff1_w      = (const float*)d_in[12];
    const float* ff1_b      = (const float*)d_in[13];
    const float* ff2_w      = (const float*)d_in[14];
    const float* ff2_b      = (const float*)d_in[15];
    float* outp = (float*)d_out;

    float *p_tmp,*p_nf,*p_qkv,*p_s,*p_attn,*p_attnp,*p_ka,*p_geom,*p_m,*p_y,*p_h,*p_fout,*p_wc,*p_kb;
    cudaGetSymbolAddress((void**)&p_tmp,  g_tmp);
    cudaGetSymbolAddress((void**)&p_nf,   g_nf);
    cudaGetSymbolAddress((void**)&p_qkv,  g_qkv);
    cudaGetSymbolAddress((void**)&p_s,    g_s);
    cudaGetSymbolAddress((void**)&p_attn, g_attn);
    cudaGetSymbolAddress((void**)&p_attnp,g_attnp);
    cudaGetSymbolAddress((void**)&p_ka,   g_ka);
    cudaGetSymbolAddress((void**)&p_geom, g_geom);
    cudaGetSymbolAddress((void**)&p_m,    g_m);
    cudaGetSymbolAddress((void**)&p_y,    g_y);
    cudaGetSymbolAddress((void**)&p_h,    g_h);
    cudaGetSymbolAddress((void**)&p_fout, g_fout);
    cudaGetSymbolAddress((void**)&p_wc,   g_wc);
    cudaGetSymbolAddress((void**)&p_kb,   g_kbias);

    dim3 t328(32,8);
    transpose_in<<<dim3(NN/32, DD/32, BB), t328>>>(pts, p_tmp);
    ln_rows<<<ROWS,128>>>(p_tmp, ln1_g, ln1_b, p_nf);
    prep_kernel<<<(DD*2*DD+255)/256,256>>>(knn_w, knn_b);
    sq_kernel<<<(ROWS+255)/256,256>>>(pts);

    // QKV: (8192x384)@(384x1152)
    bgemm_k<128,128,false,0><<<dim3(9,64,1),256>>>(
        p_nf,p_nf,DD, qkv_w, p_qkv, nullptr,nullptr,
        DD, DD, 3*DD, 3*DD, 1, 0,0, 0,0, 0,0, 1.0f);

    // scores = Q K^T / 8   per (b,h)
    bgemm_k<128,128,true,0><<<dim3(32,32,BB*HH),256>>>(
        p_qkv, p_qkv, 64, p_qkv + DD, p_s, nullptr,nullptr,
        64, 3*DD, 3*DD, NN, HH,
        (long long)NN*3*DD, 64, (long long)NN*3*DD, 64,
        (long long)HH*NN*NN, (long long)NN*NN, 0.125f);

    softmax_rows<<<BB*HH*NN,256>>>(p_s);

    // attn = S @ V  per (b,h), write head-merged (b,n,384)
    bgemm_k<128,64,false,0><<<dim3(1,32,BB*HH),256>>>(
        p_s, p_s, NN, p_qkv + 2*DD, p_attn, nullptr,nullptr,
        NN, NN, 3*DD, DD, HH,
        (long long)HH*NN*NN, (long long)NN*NN,
        (long long)NN*3*DD, 64,
        (long long)NN*DD, 64, 1.0f);

    // attn projection
    bgemm_k<128,128,false,1><<<dim3(3,64,1),256>>>(
        p_attn,p_attn,DD, attn_out_w, p_attnp, attn_out_b,nullptr,
        DD, DD, DD, DD, 1, 0,0, 0,0, 0,0, 1.0f);

    // KNN + factored edge-MLP
    knn_kernel<<<ROWS,256>>>(pts);
    bgemm_k<128,128,false,1><<<dim3(6,64,1),256>>>(
        p_nf,p_nf,DD, p_wc, p_ka, p_kb,nullptr,
        DD, DD, 2*DD, 2*DD, 1, 0,0, 0,0, 0,0, 1.0f);
    geom_kernel<<<ROWS,128>>>();

    // merge: concat([attnp, geom]) @ merge_w + b + attnp
    bgemm_k<128,128,false,3><<<dim3(3,64,1),256>>>(
        p_attnp, p_geom, DD, merge_w, p_m, merge_b, p_attnp,
        2*DD, DD, DD, DD, 1, 0,0, 0,0, 0,0, 1.0f);

    ln_rows<<<ROWS,128>>>(p_m, ln2_g, ln2_b, p_y);

    // FFN
    bgemm_k<128,128,false,2><<<dim3(6,64,1),256>>>(
        p_y,p_y,DD, ff1_w, p_h, ff1_b,nullptr,
        DD, DD, 2*DD, 2*DD, 1, 0,0, 0,0, 0,0, 1.0f);
    bgemm_k<128,128,false,3><<<dim3(3,64,1),256>>>(
        p_h,p_h,2*DD, ff2_w, p_fout, ff2_b, p_y,
        2*DD, 2*DD, DD, DD, 1, 0,0, 0,0, 0,0, 1.0f);

    // assemble output
    copy_coords<<<(BB*3*NN+255)/256,256>>>(pts, outp);
    transpose_out<<<dim3(NN/32, DD/32, BB), t328>>>(p_fout, outp);
}

// round 7
// speedup vs baseline: 2.0009x; 1.8867x over previous
#include <cuda_runtime.h>
#include <cuda_bf16.h>
#include <float.h>
#include <math.h>
#include <stdint.h>

#define BB   2
#define NN   4096
#define DD   384
#define HH   6
#define KNN  8
#define CH   387
#define ROWS (BB*NN)
#define SELEM (12LL*NN*NN)

typedef unsigned long long u64;
typedef unsigned int u32;
typedef __nv_bfloat16 bf16;

// ------------------------- scratch (static device mem) ----------------------
__device__ float g_tmp  [ROWS*DD];
__device__ bf16  g_nfh  [ROWS*DD];
__device__ bf16  g_nfl  [ROWS*DD];
__device__ bf16  g_qh   [ROWS*3*DD];
__device__ bf16  g_ql   [ROWS*3*DD];
__device__ bf16  g_vth  [BB*HH*64*NN];
__device__ bf16  g_vtl  [BB*HH*64*NN];
__device__ float g_s    [SELEM];
__device__ bf16  g_ph   [SELEM];
__device__ bf16  g_pl   [SELEM];
__device__ bf16  g_ath  [ROWS*DD];
__device__ bf16  g_atl  [ROWS*DD];
__device__ float g_attnp[ROWS*DD];
__device__ bf16  g_aph  [ROWS*DD];
__device__ bf16  g_apl  [ROWS*DD];
__device__ float g_ka   [ROWS*2*DD];
__device__ bf16  g_gh   [ROWS*DD];
__device__ bf16  g_gl   [ROWS*DD];
__device__ float g_m    [ROWS*DD];
__device__ float g_y    [ROWS*DD];
__device__ bf16  g_yh   [ROWS*DD];
__device__ bf16  g_yl   [ROWS*DD];
__device__ bf16  g_hh   [ROWS*2*DD];
__device__ bf16  g_hl   [ROWS*2*DD];
__device__ float g_fout [ROWS*DD];
__device__ float g_wc   [DD*2*DD];
__device__ float g_kbias[2*DD];
__device__ float g_sq   [ROWS];
__device__ int   g_idx  [ROWS*KNN];
// transposed+split weights ([n][k] planes)
__device__ bf16  g_wqh[3*DD*DD], g_wql[3*DD*DD];
__device__ bf16  g_woh[DD*DD],   g_wol[DD*DD];
__device__ bf16  g_wch[2*DD*DD], g_wcl[2*DD*DD];
__device__ bf16  g_wmh[2*DD*DD], g_wml[2*DD*DD];
__device__ bf16  g_w1h[2*DD*DD], g_w1l[2*DD*DD];
__device__ bf16  g_w2h[2*DD*DD], g_w2l[2*DD*DD];

// ------------------------------ helpers -------------------------------------
__device__ __forceinline__ void split2(float v, bf16& h, bf16& l){
    h = __float2bfloat16(v);
    l = __float2bfloat16(v - __bfloat162float(h));
}
__device__ __forceinline__ float block_sum(float v, float* sb){
    #pragma unroll
    for (int o=16;o>0;o>>=1) v += __shfl_xor_sync(0xffffffffu, v, o);
    int lane = threadIdx.x & 31, w = threadIdx.x >> 5, nw = blockDim.x >> 5;
    if (lane==0) sb[w] = v;
    __syncthreads();
    if (w==0){
        float x = (lane < nw) ? sb[lane] : 0.f;
        #pragma unroll
        for (int o=16;o>0;o>>=1) x += __shfl_xor_sync(0xffffffffu, x, o);
        if (lane==0) sb[0] = x;
    }
    __syncthreads();
    float r = sb[0]; __syncthreads(); return r;
}
__device__ __forceinline__ float block_max(float v, float* sb){
    #pragma unroll
    for (int o=16;o>0;o>>=1) v = fmaxf(v, __shfl_xor_sync(0xffffffffu, v, o));
    int lane = threadIdx.x & 31, w = threadIdx.x >> 5, nw = blockDim.x >> 5;
    if (lane==0) sb[w] = v;
    __syncthreads();
    if (w==0){
        float x = (lane < nw) ? sb[lane] : -FLT_MAX;
        #pragma unroll
        for (int o=16;o>0;o>>=1) x = fmaxf(x, __shfl_xor_sync(0xffffffffu, x, o));
        if (lane==0) sb[0] = x;
    }
    __syncthreads();
    float r = sb[0]; __syncthreads(); return r;
}
__device__ __forceinline__ u32 smem_u32(const void* p){
    u32 a;
    asm("{ .reg .u64 t; cvta.to.shared.u64 t, %1; cvt.u32.u64 %0, t; }" : "=r"(a) : "l"(p));
    return a;
}
__device__ __forceinline__ void mma16816(float* c, const u32* a, const u32* b){
    asm volatile(
        "mma.sync.aligned.m16n8k16.row.col.f32.bf16.bf16.f32 "
        "{%0,%1,%2,%3}, {%4,%5,%6,%7}, {%8,%9}, {%0,%1,%2,%3};"
        : "+f"(c[0]), "+f"(c[1]), "+f"(c[2]), "+f"(c[3])
        : "r"(a[0]), "r"(a[1]), "r"(a[2]), "r"(a[3]), "r"(b[0]), "r"(b[1]));
}
__device__ __forceinline__ void ldsm_x4(u32* r, u32 addr){
    asm volatile("ldmatrix.sync.aligned.m8n8.x4.shared.b16 {%0,%1,%2,%3}, [%4];"
        : "=r"(r[0]), "=r"(r[1]), "=r"(r[2]), "=r"(r[3]) : "r"(addr));
}
#define CP16(dst,src) asm volatile("cp.async.cg.shared.global [%0], [%1], 16;" :: "r"(dst), "l"(src))
#define CP_COMMIT()   asm volatile("cp.async.commit_group;" ::: "memory")
#define CP_WAIT1()    asm volatile("cp.async.wait_group 1;" ::: "memory")
#define CP_WAIT0()    asm volatile("cp.async.wait_group 0;" ::: "memory")

// --------------- HMMA split-precision GEMM (bf16 planes in, fused epi) -------
// C = scale*(A@Bt)  A planes [m][k] (A0|A1 split at ksplit), B planes [n][k].
// 3-term split: AhBh + AhBl + AlBh.  EPI: 0 none,1 +bias,2 +bias+gelu,3 +bias+res
template<int BN,int EPI,bool OUTF,bool OUTP>
__global__ void __launch_bounds__(256)
hgemm(const bf16* __restrict__ A0h, const bf16* __restrict__ A0l,
      const bf16* __restrict__ A1h, const bf16* __restrict__ A1l,
      int ksplit, int lda0, int lda1,
      const bf16* __restrict__ Bh, const bf16* __restrict__ Bl, int ldb,
      float* __restrict__ Cf,
      bf16* __restrict__ Ph, bf16* __restrict__ Pl, int ldc,
      const float* __restrict__ bias, const float* __restrict__ res,
      int Kk, int Hdiv,
      long long zaB, long long zaH, long long zbB, long long zbH,
      long long zcB, long long zcH, float scale)
{
    constexpr int BM = 128, BK = 32;
    constexpr int STR = 80;                 // smem bytes per row (64 data + 16 pad)
    constexpr int ASZ = BM*STR, BSZ = BN*STR;
    constexpr int STAGE = 2*ASZ + 2*BSZ;
    constexpr int TWN = BN/2, FN = TWN/8;   // warps: 4(M) x 2(N)

    extern __shared__ char sm[];
    int tid = threadIdx.x, lane = tid & 31, warp = tid >> 5;
    int wm = warp & 3, wn = warp >> 2;
    int g = lane >> 2, t4 = lane & 3;

    int z = blockIdx.z, zb = z / Hdiv, zh = z - zb*Hdiv;
    long long aoff = zb*zaB + zh*zaH, boff = zb*zbB + zh*zbH, coff = zb*zcB + zh*zcH;
    A0h += aoff; A0l += aoff; A1h += aoff; A1l += aoff;
    Bh  += boff; Bl  += boff;
    if (OUTF) Cf += coff;
    if (OUTP){ Ph += coff; Pl += coff; }
    if (EPI == 3) res += coff;
    int m0 = blockIdx.y*BM, n0 = blockIdx.x*BN;

    // per-lane ldmatrix offsets
    int arow = ((lane>>3)&1)*8 + (lane&7);   // + m-block base
    int akc  = (lane>>4)*8;                   // + kk
    int brow = (lane>>4)*8 + (lane&7);        // + n-block base
    int bkc  = ((lane>>3)&1)*8;               // + kk

    float acc[2][FN][4];
    #pragma unroll
    for (int i=0;i<2;i++)
        #pragma unroll
        for (int j=0;j<FN;j++)
            #pragma unroll
            for (int q=0;q<4;q++) acc[i][j][q] = 0.f;

    u32 smbase = smem_u32(sm);
    int nch = Kk / BK;

    auto load_stage = [&](int ch, int s){
        int kg = ch*BK;
        const bf16 *pAh, *pAl; long long la;
        if (kg < ksplit){ pAh = A0h + (size_t)m0*lda0 + kg;          pAl = A0l + (size_t)m0*lda0 + kg;          la = lda0; }
        else            { pAh = A1h + (size_t)m0*lda1 + (kg-ksplit); pAl = A1l + (size_t)m0*lda1 + (kg-ksplit); la = lda1; }
        u32 sa = smbase + s*STAGE;
        #pragma unroll
        for (int it=0; it<BM*4/256; it++){
            int idx = it*256 + tid, r = idx>>2, c = idx&3;
            CP16(sa + r*STR + c*16,        pAh + (size_t)r*la + c*8);
            CP16(sa + ASZ + r*STR + c*16,  pAl + (size_t)r*la + c*8);
        }
        u32 sb = sa + 2*ASZ;
        const bf16* pBh = Bh + (size_t)n0*ldb + kg;
        const bf16* pBl = Bl + (size_t)n0*ldb + kg;
        #pragma unroll
        for (int it=0; it<BN*4/256 || it<1; it++){
            int idx = it*256 + tid, r = idx>>2, c = idx&3;
            if (BN*4 >= 256 || idx < BN*4){
                CP16(sb + r*STR + c*16,        pBh + (size_t)r*ldb + c*8);
                CP16(sb + BSZ + r*STR + c*16,  pBl + (size_t)r*ldb + c*8);
            }
        }
    };

    load_stage(0, 0); CP_COMMIT();

    for (int ch = 0; ch < nch; ch++){
        int s = ch & 1;
        if (ch+1 < nch){ load_stage(ch+1, (ch+1)&1); CP_COMMIT(); CP_WAIT1(); }
        else CP_WAIT0();
        __syncthreads();

        u32 sa = smbase + s*STAGE;
        u32 sAh = sa, sAl = sa + ASZ, sBh = sa + 2*ASZ, sBl = sa + 2*ASZ + BSZ;
        #pragma unroll
        for (int kk=0; kk<BK; kk+=16){
            u32 ah[2][4], al[2][4], bh[FN][2], bl[FN][2];
            #pragma unroll
            for (int fm=0; fm<2; fm++){
                u32 ra = (wm*32 + fm*16 + arow)*STR + (kk + akc)*2;
                ldsm_x4(ah[fm], sAh + ra);
                ldsm_x4(al[fm], sAl + ra);
            }
            #pragma unroll
            for (int fp=0; fp<FN/2; fp++){
                u32 rb = (wn*TWN + fp*16 + brow)*STR + (kk + bkc)*2;
                u32 t[4];
                ldsm_x4(t, sBh + rb);
                bh[2*fp][0]=t[0]; bh[2*fp][1]=t[1]; bh[2*fp+1][0]=t[2]; bh[2*fp+1][1]=t[3];
                ldsm_x4(t, sBl + rb);
                bl[2*fp][0]=t[0]; bl[2*fp][1]=t[1]; bl[2*fp+1][0]=t[2]; bl[2*fp+1][1]=t[3];
            }
            #pragma unroll
            for (int fm=0; fm<2; fm++)
                #pragma unroll
                for (int fn=0; fn<FN; fn++){
                    mma16816(acc[fm][fn], ah[fm], bh[fn]);
                    mma16816(acc[fm][fn], ah[fm], bl[fn]);
                    mma16816(acc[fm][fn], al[fm], bh[fn]);
                }
        }
        __syncthreads();
    }

    // ---- epilogue (mapping identical to verified round-4 kernel) ----
    #pragma unroll
    for (int fm=0; fm<2; fm++){
        #pragma unroll
        for (int fn=0; fn<FN; fn++){
            int col = n0 + wn*TWN + fn*8 + 2*t4;
            #pragma unroll
            for (int half=0; half<2; half++){
                int row = m0 + wm*32 + fm*16 + g + half*8;
                float v0 = acc[fm][fn][2*half+0]*scale;
                float v1 = acc[fm][fn][2*half+1]*scale;
                if (EPI >= 1){ v0 += bias[col]; v1 += bias[col+1]; }
                if (EPI == 2){
                    v0 = 0.5f*v0*(1.0f + erff(v0*0.70710678118654752f));
                    v1 = 0.5f*v1*(1.0f + erff(v1*0.70710678118654752f));
                }
                if (EPI == 3){
                    float2 rr = *(const float2*)(res + (size_t)row*ldc + col);
                    v0 += rr.x; v1 += rr.y;
                }
                if (OUTF){ float2 o; o.x=v0; o.y=v1; *(float2*)(Cf + (size_t)row*ldc + col) = o; }
                if (OUTP){
                    bf16 h0,l0,h1,l1; split2(v0,h0,l0); split2(v1,h1,l1);
                    u32 hp = ((u32)__bfloat16_as_ushort(h1)<<16) | __bfloat16_as_ushort(h0);
                    u32 lp = ((u32)__bfloat16_as_ushort(l1)<<16) | __bfloat16_as_ushort(l0);
                    *(u32*)(Ph + (size_t)row*ldc + col) = hp;
                    *(u32*)(Pl + (size_t)row*ldc + col) = lp;
                }
            }
        }
    }
}

// ------------------------------ prep / misc ----------------------------------
__global__ void copy_coords(const float* __restrict__ pts, float* __restrict__ outp){
    int i = blockIdx.x*blockDim.x + threadIdx.x;
    if (i < BB*3*NN){
        int b = i / (3*NN), r = i % (3*NN);
        outp[(size_t)b*CH*NN + r] = pts[(size_t)b*CH*NN + r];
    }
}
__global__ void prep_kernel(const float* __restrict__ knn_w, const float* __restrict__ knn_b){
    int i = blockIdx.x*blockDim.x + threadIdx.x;
    if (i < DD*2*DD){
        int r = i / (2*DD), c = i % (2*DD);
        float v;
        if (c < DD) v = knn_w[r*DD + c];
        else { int cc = c - DD; v = knn_w[(DD + r)*DD + cc] - knn_w[r*DD + cc]; }
        g_wc[i] = v;
    }
    if (i < 2*DD) g_kbias[i] = (i < DD) ? 0.f : knn_b[i-DD];
}
__global__ void sq_kernel(const float* __restrict__ pts){
    int i = blockIdx.x*blockDim.x + threadIdx.x;
    if (i < ROWS){
        int b = i >> 12, n = i & 4095;
        const float* base = pts + (size_t)b*CH*NN;
        float x = base[n], y = base[NN+n], z = base[2*NN+n];
        g_sq[i] = x*x + y*y + z*z;
    }
}
// W[K][N] fp32 -> [n][k] bf16 hi/lo planes
__global__ void wt_conv(const float* __restrict__ W, int K, int N,
                        bf16* __restrict__ oh, bf16* __restrict__ ol){
    __shared__ float t[32][33];
    int k0 = blockIdx.x*32, n0 = blockIdx.y*32;
    for (int r = threadIdx.y; r < 32; r += 8)
        t[r][threadIdx.x] = W[(size_t)(k0+r)*N + n0 + threadIdx.x];
    __syncthreads();
    for (int r = threadIdx.y; r < 32; r += 8){
        float v = t[threadIdx.x][r];
        bf16 h,l; split2(v,h,l);
        size_t o = (size_t)(n0+r)*K + k0 + threadIdx.x;
        oh[o] = h; ol[o] = l;
    }
}
// V section of qkv planes -> Vt[b][h][64][4096] planes
__global__ void vt_conv(void){
    __shared__ bf16 th[32][33], tl[32][33];
    int z = blockIdx.z, b = z / HH, h = z % HH;
    int n0 = blockIdx.x*32, f0 = blockIdx.y*32;
    for (int r = threadIdx.y; r < 32; r += 8){
        size_t src = (size_t)(b*NN + n0 + r)*(3*DD) + 2*DD + h*64 + f0 + threadIdx.x;
        th[r][threadIdx.x] = g_qh[src];
        tl[r][threadIdx.x] = g_ql[src];
    }
    __syncthreads();
    for (int r = threadIdx.y; r < 32; r += 8){
        size_t dst = ((size_t)z*64 + f0 + r)*NN + n0 + threadIdx.x;
        g_vth[dst] = th[threadIdx.x][r];
        g_vtl[dst] = tl[threadIdx.x][r];
    }
}
__global__ void transpose_in(const float* __restrict__ pts, float* __restrict__ dst){
    __shared__ float tile[32][33];
    int b = blockIdx.z, n0 = blockIdx.x*32, d0 = blockIdx.y*32;
    const float* src = pts + (size_t)b*CH*NN;
    for (int r = threadIdx.y; r < 32; r += 8)
        tile[r][threadIdx.x] = src[(size_t)(3+d0+r)*NN + n0 + threadIdx.x];
    __syncthreads();
    float* o = dst + (size_t)b*NN*DD;
    for (int r = threadIdx.y; r < 32; r += 8)
        o[(size_t)(n0+r)*DD + d0 + threadIdx.x] = tile[threadIdx.x][r];
}
__global__ void transpose_out(const float* __restrict__ fin, float* __restrict__ outp){
    __shared__ float tile[32][33];
    int b = blockIdx.z, n0 = blockIdx.x*32, d0 = blockIdx.y*32;
    const float* src = fin + (size_t)b*NN*DD;
    for (int r = threadIdx.y; r < 32; r += 8)
        tile[r][threadIdx.x] = src[(size_t)(n0+r)*DD + d0 + threadIdx.x];
    __syncthreads();
    float* dst = outp + (size_t)b*CH*NN;
    for (int r = threadIdx.y; r < 32; r += 8)
        dst[(size_t)(3+d0+r)*NN + n0 + threadIdx.x] = tile[threadIdx.x][r];
}
// LayerNorm; writes optional fp32 + optional bf16 planes
__global__ void ln_rows(const float* __restrict__ in,
                        const float* __restrict__ gam, const float* __restrict__ bet,
                        float* __restrict__ outf,
                        bf16* __restrict__ outh, bf16* __restrict__ outl){
    __shared__ float sb[8];
    int row = blockIdx.x, tid = threadIdx.x;
    const float* x = in + (size_t)row*DD;
    float v[3]; float s = 0.f;
    #pragma unroll
    for (int i=0;i<3;i++){ v[i] = x[tid + i*128]; s += v[i]; }
    s = block_sum(s, sb);
    float mean = s * (1.0f/DD), q = 0.f;
    #pragma unroll
    for (int i=0;i<3;i++){ float c = v[i]-mean; q += c*c; }
    q = block_sum(q, sb);
    float rinv = rsqrtf(q*(1.0f/DD) + 1e-5f);
    #pragma unroll
    for (int i=0;i<3;i++){
        int d = tid + i*128;
        float o = (v[i]-mean)*rinv*gam[d] + bet[d];
        size_t idx = (size_t)row*DD + d;
        if (outf) outf[idx] = o;
        if (outh){ bf16 h,l; split2(o,h,l); outh[idx]=h; outl[idx]=l; }
    }
}
// softmax over 4096; writes bf16 hi/lo prob planes
__global__ void __launch_bounds__(256) softmax_rows(const float* __restrict__ S,
                                                    bf16* __restrict__ Ph,
                                                    bf16* __restrict__ Pl){
    __shared__ float sb[8];
    size_t row = blockIdx.x;
    const float* p = S + row*(size_t)NN;
    int tid = threadIdx.x;
    float v[16]; float mx = -FLT_MAX;
    #pragma unroll
    for (int i=0;i<16;i++){ v[i] = p[tid + i*256]; mx = fmaxf(mx, v[i]); }
    mx = block_max(mx, sb);
    float s = 0.f;
    #pragma unroll
    for (int i=0;i<16;i++){ v[i] = __expf(v[i]-mx); s += v[i]; }
    s = block_sum(s, sb);
    float inv = 1.0f/s;
    #pragma unroll
    for (int i=0;i<16;i++){
        float pv = v[i]*inv;
        bf16 h,l; split2(pv,h,l);
        size_t o = row*(size_t)NN + tid + i*256;
        Ph[o] = h; Pl[o] = l;
    }
}
// ------------------------------ KNN (top-8) ----------------------------------
__global__ void __launch_bounds__(256)
knn_kernel(const float* __restrict__ pts){
    __shared__ u64 sk[256*KNN];
    int row = blockIdx.x;
    int b = row >> 12, n = row & 4095;
    const float* base = pts + (size_t)b*CH*NN;
    float qx = base[n], qy = base[NN+n], qz = base[2*NN+n];
    float sqn = g_sq[row];
    const float* sqb = g_sq + (size_t)b*NN;

    u64 key[KNN];
    #pragma unroll
    for (int j=0;j<KNN;j++) key[j] = ~0ull;

    for (int m = threadIdx.x; m < NN; m += 256){
        float d2 = sqn + sqb[m]
                 - 2.0f*(qx*base[m] + qy*base[NN+m] + qz*base[2*NN+m]);
        d2 = fmaxf(d2, 0.0f);
        u64 kk = ((u64)__float_as_uint(d2) << 32) | (unsigned)m;
        if (kk < key[KNN-1]){
            key[KNN-1] = kk;
            #pragma unroll
            for (int j=KNN-1;j>0;j--){
                u64 a = key[j-1], c = key[j];
                key[j-1] = (c < a) ? c : a;
                key[j]   = (c < a) ? a : c;
            }
        }
    }
    #pragma unroll
    for (int j=0;j<KNN;j++) sk[threadIdx.x*KNN+j] = key[j];

    for (int s=128; s>0; s>>=1){
        __syncthreads();
        if ((int)threadIdx.x < s){
            int pa = threadIdx.x*KNN, pb = (threadIdx.x+s)*KNN;
            u64 outk[KNN]; int ia=0, ib=0;
            #pragma unroll
            for (int r=0;r<KNN;r++){
                u64 va = sk[pa+ia], vb = sk[pb+ib];
                if (va <= vb){ outk[r]=va; ia++; } else { outk[r]=vb; ib++; }
            }
            #pragma unroll
            for (int r=0;r<KNN;r++) sk[pa+r] = outk[r];
        }
    }
    __syncthreads();
    if (threadIdx.x < KNN)
        g_idx[(size_t)row*KNN + threadIdx.x] = (int)(unsigned)(sk[threadIdx.x] & 0xffffffffu);
}
// ------------------------- gather + lrelu + max ------------------------------
__global__ void __launch_bounds__(128) geom_kernel(void){
    __shared__ int sidx[KNN];
    int row = blockIdx.x, tid = threadIdx.x;
    int gb = row >> 12;
    if (tid < KNN) sidx[tid] = gb*NN + g_idx[(size_t)row*KNN + tid];
    __syncthreads();
    #pragma unroll
    for (int i=0;i<3;i++){
        int d = tid + i*128;
        float c = g_ka[(size_t)row*(2*DD) + DD + d];
        float mx = -FLT_MAX;
        #pragma unroll
        for (int k=0;k<KNN;k++){
            float v = g_ka[(size_t)sidx[k]*(2*DD) + d] + c;
            v = (v > 0.f) ? v : 0.2f*v;
            mx = fmaxf(mx, v);
        }
        bf16 h,l; split2(mx,h,l);
        g_gh[(size_t)row*DD + d] = h;
        g_gl[(size_t)row*DD + d] = l;
    }
}

// ------------------------------ launch ---------------------------------------
extern "C" void kernel_launch(void* const* d_in, const int* in_sizes, int n_in,
                              void* d_out, int out_size) {
    const float* pts        = (const float*)d_in[0];
    const float* ln1_g      = (const float*)d_in[1];
    const float* ln1_b      = (const float*)d_in[2];
    const float* qkv_w      = (const float*)d_in[3];
    const float* attn_out_w = (const float*)d_in[4];
    const float* attn_out_b = (const float*)d_in[5];
    const float* knn_w      = (const float*)d_in[6];
    const float* knn_b      = (const float*)d_in[7];
    const float* merge_w    = (const float*)d_in[8];
    const float* merge_b    = (const float*)d_in[9];
    const float* ln2_g      = (const float*)d_in[10];
    const float* ln2_b      = (const float*)d_in[11];
    const float* ff1_w      = (const float*)d_in[12];
    const float* ff1_b      = (const float*)d_in[13];
    const float* ff2_w      = (const float*)d_in[14];
    const float* ff2_b      = (const float*)d_in[15];
    float* outp = (float*)d_out;

    #define GSA(v,s) cudaGetSymbolAddress((void**)&v, s)
    float *p_tmp,*p_s,*p_attnp,*p_ka,*p_m,*p_y,*p_fout,*p_wc,*p_kb;
    bf16 *p_nfh,*p_nfl,*p_qh,*p_ql,*p_vth,*p_vtl,*p_ph,*p_pl,*p_ath,*p_atl;
    bf16 *p_aph,*p_apl,*p_gh,*p_gl,*p_yh,*p_yl,*p_hh,*p_hl;
    bf16 *p_wqh,*p_wql,*p_woh,*p_wol,*p_wch,*p_wcl,*p_wmh,*p_wml,*p_w1h,*p_w1l,*p_w2h,*p_w2l;
    GSA(p_tmp,g_tmp); GSA(p_s,g_s); GSA(p_attnp,g_attnp); GSA(p_ka,g_ka);
    GSA(p_m,g_m); GSA(p_y,g_y); GSA(p_fout,g_fout); GSA(p_wc,g_wc); GSA(p_kb,g_kbias);
    GSA(p_nfh,g_nfh); GSA(p_nfl,g_nfl); GSA(p_qh,g_qh); GSA(p_ql,g_ql);
    GSA(p_vth,g_vth); GSA(p_vtl,g_vtl); GSA(p_ph,g_ph); GSA(p_pl,g_pl);
    GSA(p_ath,g_ath); GSA(p_atl,g_atl); GSA(p_aph,g_aph); GSA(p_apl,g_apl);
    GSA(p_gh,g_gh); GSA(p_gl,g_gl); GSA(p_yh,g_yh); GSA(p_yl,g_yl);
    GSA(p_hh,g_hh); GSA(p_hl,g_hl);
    GSA(p_wqh,g_wqh); GSA(p_wql,g_wql); GSA(p_woh,g_woh); GSA(p_wol,g_wol);
    GSA(p_wch,g_wch); GSA(p_wcl,g_wcl); GSA(p_wmh,g_wmh); GSA(p_wml,g_wml);
    GSA(p_w1h,g_w1h); GSA(p_w1l,g_w1l); GSA(p_w2h,g_w2h); GSA(p_w2l,g_w2l);

    // dynamic smem: 2 stages x (128+BN) rows x 80B x 2 planes
    const int SM128 = 2*(2*128*80 + 2*128*80);   // 81920
    const int SM64  = 2*(2*128*80 + 2*64*80);    // 61440
    cudaFuncSetAttribute(hgemm<128,0,false,true>,  cudaFuncAttributeMaxDynamicSharedMemorySize, SM128);
    cudaFuncSetAttribute(hgemm<128,0,true ,false>, cudaFuncAttributeMaxDynamicSharedMemorySize, SM128);
    cudaFuncSetAttribute(hgemm<64 ,0,false,true>,  cudaFuncAttributeMaxDynamicSharedMemorySize, SM64);
    cudaFuncSetAttribute(hgemm<128,1,true ,true>,  cudaFuncAttributeMaxDynamicSharedMemorySize, SM128);
    cudaFuncSetAttribute(hgemm<128,1,true ,false>, cudaFuncAttributeMaxDynamicSharedMemorySize, SM128);
    cudaFuncSetAttribute(hgemm<128,3,true ,false>, cudaFuncAttributeMaxDynamicSharedMemorySize, SM128);
    cudaFuncSetAttribute(hgemm<128,2,false,true>,  cudaFuncAttributeMaxDynamicSharedMemorySize, SM128);

    dim3 t328(32,8);
    transpose_in<<<dim3(NN/32, DD/32, BB), t328>>>(pts, p_tmp);                       // 0
    ln_rows<<<ROWS,128>>>(p_tmp, ln1_g, ln1_b, nullptr, p_nfh, p_nfl);                // 1
    wt_conv<<<dim3(DD/32, 3*DD/32), t328>>>(qkv_w, DD, 3*DD, p_wqh, p_wql);           // 2

    // 3: QKV GEMM (target for ncu capture slot)
    hgemm<128,0,false,true><<<dim3(9,64,1),256,SM128>>>(
        p_nfh,p_nfl,p_nfh,p_nfl, DD, DD, DD,
        p_wqh,p_wql, DD,
        nullptr, p_qh,p_ql, 3*DD, nullptr,nullptr,
        DD, 1, 0,0, 0,0, 0,0, 1.0f);

    vt_conv<<<dim3(NN/32, 2, BB*HH), t328>>>();                                       // 4

    // scores = QK^T/8
    hgemm<128,0,true,false><<<dim3(32,32,BB*HH),256,SM128>>>(
        p_qh,p_ql,p_qh,p_ql, 64, 3*DD, 3*DD,
        p_qh + DD, p_ql + DD, 3*DD,
        p_s, nullptr,nullptr, NN, nullptr,nullptr,
        64, HH, (long long)NN*3*DD, 64, (long long)NN*3*DD, 64,
        (long long)HH*NN*NN, (long long)NN*NN, 0.125f);

    softmax_rows<<<BB*HH*NN,256>>>(p_s, p_ph, p_pl);

    // attn = P @ V  (head-merged output columns)
    hgemm<64,0,false,true><<<dim3(1,32,BB*HH),256,SM64>>>(
        p_ph,p_pl,p_ph,p_pl, NN, NN, NN,
        p_vth,p_vtl, NN,
        nullptr, p_ath,p_atl, DD, nullptr,nullptr,
        NN, HH, (long long)HH*NN*NN, (long long)NN*NN,
        (long long)HH*64*NN, (long long)64*NN,
        (long long)NN*DD, 64, 1.0f);

    wt_conv<<<dim3(DD/32, DD/32), t328>>>(attn_out_w, DD, DD, p_woh, p_wol);
    hgemm<128,1,true,true><<<dim3(3,64,1),256,SM128>>>(
        p_ath,p_atl,p_ath,p_atl, DD, DD, DD,
        p_woh,p_wol, DD,
        p_attnp, p_aph,p_apl, DD, attn_out_b,nullptr,
        DD, 1, 0,0, 0,0, 0,0, 1.0f);

    // KNN branch
    prep_kernel<<<(DD*2*DD+255)/256,256>>>(knn_w, knn_b);
    wt_conv<<<dim3(DD/32, 2*DD/32), t328>>>(p_wc, DD, 2*DD, p_wch, p_wcl);
    sq_kernel<<<(ROWS+255)/256,256>>>(pts);
    knn_kernel<<<ROWS,256>>>(pts);
    hgemm<128,1,true,false><<<dim3(6,64,1),256,SM128>>>(
        p_nfh,p_nfl,p_nfh,p_nfl, DD, DD, DD,
        p_wch,p_wcl, DD,
        p_ka, nullptr,nullptr, 2*DD, p_kb,nullptr,
        DD, 1, 0,0, 0,0, 0,0, 1.0f);
    geom_kernel<<<ROWS,128>>>();

    // merge: [attnp | geom] @ merge_w + b + attnp
    wt_conv<<<dim3(2*DD/32, DD/32), t328>>>(merge_w, 2*DD, DD, p_wmh, p_wml);
    hgemm<128,3,true,false><<<dim3(3,64,1),256,SM128>>>(
        p_aph,p_apl, p_gh,p_gl, DD, DD, DD,
        p_wmh,p_wml, 2*DD,
        p_m, nullptr,nullptr, DD, merge_b, p_attnp,
        2*DD, 1, 0,0, 0,0, 0,0, 1.0f);

    ln_rows<<<ROWS,128>>>(p_m, ln2_g, ln2_b, p_y, p_yh, p_yl);

    // FFN
    wt_conv<<<dim3(DD/32, 2*DD/32), t328>>>(ff1_w, DD, 2*DD, p_w1h, p_w1l);
    hgemm<128,2,false,true><<<dim3(6,64,1),256,SM128>>>(
        p_yh,p_yl,p_yh,p_yl, DD, DD, DD,
        p_w1h,p_w1l, DD,
        nullptr, p_hh,p_hl, 2*DD, ff1_b,nullptr,
        DD, 1, 0,0, 0,0, 0,0, 1.0f);
    wt_conv<<<dim3(2*DD/32, DD/32), t328>>>(ff2_w, 2*DD, DD, p_w2h, p_w2l);
    hgemm<128,3,true,false><<<dim3(3,64,1),256,SM128>>>(
        p_hh,p_hl,p_hh,p_hl, 2*DD, 2*DD, 2*DD,
        p_w2h,p_w2l, 2*DD,
        p_fout, nullptr,nullptr, DD, ff2_b, p_y,
        2*DD, 1, 0,0, 0,0, 0,0, 1.0f);

    copy_coords<<<(BB*3*NN+255)/256,256>>>(pts, outp);
    transpose_out<<<dim3(NN/32, DD/32, BB), t328>>>(p_fout, outp);
}

// round 10
// speedup vs baseline: 2.5327x; 1.2658x over previous
#include <cuda_runtime.h>
#include <cuda_bf16.h>
#include <float.h>
#include <math.h>
#include <stdint.h>

#define BB   2
#define NN   4096
#define DD   384
#define HH   6
#define KNN  8
#define CH   387
#define ROWS (BB*NN)

typedef unsigned long long u64;
typedef unsigned int u32;
typedef __nv_bfloat16 bf16;

// ------------------------- scratch (static device mem) ----------------------
__device__ float g_tmp  [ROWS*DD];
__device__ bf16  g_nfh  [ROWS*DD];
__device__ bf16  g_nfl  [ROWS*DD];
__device__ bf16  g_qh   [ROWS*3*DD];
__device__ bf16  g_ql   [ROWS*3*DD];
__device__ bf16  g_vth  [BB*HH*64*NN];
__device__ bf16  g_vtl  [BB*HH*64*NN];
__device__ bf16  g_ath  [ROWS*DD];
__device__ bf16  g_atl  [ROWS*DD];
__device__ float g_attnp[ROWS*DD];
__device__ bf16  g_aph  [ROWS*DD];
__device__ bf16  g_apl  [ROWS*DD];
__device__ float g_ka   [ROWS*2*DD];
__device__ bf16  g_gh   [ROWS*DD];
__device__ bf16  g_gl   [ROWS*DD];
__device__ float g_m    [ROWS*DD];
__device__ float g_y    [ROWS*DD];
__device__ bf16  g_yh   [ROWS*DD];
__device__ bf16  g_yl   [ROWS*DD];
__device__ bf16  g_hh   [ROWS*2*DD];
__device__ bf16  g_hl   [ROWS*2*DD];
__device__ float g_fout [ROWS*DD];
__device__ float g_wc   [DD*2*DD];
__device__ float g_kbias[2*DD];
__device__ float g_sq   [ROWS];
__device__ int   g_idx  [ROWS*KNN];
// transposed+split weights ([n][k] planes)
__device__ bf16  g_wqh[3*DD*DD], g_wql[3*DD*DD];
__device__ bf16  g_woh[DD*DD],   g_wol[DD*DD];
__device__ bf16  g_wch[2*DD*DD], g_wcl[2*DD*DD];
__device__ bf16  g_wmh[2*DD*DD], g_wml[2*DD*DD];
__device__ bf16  g_w1h[2*DD*DD], g_w1l[2*DD*DD];
__device__ bf16  g_w2h[2*DD*DD], g_w2l[2*DD*DD];

// ------------------------------ helpers -------------------------------------
__device__ __forceinline__ void split2(float v, bf16& h, bf16& l){
    h = __float2bfloat16(v);
    l = __float2bfloat16(v - __bfloat162float(h));
}
__device__ __forceinline__ u32 pk(bf16 a, bf16 b){
    return ((u32)__bfloat16_as_ushort(b) << 16) | (u32)__bfloat16_as_ushort(a);
}
__device__ __forceinline__ float block_sum(float v, float* sb){
    #pragma unroll
    for (int o=16;o>0;o>>=1) v += __shfl_xor_sync(0xffffffffu, v, o);
    int lane = threadIdx.x & 31, w = threadIdx.x >> 5, nw = blockDim.x >> 5;
    if (lane==0) sb[w] = v;
    __syncthreads();
    if (w==0){
        float x = (lane < nw) ? sb[lane] : 0.f;
        #pragma unroll
        for (int o=16;o>0;o>>=1) x += __shfl_xor_sync(0xffffffffu, x, o);
        if (lane==0) sb[0] = x;
    }
    __syncthreads();
    float r = sb[0]; __syncthreads(); return r;
}
__device__ __forceinline__ u32 smem_u32(const void* p){
    u32 a;
    asm("{ .reg .u64 t; cvta.to.shared.u64 t, %1; cvt.u32.u64 %0, t; }" : "=r"(a) : "l"(p));
    return a;
}
__device__ __forceinline__ void mma16816(float* c, const u32* a, const u32* b){
    asm volatile(
        "mma.sync.aligned.m16n8k16.row.col.f32.bf16.bf16.f32 "
        "{%0,%1,%2,%3}, {%4,%5,%6,%7}, {%8,%9}, {%0,%1,%2,%3};"
        : "+f"(c[0]), "+f"(c[1]), "+f"(c[2]), "+f"(c[3])
        : "r"(a[0]), "r"(a[1]), "r"(a[2]), "r"(a[3]), "r"(b[0]), "r"(b[1]));
}
__device__ __forceinline__ void ldsm_x4(u32* r, u32 addr){
    asm volatile("ldmatrix.sync.aligned.m8n8.x4.shared.b16 {%0,%1,%2,%3}, [%4];"
        : "=r"(r[0]), "=r"(r[1]), "=r"(r[2]), "=r"(r[3]) : "r"(addr));
}
#define CP16(dst,src) asm volatile("cp.async.cg.shared.global [%0], [%1], 16;" :: "r"(dst), "l"(src))
#define CP_COMMIT()   asm volatile("cp.async.commit_group;" ::: "memory")
#define CP_WAIT1()    asm volatile("cp.async.wait_group 1;" ::: "memory")
#define CP_WAIT0()    asm volatile("cp.async.wait_group 0;" ::: "memory")

// --------------- HMMA split-precision GEMM (bf16 planes in, fused epi) -------
template<int BN,int EPI,bool OUTF,bool OUTP>
__global__ void __launch_bounds__(256)
hgemm(const bf16* __restrict__ A0h, const bf16* __restrict__ A0l,
      const bf16* __restrict__ A1h, const bf16* __restrict__ A1l,
      int ksplit, int lda0, int lda1,
      const bf16* __restrict__ Bh, const bf16* __restrict__ Bl, int ldb,
      float* __restrict__ Cf,
      bf16* __restrict__ Ph, bf16* __restrict__ Pl, int ldc,
      const float* __restrict__ bias, const float* __restrict__ res,
      int Kk, int Hdiv,
      long long zaB, long long zaH, long long zbB, long long zbH,
      long long zcB, long long zcH, float scale)
{
    constexpr int BM = 128, BK = 32;
    constexpr int STR = 80;
    constexpr int ASZ = BM*STR, BSZ = BN*STR;
    constexpr int STAGE = 2*ASZ + 2*BSZ;
    constexpr int TWN = BN/2, FN = TWN/8;

    extern __shared__ char sm[];
    int tid = threadIdx.x, lane = tid & 31, warp = tid >> 5;
    int wm = warp & 3, wn = warp >> 2;
    int g = lane >> 2, t4 = lane & 3;

    int z = blockIdx.z, zb = z / Hdiv, zh = z - zb*Hdiv;
    long long aoff = zb*zaB + zh*zaH, boff = zb*zbB + zh*zbH, coff = zb*zcB + zh*zcH;
    A0h += aoff; A0l += aoff; A1h += aoff; A1l += aoff;
    Bh  += boff; Bl  += boff;
    if (OUTF) Cf += coff;
    if (OUTP){ Ph += coff; Pl += coff; }
    if (EPI == 3) res += coff;
    int m0 = blockIdx.y*BM, n0 = blockIdx.x*BN;

    int arow = ((lane>>3)&1)*8 + (lane&7);
    int akc  = (lane>>4)*8;
    int brow = (lane>>4)*8 + (lane&7);
    int bkc  = ((lane>>3)&1)*8;

    float acc[2][FN][4];
    #pragma unroll
    for (int i=0;i<2;i++)
        #pragma unroll
        for (int j=0;j<FN;j++)
            #pragma unroll
            for (int q=0;q<4;q++) acc[i][j][q] = 0.f;

    u32 smbase = smem_u32(sm);
    int nch = Kk / BK;

    auto load_stage = [&](int ch, int s){
        int kg = ch*BK;
        const bf16 *pAh, *pAl; long long la;
        if (kg < ksplit){ pAh = A0h + (size_t)m0*lda0 + kg;          pAl = A0l + (size_t)m0*lda0 + kg;          la = lda0; }
        else            { pAh = A1h + (size_t)m0*lda1 + (kg-ksplit); pAl = A1l + (size_t)m0*lda1 + (kg-ksplit); la = lda1; }
        u32 sa = smbase + s*STAGE;
        #pragma unroll
        for (int it=0; it<BM*4/256; it++){
            int idx = it*256 + tid, r = idx>>2, c = idx&3;
            CP16(sa + r*STR + c*16,        pAh + (size_t)r*la + c*8);
            CP16(sa + ASZ + r*STR + c*16,  pAl + (size_t)r*la + c*8);
        }
        u32 sb = sa + 2*ASZ;
        const bf16* pBh = Bh + (size_t)n0*ldb + kg;
        const bf16* pBl = Bl + (size_t)n0*ldb + kg;
        #pragma unroll
        for (int it=0; it<BN*4/256 || it<1; it++){
            int idx = it*256 + tid, r = idx>>2, c = idx&3;
            if (BN*4 >= 256 || idx < BN*4){
                CP16(sb + r*STR + c*16,        pBh + (size_t)r*ldb + c*8);
                CP16(sb + BSZ + r*STR + c*16,  pBl + (size_t)r*ldb + c*8);
            }
        }
    };

    load_stage(0, 0); CP_COMMIT();

    for (int ch = 0; ch < nch; ch++){
        int s = ch & 1;
        if (ch+1 < nch){ load_stage(ch+1, (ch+1)&1); CP_COMMIT(); CP_WAIT1(); }
        else CP_WAIT0();
        __syncthreads();

        u32 sa = smbase + s*STAGE;
        u32 sAh = sa, sAl = sa + ASZ, sBh = sa + 2*ASZ, sBl = sa + 2*ASZ + BSZ;
        #pragma unroll
        for (int kk=0; kk<BK; kk+=16){
            u32 ah[2][4], al[2][4], bh[FN][2], bl[FN][2];
            #pragma unroll
            for (int fm=0; fm<2; fm++){
                u32 ra = (wm*32 + fm*16 + arow)*STR + (kk + akc)*2;
                ldsm_x4(ah[fm], sAh + ra);
                ldsm_x4(al[fm], sAl + ra);
            }
            #pragma unroll
            for (int fp=0; fp<FN/2; fp++){
                u32 rb = (wn*TWN + fp*16 + brow)*STR + (kk + bkc)*2;
                u32 t[4];
                ldsm_x4(t, sBh + rb);
                bh[2*fp][0]=t[0]; bh[2*fp][1]=t[1]; bh[2*fp+1][0]=t[2]; bh[2*fp+1][1]=t[3];
                ldsm_x4(t, sBl + rb);
                bl[2*fp][0]=t[0]; bl[2*fp][1]=t[1]; bl[2*fp+1][0]=t[2]; bl[2*fp+1][1]=t[3];
            }
            #pragma unroll
            for (int fm=0; fm<2; fm++)
                #pragma unroll
                for (int fn=0; fn<FN; fn++){
                    mma16816(acc[fm][fn], ah[fm], bh[fn]);
                    mma16816(acc[fm][fn], ah[fm], bl[fn]);
                    mma16816(acc[fm][fn], al[fm], bh[fn]);
                }
        }
        __syncthreads();
    }

    #pragma unroll
    for (int fm=0; fm<2; fm++){
        #pragma unroll
        for (int fn=0; fn<FN; fn++){
            int col = n0 + wn*TWN + fn*8 + 2*t4;
            #pragma unroll
            for (int half=0; half<2; half++){
                int row = m0 + wm*32 + fm*16 + g + half*8;
                float v0 = acc[fm][fn][2*half+0]*scale;
                float v1 = acc[fm][fn][2*half+1]*scale;
                if (EPI >= 1){ v0 += bias[col]; v1 += bias[col+1]; }
                if (EPI == 2){
                    v0 = 0.5f*v0*(1.0f + erff(v0*0.70710678118654752f));
                    v1 = 0.5f*v1*(1.0f + erff(v1*0.70710678118654752f));
                }
                if (EPI == 3){
                    float2 rr = *(const float2*)(res + (size_t)row*ldc + col);
                    v0 += rr.x; v1 += rr.y;
                }
                if (OUTF){ float2 o; o.x=v0; o.y=v1; *(float2*)(Cf + (size_t)row*ldc + col) = o; }
                if (OUTP){
                    bf16 h0,l0,h1,l1; split2(v0,h0,l0); split2(v1,h1,l1);
                    *(u32*)(Ph + (size_t)row*ldc + col) = pk(h0,h1);
                    *(u32*)(Pl + (size_t)row*ldc + col) = pk(l0,l1);
                }
            }
        }
    }
}

// ------------------------- flash attention (fused) ---------------------------
// Per CTA: one (b,h), 128 query rows, 8 warps x 16 rows. Online softmax.
// K/Q rows are full head dim: 64 bf16 = 128 B -> KSTR=144 (128+16 pad).
__global__ void __launch_bounds__(256)
flash_attn(void){
    constexpr int KSTR=144, VSTR=272;
    constexpr int KSZ=128*KSTR, VSZ=64*VSTR;
    constexpr int STAGE=2*KSZ+2*VSZ;        // 71680 bytes
    extern __shared__ char sm[];
    int tid=threadIdx.x, lane=tid&31, w=tid>>5;
    int g=lane>>2, t4=lane&3;
    int arow=((lane>>3)&1)*8+(lane&7), akc=(lane>>4)*8;
    int brow=(lane>>4)*8+(lane&7),     bkc=((lane>>3)&1)*8;
    int qblk=blockIdx.x, z=blockIdx.y;
    int b=z/HH, h=z-b*HH;
    const bf16* Qh=g_qh+((size_t)(b*NN+qblk*128))*(3*DD)+h*64;
    const bf16* Ql=g_ql+((size_t)(b*NN+qblk*128))*(3*DD)+h*64;
    const bf16* Kh=g_qh+((size_t)b*NN)*(3*DD)+DD+h*64;
    const bf16* Kl=g_ql+((size_t)b*NN)*(3*DD)+DD+h*64;
    const bf16* Vh=g_vth+(size_t)z*64*NN;
    const bf16* Vl=g_vtl+(size_t)z*64*NN;
    u32 smb=smem_u32(sm);

    // ---- load Q tile (128 rows x 128 B) into stage-0 smem, move to regs ----
    #pragma unroll
    for(int it=0; it<4; it++){
        int idx=it*256+tid, r=idx>>3, c=idx&7;
        CP16(smb + r*KSTR + c*16,       Qh + (size_t)r*(3*DD) + c*8);
        CP16(smb + KSZ + r*KSTR + c*16, Ql + (size_t)r*(3*DD) + c*8);
    }
    CP_COMMIT(); CP_WAIT0(); __syncthreads();
    u32 qha[4][4], qla[4][4];
    #pragma unroll
    for(int kk=0;kk<4;kk++){
        u32 ra=(w*16+arow)*KSTR+(kk*16+akc)*2;
        ldsm_x4(qha[kk], smb+ra);
        ldsm_x4(qla[kk], smb+KSZ+ra);
    }
    __syncthreads();

    auto load_kv=[&](int kt,int s){
        u32 sa=smb+(u32)s*STAGE;
        #pragma unroll
        for(int it=0;it<4;it++){
            int idx=it*256+tid, r=idx>>3, c=idx&7;
            CP16(sa + r*KSTR + c*16,       Kh + (size_t)(kt*128+r)*(3*DD) + c*8);
            CP16(sa + KSZ + r*KSTR + c*16, Kl + (size_t)(kt*128+r)*(3*DD) + c*8);
        }
        u32 sv=sa+2*KSZ;
        #pragma unroll
        for(int it=0;it<4;it++){
            int idx=it*256+tid, r=idx>>4, c=idx&15;
            CP16(sv + r*VSTR + c*16,       Vh + (size_t)r*NN + kt*128 + c*8);
            CP16(sv + VSZ + r*VSTR + c*16, Vl + (size_t)r*NN + kt*128 + c*8);
        }
    };

    float o[8][4];
    #pragma unroll
    for(int t=0;t<8;t++){ o[t][0]=0.f; o[t][1]=0.f; o[t][2]=0.f; o[t][3]=0.f; }
    float mA=-1e30f, mB=-1e30f, lA=0.f, lB=0.f;

    load_kv(0,0); CP_COMMIT();

    for(int kt=0; kt<NN/128; kt++){
        int s=kt&1;
        if(kt+1<NN/128){ load_kv(kt+1,s^1); CP_COMMIT(); CP_WAIT1(); } else CP_WAIT0();
        __syncthreads();
        u32 sK=smb+(u32)s*STAGE, sKl=sK+KSZ, sV=sK+2*KSZ, sVl=sV+VSZ;

        // ---- S = Q K^T (128 keys), 3-term split ----
        float sa[16][4];
        #pragma unroll
        for(int t=0;t<16;t++){ sa[t][0]=0.f; sa[t][1]=0.f; sa[t][2]=0.f; sa[t][3]=0.f; }
        #pragma unroll
        for(int np=0;np<8;np++){
            #pragma unroll
            for(int kk=0;kk<4;kk++){
                u32 bh[4],bl[4];
                u32 rb=(np*16+brow)*KSTR+(kk*16+bkc)*2;
                ldsm_x4(bh,sK+rb); ldsm_x4(bl,sKl+rb);
                mma16816(sa[2*np],   qha[kk], bh+0);
                mma16816(sa[2*np],   qha[kk], bl+0);
                mma16816(sa[2*np],   qla[kk], bh+0);
                mma16816(sa[2*np+1], qha[kk], bh+2);
                mma16816(sa[2*np+1], qha[kk], bl+2);
                mma16816(sa[2*np+1], qla[kk], bh+2);
            }
        }
        // ---- online softmax ----
        float mxA=-1e30f, mxB=-1e30f;
        #pragma unroll
        for(int t=0;t<16;t++){
            sa[t][0]*=0.125f; sa[t][1]*=0.125f; sa[t][2]*=0.125f; sa[t][3]*=0.125f;
            mxA=fmaxf(mxA,fmaxf(sa[t][0],sa[t][1]));
            mxB=fmaxf(mxB,fmaxf(sa[t][2],sa[t][3]));
        }
        mxA=fmaxf(mxA,__shfl_xor_sync(0xffffffffu,mxA,1));
        mxA=fmaxf(mxA,__shfl_xor_sync(0xffffffffu,mxA,2));
        mxB=fmaxf(mxB,__shfl_xor_sync(0xffffffffu,mxB,1));
        mxB=fmaxf(mxB,__shfl_xor_sync(0xffffffffu,mxB,2));
        float mAn=fmaxf(mA,mxA), mBn=fmaxf(mB,mxB);
        float scA=__expf(mA-mAn), scB=__expf(mB-mBn);
        mA=mAn; mB=mBn;
        lA*=scA; lB*=scB;
        #pragma unroll
        for(int t=0;t<16;t++){
            sa[t][0]=__expf(sa[t][0]-mA); sa[t][1]=__expf(sa[t][1]-mA);
            sa[t][2]=__expf(sa[t][2]-mB); sa[t][3]=__expf(sa[t][3]-mB);
            lA+=sa[t][0]+sa[t][1]; lB+=sa[t][2]+sa[t][3];
        }
        #pragma unroll
        for(int t=0;t<8;t++){ o[t][0]*=scA; o[t][1]*=scA; o[t][2]*=scB; o[t][3]*=scB; }
        // ---- O += P V^T, P split in registers (acc layout == A layout) ----
        #pragma unroll
        for(int kk=0;kk<8;kk++){
            u32 pah[4],pal[4];
            {
                bf16 h0,l0,h1,l1;
                split2(sa[2*kk][0],h0,l0);   split2(sa[2*kk][1],h1,l1);
                pah[0]=pk(h0,h1); pal[0]=pk(l0,l1);
                split2(sa[2*kk][2],h0,l0);   split2(sa[2*kk][3],h1,l1);
                pah[1]=pk(h0,h1); pal[1]=pk(l0,l1);
                split2(sa[2*kk+1][0],h0,l0); split2(sa[2*kk+1][1],h1,l1);
                pah[2]=pk(h0,h1); pal[2]=pk(l0,l1);
                split2(sa[2*kk+1][2],h0,l0); split2(sa[2*kk+1][3],h1,l1);
                pah[3]=pk(h0,h1); pal[3]=pk(l0,l1);
            }
            #pragma unroll
            for(int hp=0;hp<4;hp++){
                u32 vh[4],vl[4];
                u32 rb=(hp*16+brow)*VSTR+(kk*16+bkc)*2;
                ldsm_x4(vh,sV+rb); ldsm_x4(vl,sVl+rb);
                mma16816(o[2*hp],   pah, vh+0);
                mma16816(o[2*hp],   pah, vl+0);
                mma16816(o[2*hp],   pal, vh+0);
                mma16816(o[2*hp+1], pah, vh+2);
                mma16816(o[2*hp+1], pah, vl+2);
                mma16816(o[2*hp+1], pal, vh+2);
            }
        }
        __syncthreads();
    }
    lA+=__shfl_xor_sync(0xffffffffu,lA,1); lA+=__shfl_xor_sync(0xffffffffu,lA,2);
    lB+=__shfl_xor_sync(0xffffffffu,lB,1); lB+=__shfl_xor_sync(0xffffffffu,lB,2);
    float iA=1.f/lA, iB=1.f/lB;
    int rowA=qblk*128+w*16+g, rowB=rowA+8;
    bf16* Oh=g_ath+((size_t)b*NN)*DD;
    bf16* Ol=g_atl+((size_t)b*NN)*DD;
    #pragma unroll
    for(int t=0;t<8;t++){
        int col=h*64+t*8+2*t4;
        float v0=o[t][0]*iA, v1=o[t][1]*iA, v2=o[t][2]*iB, v3=o[t][3]*iB;
        bf16 h0,l0,h1,l1;
        split2(v0,h0,l0); split2(v1,h1,l1);
        *(u32*)(Oh+(size_t)rowA*DD+col)=pk(h0,h1);
        *(u32*)(Ol+(size_t)rowA*DD+col)=pk(l0,l1);
        split2(v2,h0,l0); split2(v3,h1,l1);
        *(u32*)(Oh+(size_t)rowB*DD+col)=pk(h0,h1);
        *(u32*)(Ol+(size_t)rowB*DD+col)=pk(l0,l1);
    }
}

// ------------------------------ prep / misc ----------------------------------
__global__ void copy_coords(const float* __restrict__ pts, float* __restrict__ outp){
    int i = blockIdx.x*blockDim.x + threadIdx.x;
    if (i < BB*3*NN){
        int b = i / (3*NN), r = i % (3*NN);
        outp[(size_t)b*CH*NN + r] = pts[(size_t)b*CH*NN + r];
    }
}
__global__ void prep_kernel(const float* __restrict__ knn_w, const float* __restrict__ knn_b){
    int i = blockIdx.x*blockDim.x + threadIdx.x;
    if (i < DD*2*DD){
        int r = i / (2*DD), c = i % (2*DD);
        float v;
        if (c < DD) v = knn_w[r*DD + c];
        else { int cc = c - DD; v = knn_w[(DD + r)*DD + cc] - knn_w[r*DD + cc]; }
        g_wc[i] = v;
    }
    if (i < 2*DD) g_kbias[i] = (i < DD) ? 0.f : knn_b[i-DD];
}
__global__ void sq_kernel(const float* __restrict__ pts){
    int i = blockIdx.x*blockDim.x + threadIdx.x;
    if (i < ROWS){
        int b = i >> 12, n = i & 4095;
        const float* base = pts + (size_t)b*CH*NN;
        float x = base[n], y = base[NN+n], z = base[2*NN+n];
        g_sq[i] = x*x + y*y + z*z;
    }
}
__global__ void wt_conv(const float* __restrict__ W, int K, int N,
                        bf16* __restrict__ oh, bf16* __restrict__ ol){
    __shared__ float t[32][33];
    int k0 = blockIdx.x*32, n0 = blockIdx.y*32;
    for (int r = threadIdx.y; r < 32; r += 8)
        t[r][threadIdx.x] = W[(size_t)(k0+r)*N + n0 + threadIdx.x];
    __syncthreads();
    for (int r = threadIdx.y; r < 32; r += 8){
        float v = t[threadIdx.x][r];
        bf16 h,l; split2(v,h,l);
        size_t o = (size_t)(n0+r)*K + k0 + threadIdx.x;
        oh[o] = h; ol[o] = l;
    }
}
__global__ void vt_conv(void){
    __shared__ bf16 th[32][33], tl[32][33];
    int z = blockIdx.z, b = z / HH, h = z % HH;
    int n0 = blockIdx.x*32, f0 = blockIdx.y*32;
    for (int r = threadIdx.y; r < 32; r += 8){
        size_t src = (size_t)(b*NN + n0 + r)*(3*DD) + 2*DD + h*64 + f0 + threadIdx.x;
        th[r][threadIdx.x] = g_qh[src];
        tl[r][threadIdx.x] = g_ql[src];
    }
    __syncthreads();
    for (int r = threadIdx.y; r < 32; r += 8){
        size_t dst = ((size_t)z*64 + f0 + r)*NN + n0 + threadIdx.x;
        g_vth[dst] = th[threadIdx.x][r];
        g_vtl[dst] = tl[threadIdx.x][r];
    }
}
__global__ void transpose_in(const float* __restrict__ pts, float* __restrict__ dst){
    __shared__ float tile[32][33];
    int b = blockIdx.z, n0 = blockIdx.x*32, d0 = blockIdx.y*32;
    const float* src = pts + (size_t)b*CH*NN;
    for (int r = threadIdx.y; r < 32; r += 8)
        tile[r][threadIdx.x] = src[(size_t)(3+d0+r)*NN + n0 + threadIdx.x];
    __syncthreads();
    float* o = dst + (size_t)b*NN*DD;
    for (int r = threadIdx.y; r < 32; r += 8)
        o[(size_t)(n0+r)*DD + d0 + threadIdx.x] = tile[threadIdx.x][r];
}
__global__ void transpose_out(const float* __restrict__ fin, float* __restrict__ outp){
    __shared__ float tile[32][33];
    int b = blockIdx.z, n0 = blockIdx.x*32, d0 = blockIdx.y*32;
    const float* src = fin + (size_t)b*NN*DD;
    for (int r = threadIdx.y; r < 32; r += 8)
        tile[r][threadIdx.x] = src[(size_t)(n0+r)*DD + d0 + threadIdx.x];
    __syncthreads();
    float* dst = outp + (size_t)b*CH*NN;
    for (int r = threadIdx.y; r < 32; r += 8)
        dst[(size_t)(3+d0+r)*NN + n0 + threadIdx.x] = tile[threadIdx.x][r];
}
__global__ void ln_rows(const float* __restrict__ in,
                        const float* __restrict__ gam, const float* __restrict__ bet,
                        float* __restrict__ outf,
                        bf16* __restrict__ outh, bf16* __restrict__ outl){
    __shared__ float sb[8];
    int row = blockIdx.x, tid = threadIdx.x;
    const float* x = in + (size_t)row*DD;
    float v[3]; float s = 0.f;
    #pragma unroll
    for (int i=0;i<3;i++){ v[i] = x[tid + i*128]; s += v[i]; }
    s = block_sum(s, sb);
    float mean = s * (1.0f/DD), q = 0.f;
    #pragma unroll
    for (int i=0;i<3;i++){ float c = v[i]-mean; q += c*c; }
    q = block_sum(q, sb);
    float rinv = rsqrtf(q*(1.0f/DD) + 1e-5f);
    #pragma unroll
    for (int i=0;i<3;i++){
        int d = tid + i*128;
        float o = (v[i]-mean)*rinv*gam[d] + bet[d];
        size_t idx = (size_t)row*DD + d;
        if (outf) outf[idx] = o;
        if (outh){ bf16 h,l; split2(o,h,l); outh[idx]=h; outl[idx]=l; }
    }
}
// ------------------------------ KNN (top-8) ----------------------------------
__global__ void __launch_bounds__(256)
knn_kernel(const float* __restrict__ pts){
    __shared__ u64 sk[256*KNN];
    int row = blockIdx.x;
    int b = row >> 12, n = row & 4095;
    const float* base = pts + (size_t)b*CH*NN;
    float qx = base[n], qy = base[NN+n], qz = base[2*NN+n];
    float sqn = g_sq[row];
    const float* sqb = g_sq + (size_t)b*NN;

    u64 key[KNN];
    #pragma unroll
    for (int j=0;j<KNN;j++) key[j] = ~0ull;

    for (int m = threadIdx.x; m < NN; m += 256){
        float d2 = sqn + sqb[m]
                 - 2.0f*(qx*base[m] + qy*base[NN+m] + qz*base[2*NN+m]);
        d2 = fmaxf(d2, 0.0f);
        u64 kk = ((u64)__float_as_uint(d2) << 32) | (unsigned)m;
        if (kk < key[KNN-1]){
            key[KNN-1] = kk;
            #pragma unroll
            for (int j=KNN-1;j>0;j--){
                u64 a = key[j-1], c = key[j];
                key[j-1] = (c < a) ? c : a;
                key[j]   = (c < a) ? a : c;
            }
        }
    }
    #pragma unroll
    for (int j=0;j<KNN;j++) sk[threadIdx.x*KNN+j] = key[j];

    for (int s=128; s>0; s>>=1){
        __syncthreads();
        if ((int)threadIdx.x < s){
            int pa = threadIdx.x*KNN, pb = (threadIdx.x+s)*KNN;
            u64 outk[KNN]; int ia=0, ib=0;
            #pragma unroll
            for (int r=0;r<KNN;r++){
                u64 va = sk[pa+ia], vb = sk[pb+ib];
                if (va <= vb){ outk[r]=va; ia++; } else { outk[r]=vb; ib++; }
            }
            #pragma unroll
            for (int r=0;r<KNN;r++) sk[pa+r] = outk[r];
        }
    }
    __syncthreads();
    if (threadIdx.x < KNN)
        g_idx[(size_t)row*KNN + threadIdx.x] = (int)(unsigned)(sk[threadIdx.x] & 0xffffffffu);
}
// ------------------------- gather + lrelu + max ------------------------------
__global__ void __launch_bounds__(128) geom_kernel(void){
    __shared__ int sidx[KNN];
    int row = blockIdx.x, tid = threadIdx.x;
    int gb = row >> 12;
    if (tid < KNN) sidx[tid] = gb*NN + g_idx[(size_t)row*KNN + tid];
    __syncthreads();
    #pragma unroll
    for (int i=0;i<3;i++){
        int d = tid + i*128;
        float c = g_ka[(size_t)row*(2*DD) + DD + d];
        float mx = -FLT_MAX;
        #pragma unroll
        for (int k=0;k<KNN;k++){
            float v = g_ka[(size_t)sidx[k]*(2*DD) + d] + c;
            v = (v > 0.f) ? v : 0.2f*v;
            mx = fmaxf(mx, v);
        }
        bf16 h,l; split2(mx,h,l);
        g_gh[(size_t)row*DD + d] = h;
        g_gl[(size_t)row*DD + d] = l;
    }
}

// ------------------------------ launch ---------------------------------------
extern "C" void kernel_launch(void* const* d_in, const int* in_sizes, int n_in,
                              void* d_out, int out_size) {
    const float* pts        = (const float*)d_in[0];
    const float* ln1_g      = (const float*)d_in[1];
    const float* ln1_b      = (const float*)d_in[2];
    const float* qkv_w      = (const float*)d_in[3];
    const float* attn_out_w = (const float*)d_in[4];
    const float* attn_out_b = (const float*)d_in[5];
    const float* knn_w      = (const float*)d_in[6];
    const float* knn_b      = (const float*)d_in[7];
    const float* merge_w    = (const float*)d_in[8];
    const float* merge_b    = (const float*)d_in[9];
    const float* ln2_g      = (const float*)d_in[10];
    const float* ln2_b      = (const float*)d_in[11];
    const float* ff1_w      = (const float*)d_in[12];
    const float* ff1_b      = (const float*)d_in[13];
    const float* ff2_w      = (const float*)d_in[14];
    const float* ff2_b      = (const float*)d_in[15];
    float* outp = (float*)d_out;

    #define GSA(v,s) cudaGetSymbolAddress((void**)&v, s)
    float *p_tmp,*p_attnp,*p_ka,*p_m,*p_y,*p_fout,*p_wc,*p_kb;
    bf16 *p_nfh,*p_nfl,*p_qh,*p_ql,*p_vth,*p_vtl,*p_ath,*p_atl;
    bf16 *p_aph,*p_apl,*p_gh,*p_gl,*p_yh,*p_yl,*p_hh,*p_hl;
    bf16 *p_wqh,*p_wql,*p_woh,*p_wol,*p_wch,*p_wcl,*p_wmh,*p_wml,*p_w1h,*p_w1l,*p_w2h,*p_w2l;
    GSA(p_tmp,g_tmp); GSA(p_attnp,g_attnp); GSA(p_ka,g_ka);
    GSA(p_m,g_m); GSA(p_y,g_y); GSA(p_fout,g_fout); GSA(p_wc,g_wc); GSA(p_kb,g_kbias);
    GSA(p_nfh,g_nfh); GSA(p_nfl,g_nfl); GSA(p_qh,g_qh); GSA(p_ql,g_ql);
    GSA(p_vth,g_vth); GSA(p_vtl,g_vtl);
    GSA(p_ath,g_ath); GSA(p_atl,g_atl); GSA(p_aph,g_aph); GSA(p_apl,g_apl);
    GSA(p_gh,g_gh); GSA(p_gl,g_gl); GSA(p_yh,g_yh); GSA(p_yl,g_yl);
    GSA(p_hh,g_hh); GSA(p_hl,g_hl);
    GSA(p_wqh,g_wqh); GSA(p_wql,g_wql); GSA(p_woh,g_woh); GSA(p_wol,g_wol);
    GSA(p_wch,g_wch); GSA(p_wcl,g_wcl); GSA(p_wmh,g_wmh); GSA(p_wml,g_wml);
    GSA(p_w1h,g_w1h); GSA(p_w1l,g_w1l); GSA(p_w2h,g_w2h); GSA(p_w2l,g_w2l);

    const int SM128 = 2*(2*128*80 + 2*128*80);     // 81920
    const int SMFL  = 2*(2*128*144 + 2*64*272);    // 143360
    cudaFuncSetAttribute(hgemm<128,0,false,true>,  cudaFuncAttributeMaxDynamicSharedMemorySize, SM128);
    cudaFuncSetAttribute(hgemm<128,1,true ,true>,  cudaFuncAttributeMaxDynamicSharedMemorySize, SM128);
    cudaFuncSetAttribute(hgemm<128,1,true ,false>, cudaFuncAttributeMaxDynamicSharedMemorySize, SM128);
    cudaFuncSetAttribute(hgemm<128,3,true ,false>, cudaFuncAttributeMaxDynamicSharedMemorySize, SM128);
    cudaFuncSetAttribute(hgemm<128,2,false,true>,  cudaFuncAttributeMaxDynamicSharedMemorySize, SM128);
    cudaFuncSetAttribute(flash_attn, cudaFuncAttributeMaxDynamicSharedMemorySize, SMFL);

    dim3 t328(32,8);
    transpose_in<<<dim3(NN/32, DD/32, BB), t328>>>(pts, p_tmp);
    ln_rows<<<ROWS,128>>>(p_tmp, ln1_g, ln1_b, nullptr, p_nfh, p_nfl);
    wt_conv<<<dim3(DD/32, 3*DD/32), t328>>>(qkv_w, DD, 3*DD, p_wqh, p_wql);

    // QKV
    hgemm<128,0,false,true><<<dim3(9,64,1),256,SM128>>>(
        p_nfh,p_nfl,p_nfh,p_nfl, DD, DD, DD,
        p_wqh,p_wql, DD,
        nullptr, p_qh,p_ql, 3*DD, nullptr,nullptr,
        DD, 1, 0,0, 0,0, 0,0, 1.0f);

    vt_conv<<<dim3(NN/32, 2, BB*HH), t328>>>();

    // fused attention
    flash_attn<<<dim3(NN/128, BB*HH),256,SMFL>>>();

    // attn projection
    wt_conv<<<dim3(DD/32, DD/32), t328>>>(attn_out_w, DD, DD, p_woh, p_wol);
    hgemm<128,1,true,true><<<dim3(3,64,1),256,SM128>>>(
        p_ath,p_atl,p_ath,p_atl, DD, DD, DD,
        p_woh,p_wol, DD,
        p_attnp, p_aph,p_apl, DD, attn_out_b,nullptr,
        DD, 1, 0,0, 0,0, 0,0, 1.0f);

    // KNN branch
    prep_kernel<<<(DD*2*DD+255)/256,256>>>(knn_w, knn_b);
    wt_conv<<<dim3(DD/32, 2*DD/32), t328>>>(p_wc, DD, 2*DD, p_wch, p_wcl);
    sq_kernel<<<(ROWS+255)/256,256>>>(pts);
    knn_kernel<<<ROWS,256>>>(pts);
    hgemm<128,1,true,false><<<dim3(6,64,1),256,SM128>>>(
        p_nfh,p_nfl,p_nfh,p_nfl, DD, DD, DD,
        p_wch,p_wcl, DD,
        p_ka, nullptr,nullptr, 2*DD, p_kb,nullptr,
        DD, 1, 0,0, 0,0, 0,0, 1.0f);
    geom_kernel<<<ROWS,128>>>();

    // merge: [attnp | geom] @ merge_w + b + attnp
    wt_conv<<<dim3(2*DD/32, DD/32), t328>>>(merge_w, 2*DD, DD, p_wmh, p_wml);
    hgemm<128,3,true,false><<<dim3(3,64,1),256,SM128>>>(
        p_aph,p_apl, p_gh,p_gl, DD, DD, DD,
        p_wmh,p_wml, 2*DD,
        p_m, nullptr,nullptr, DD, merge_b, p_attnp,
        2*DD, 1, 0,0, 0,0, 0,0, 1.0f);

    ln_rows<<<ROWS,128>>>(p_m, ln2_g, ln2_b, p_y, p_yh, p_yl);

    // FFN
    wt_conv<<<dim3(DD/32, 2*DD/32), t328>>>(ff1_w, DD, 2*DD, p_w1h, p_w1l);
    hgemm<128,2,false,true><<<dim3(6,64,1),256,SM128>>>(
        p_yh,p_yl,p_yh,p_yl, DD, DD, DD,
        p_w1h,p_w1l, DD,
        nullptr, p_hh,p_hl, 2*DD, ff1_b,nullptr,
        DD, 1, 0,0, 0,0, 0,0, 1.0f);
    wt_conv<<<dim3(2*DD/32, DD/32), t328>>>(ff2_w, 2*DD, DD, p_w2h, p_w2l);
    hgemm<128,3,true,false><<<dim3(3,64,1),256,SM128>>>(
        p_hh,p_hl,p_hh,p_hl, 2*DD, 2*DD, 2*DD,
        p_w2h,p_w2l, 2*DD,
        p_fout, nullptr,nullptr, DD, ff2_b, p_y,
        2*DD, 1, 0,0, 0,0, 0,0, 1.0f);

    copy_coords<<<(BB*3*NN+255)/256,256>>>(pts, outp);
    transpose_out<<<dim3(NN/32, DD/32, BB), t328>>>(p_fout, outp);
}

// round 11
// speedup vs baseline: 2.7492x; 1.0855x over previous
#include <cuda_runtime.h>
#include <cuda_bf16.h>
#include <float.h>
#include <math.h>
#include <stdint.h>

#define BB   2
#define NN   4096
#define DD   384
#define HH   6
#define KNN  8
#define CH   387
#define ROWS (BB*NN)

typedef unsigned long long u64;
typedef unsigned int u32;
typedef __nv_bfloat16 bf16;

// ------------------------- scratch (static device mem) ----------------------
__device__ float g_tmp  [ROWS*DD];
__device__ bf16  g_nfh  [ROWS*DD];
__device__ bf16  g_nfl  [ROWS*DD];
__device__ bf16  g_qh   [ROWS*3*DD];
__device__ bf16  g_ql   [ROWS*3*DD];
__device__ bf16  g_vth  [BB*HH*64*NN];
__device__ bf16  g_vtl  [BB*HH*64*NN];
__device__ bf16  g_ath  [ROWS*DD];
__device__ bf16  g_atl  [ROWS*DD];
__device__ float g_attnp[ROWS*DD];
__device__ bf16  g_aph  [ROWS*DD];
__device__ bf16  g_apl  [ROWS*DD];
__device__ float g_ka   [ROWS*2*DD];
__device__ bf16  g_gh   [ROWS*DD];
__device__ bf16  g_gl   [ROWS*DD];
__device__ float g_m    [ROWS*DD];
__device__ float g_y    [ROWS*DD];
__device__ bf16  g_yh   [ROWS*DD];
__device__ bf16  g_yl   [ROWS*DD];
__device__ bf16  g_hh   [ROWS*2*DD];
__device__ bf16  g_hl   [ROWS*2*DD];
__device__ float g_fout [ROWS*DD];
__device__ float g_wc   [DD*2*DD];
__device__ float g_kbias[2*DD];
__device__ float g_sq   [ROWS];
__device__ int   g_idx  [ROWS*KNN];
// transposed+split weights ([n][k] planes)
__device__ bf16  g_wqh[3*DD*DD], g_wql[3*DD*DD];
__device__ bf16  g_woh[DD*DD],   g_wol[DD*DD];
__device__ bf16  g_wch[2*DD*DD], g_wcl[2*DD*DD];
__device__ bf16  g_wmh[2*DD*DD], g_wml[2*DD*DD];
__device__ bf16  g_w1h[2*DD*DD], g_w1l[2*DD*DD];
__device__ bf16  g_w2h[2*DD*DD], g_w2l[2*DD*DD];

// ------------------------------ helpers -------------------------------------
__device__ __forceinline__ void split2(float v, bf16& h, bf16& l){
    h = __float2bfloat16(v);
    l = __float2bfloat16(v - __bfloat162float(h));
}
__device__ __forceinline__ u32 pk(bf16 a, bf16 b){
    return ((u32)__bfloat16_as_ushort(b) << 16) | (u32)__bfloat16_as_ushort(a);
}
// packed hi/lo split: (f0,f1) -> hi pair (f1 high half), lo pair. rn both ways
// (bit-identical to split2+pk, ~40% fewer ops).
__device__ __forceinline__ void pksplit(float f0, float f1, u32& hp, u32& lp){
    asm("cvt.rn.bf16x2.f32 %0, %1, %2;" : "=r"(hp) : "f"(f1), "f"(f0));
    float h0 = __uint_as_float(hp << 16);
    float h1 = __uint_as_float(hp & 0xffff0000u);
    asm("cvt.rn.bf16x2.f32 %0, %1, %2;" : "=r"(lp) : "f"(f1 - h1), "f"(f0 - h0));
}
__device__ __forceinline__ float ex2(float x){
    float r; asm("ex2.approx.f32 %0, %1;" : "=f"(r) : "f"(x)); return r;
}
__device__ __forceinline__ float block_sum(float v, float* sb){
    #pragma unroll
    for (int o=16;o>0;o>>=1) v += __shfl_xor_sync(0xffffffffu, v, o);
    int lane = threadIdx.x & 31, w = threadIdx.x >> 5, nw = blockDim.x >> 5;
    if (lane==0) sb[w] = v;
    __syncthreads();
    if (w==0){
        float x = (lane < nw) ? sb[lane] : 0.f;
        #pragma unroll
        for (int o=16;o>0;o>>=1) x += __shfl_xor_sync(0xffffffffu, x, o);
        if (lane==0) sb[0] = x;
    }
    __syncthreads();
    float r = sb[0]; __syncthreads(); return r;
}
__device__ __forceinline__ u32 smem_u32(const void* p){
    u32 a;
    asm("{ .reg .u64 t; cvta.to.shared.u64 t, %1; cvt.u32.u64 %0, t; }" : "=r"(a) : "l"(p));
    return a;
}
__device__ __forceinline__ void mma16816(float* c, const u32* a, const u32* b){
    asm volatile(
        "mma.sync.aligned.m16n8k16.row.col.f32.bf16.bf16.f32 "
        "{%0,%1,%2,%3}, {%4,%5,%6,%7}, {%8,%9}, {%0,%1,%2,%3};"
        : "+f"(c[0]), "+f"(c[1]), "+f"(c[2]), "+f"(c[3])
        : "r"(a[0]), "r"(a[1]), "r"(a[2]), "r"(a[3]), "r"(b[0]), "r"(b[1]));
}
__device__ __forceinline__ void ldsm_x4(u32* r, u32 addr){
    asm volatile("ldmatrix.sync.aligned.m8n8.x4.shared.b16 {%0,%1,%2,%3}, [%4];"
        : "=r"(r[0]), "=r"(r[1]), "=r"(r[2]), "=r"(r[3]) : "r"(addr));
}
#define CP16(dst,src) asm volatile("cp.async.cg.shared.global [%0], [%1], 16;" :: "r"(dst), "l"(src))
#define CP_COMMIT()   asm volatile("cp.async.commit_group;" ::: "memory")
#define CP_WAIT1()    asm volatile("cp.async.wait_group 1;" ::: "memory")
#define CP_WAIT0()    asm volatile("cp.async.wait_group 0;" ::: "memory")

// --------------- HMMA split-precision GEMM (bf16 planes in, fused epi) -------
template<int BN,int EPI,bool OUTF,bool OUTP>
__global__ void __launch_bounds__(256)
hgemm(const bf16* __restrict__ A0h, const bf16* __restrict__ A0l,
      const bf16* __restrict__ A1h, const bf16* __restrict__ A1l,
      int ksplit, int lda0, int lda1,
      const bf16* __restrict__ Bh, const bf16* __restrict__ Bl, int ldb,
      float* __restrict__ Cf,
      bf16* __restrict__ Ph, bf16* __restrict__ Pl, int ldc,
      const float* __restrict__ bias, const float* __restrict__ res,
      int Kk, int Hdiv,
      long long zaB, long long zaH, long long zbB, long long zbH,
      long long zcB, long long zcH, float scale)
{
    constexpr int BM = 128, BK = 32;
    constexpr int STR = 80;
    constexpr int ASZ = BM*STR, BSZ = BN*STR;
    constexpr int STAGE = 2*ASZ + 2*BSZ;
    constexpr int TWN = BN/2, FN = TWN/8;

    extern __shared__ char sm[];
    int tid = threadIdx.x, lane = tid & 31, warp = tid >> 5;
    int wm = warp & 3, wn = warp >> 2;
    int g = lane >> 2, t4 = lane & 3;

    int z = blockIdx.z, zb = z / Hdiv, zh = z - zb*Hdiv;
    long long aoff = zb*zaB + zh*zaH, boff = zb*zbB + zh*zbH, coff = zb*zcB + zh*zcH;
    A0h += aoff; A0l += aoff; A1h += aoff; A1l += aoff;
    Bh  += boff; Bl  += boff;
    if (OUTF) Cf += coff;
    if (OUTP){ Ph += coff; Pl += coff; }
    if (EPI == 3) res += coff;
    int m0 = blockIdx.y*BM, n0 = blockIdx.x*BN;

    int arow = ((lane>>3)&1)*8 + (lane&7);
    int akc  = (lane>>4)*8;
    int brow = (lane>>4)*8 + (lane&7);
    int bkc  = ((lane>>3)&1)*8;

    float acc[2][FN][4];
    #pragma unroll
    for (int i=0;i<2;i++)
        #pragma unroll
        for (int j=0;j<FN;j++)
            #pragma unroll
            for (int q=0;q<4;q++) acc[i][j][q] = 0.f;

    u32 smbase = smem_u32(sm);
    int nch = Kk / BK;

    auto load_stage = [&](int ch, int s){
        int kg = ch*BK;
        const bf16 *pAh, *pAl; long long la;
        if (kg < ksplit){ pAh = A0h + (size_t)m0*lda0 + kg;          pAl = A0l + (size_t)m0*lda0 + kg;          la = lda0; }
        else            { pAh = A1h + (size_t)m0*lda1 + (kg-ksplit); pAl = A1l + (size_t)m0*lda1 + (kg-ksplit); la = lda1; }
        u32 sa = smbase + s*STAGE;
        #pragma unroll
        for (int it=0; it<BM*4/256; it++){
            int idx = it*256 + tid, r = idx>>2, c = idx&3;
            CP16(sa + r*STR + c*16,        pAh + (size_t)r*la + c*8);
            CP16(sa + ASZ + r*STR + c*16,  pAl + (size_t)r*la + c*8);
        }
        u32 sb = sa + 2*ASZ;
        const bf16* pBh = Bh + (size_t)n0*ldb + kg;
        const bf16* pBl = Bl + (size_t)n0*ldb + kg;
        #pragma unroll
        for (int it=0; it<BN*4/256 || it<1; it++){
            int idx = it*256 + tid, r = idx>>2, c = idx&3;
            if (BN*4 >= 256 || idx < BN*4){
                CP16(sb + r*STR + c*16,        pBh + (size_t)r*ldb + c*8);
                CP16(sb + BSZ + r*STR + c*16,  pBl + (size_t)r*ldb + c*8);
            }
        }
    };

    load_stage(0, 0); CP_COMMIT();

    for (int ch = 0; ch < nch; ch++){
        int s = ch & 1;
        if (ch+1 < nch){ load_stage(ch+1, (ch+1)&1); CP_COMMIT(); CP_WAIT1(); }
        else CP_WAIT0();
        __syncthreads();

        u32 sa = smbase + s*STAGE;
        u32 sAh = sa, sAl = sa + ASZ, sBh = sa + 2*ASZ, sBl = sa + 2*ASZ + BSZ;
        #pragma unroll
        for (int kk=0; kk<BK; kk+=16){
            u32 ah[2][4], al[2][4], bh[FN][2], bl[FN][2];
            #pragma unroll
            for (int fm=0; fm<2; fm++){
                u32 ra = (wm*32 + fm*16 + arow)*STR + (kk + akc)*2;
                ldsm_x4(ah[fm], sAh + ra);
                ldsm_x4(al[fm], sAl + ra);
            }
            #pragma unroll
            for (int fp=0; fp<FN/2; fp++){
                u32 rb = (wn*TWN + fp*16 + brow)*STR + (kk + bkc)*2;
                u32 t[4];
                ldsm_x4(t, sBh + rb);
                bh[2*fp][0]=t[0]; bh[2*fp][1]=t[1]; bh[2*fp+1][0]=t[2]; bh[2*fp+1][1]=t[3];
                ldsm_x4(t, sBl + rb);
                bl[2*fp][0]=t[0]; bl[2*fp][1]=t[1]; bl[2*fp+1][0]=t[2]; bl[2*fp+1][1]=t[3];
            }
            #pragma unroll
            for (int fm=0; fm<2; fm++)
                #pragma unroll
                for (int fn=0; fn<FN; fn++){
                    mma16816(acc[fm][fn], ah[fm], bh[fn]);
                    mma16816(acc[fm][fn], ah[fm], bl[fn]);
                    mma16816(acc[fm][fn], al[fm], bh[fn]);
                }
        }
        __syncthreads();
    }

    #pragma unroll
    for (int fm=0; fm<2; fm++){
        #pragma unroll
        for (int fn=0; fn<FN; fn++){
            int col = n0 + wn*TWN + fn*8 + 2*t4;
            #pragma unroll
            for (int half=0; half<2; half++){
                int row = m0 + wm*32 + fm*16 + g + half*8;
                float v0 = acc[fm][fn][2*half+0]*scale;
                float v1 = acc[fm][fn][2*half+1]*scale;
                if (EPI >= 1){ v0 += bias[col]; v1 += bias[col+1]; }
                if (EPI == 2){
                    v0 = 0.5f*v0*(1.0f + erff(v0*0.70710678118654752f));
                    v1 = 0.5f*v1*(1.0f + erff(v1*0.70710678118654752f));
                }
                if (EPI == 3){
                    float2 rr = *(const float2*)(res + (size_t)row*ldc + col);
                    v0 += rr.x; v1 += rr.y;
                }
                if (OUTF){ float2 o; o.x=v0; o.y=v1; *(float2*)(Cf + (size_t)row*ldc + col) = o; }
                if (OUTP){
                    u32 hp, lp; pksplit(v0, v1, hp, lp);
                    *(u32*)(Ph + (size_t)row*ldc + col) = hp;
                    *(u32*)(Pl + (size_t)row*ldc + col) = lp;
                }
            }
        }
    }
}

// ------------------------- flash attention (fused) ---------------------------
// Per CTA: one (b,h), 128 query rows, 8 warps x 16 rows. Online softmax in
// log2 domain: p = 2^((s-m)*C), C = log2(e)/8. K/Q rows 128B -> KSTR=144.
__global__ void __launch_bounds__(256)
flash_attn(void){
    constexpr int KSTR=144, VSTR=272;
    constexpr int KSZ=128*KSTR, VSZ=64*VSTR;
    constexpr int STAGE=2*KSZ+2*VSZ;
    const float C = 0.18033688011112042f;   // log2(e)/8
    extern __shared__ char sm[];
    int tid=threadIdx.x, lane=tid&31, w=tid>>5;
    int g=lane>>2, t4=lane&3;
    int arow=((lane>>3)&1)*8+(lane&7), akc=(lane>>4)*8;
    int brow=(lane>>4)*8+(lane&7),     bkc=((lane>>3)&1)*8;
    int qblk=blockIdx.x, z=blockIdx.y;
    int b=z/HH, h=z-b*HH;
    const bf16* Qh=g_qh+((size_t)(b*NN+qblk*128))*(3*DD)+h*64;
    const bf16* Ql=g_ql+((size_t)(b*NN+qblk*128))*(3*DD)+h*64;
    const bf16* Kh=g_qh+((size_t)b*NN)*(3*DD)+DD+h*64;
    const bf16* Kl=g_ql+((size_t)b*NN)*(3*DD)+DD+h*64;
    const bf16* Vh=g_vth+(size_t)z*64*NN;
    const bf16* Vl=g_vtl+(size_t)z*64*NN;
    u32 smb=smem_u32(sm);

    // ---- load Q tile (128 rows x 128 B) into stage-0 smem, move to regs ----
    #pragma unroll
    for(int it=0; it<4; it++){
        int idx=it*256+tid, r=idx>>3, c=idx&7;
        CP16(smb + r*KSTR + c*16,       Qh + (size_t)r*(3*DD) + c*8);
        CP16(smb + KSZ + r*KSTR + c*16, Ql + (size_t)r*(3*DD) + c*8);
    }
    CP_COMMIT(); CP_WAIT0(); __syncthreads();
    u32 qha[4][4], qla[4][4];
    #pragma unroll
    for(int kk=0;kk<4;kk++){
        u32 ra=(w*16+arow)*KSTR+(kk*16+akc)*2;
        ldsm_x4(qha[kk], smb+ra);
        ldsm_x4(qla[kk], smb+KSZ+ra);
    }
    __syncthreads();

    auto load_kv=[&](int kt,int s){
        u32 sa=smb+(u32)s*STAGE;
        #pragma unroll
        for(int it=0;it<4;it++){
            int idx=it*256+tid, r=idx>>3, c=idx&7;
            CP16(sa + r*KSTR + c*16,       Kh + (size_t)(kt*128+r)*(3*DD) + c*8);
            CP16(sa + KSZ + r*KSTR + c*16, Kl + (size_t)(kt*128+r)*(3*DD) + c*8);
        }
        u32 sv=sa+2*KSZ;
        #pragma unroll
        for(int it=0;it<4;it++){
            int idx=it*256+tid, r=idx>>4, c=idx&15;
            CP16(sv + r*VSTR + c*16,       Vh + (size_t)r*NN + kt*128 + c*8);
            CP16(sv + VSZ + r*VSTR + c*16, Vl + (size_t)r*NN + kt*128 + c*8);
        }
    };

    float o[8][4];
    #pragma unroll
    for(int t=0;t<8;t++){ o[t][0]=0.f; o[t][1]=0.f; o[t][2]=0.f; o[t][3]=0.f; }
    float mA=-1e30f, mB=-1e30f, lA=0.f, lB=0.f;

    load_kv(0,0); CP_COMMIT();

    for(int kt=0; kt<NN/128; kt++){
        int s=kt&1;
        if(kt+1<NN/128){ load_kv(kt+1,s^1); CP_COMMIT(); CP_WAIT1(); } else CP_WAIT0();
        __syncthreads();
        u32 sK=smb+(u32)s*STAGE, sKl=sK+KSZ, sV=sK+2*KSZ, sVl=sV+VSZ;

        // ---- S = Q K^T (128 keys), 3-term split ----
        float sa[16][4];
        #pragma unroll
        for(int t=0;t<16;t++){ sa[t][0]=0.f; sa[t][1]=0.f; sa[t][2]=0.f; sa[t][3]=0.f; }
        #pragma unroll
        for(int np=0;np<8;np++){
            #pragma unroll
            for(int kk=0;kk<4;kk++){
                u32 bh[4],bl[4];
                u32 rb=(np*16+brow)*KSTR+(kk*16+bkc)*2;
                ldsm_x4(bh,sK+rb); ldsm_x4(bl,sKl+rb);
                mma16816(sa[2*np],   qha[kk], bh+0);
                mma16816(sa[2*np],   qha[kk], bl+0);
                mma16816(sa[2*np],   qla[kk], bh+0);
                mma16816(sa[2*np+1], qha[kk], bh+2);
                mma16816(sa[2*np+1], qha[kk], bl+2);
                mma16816(sa[2*np+1], qla[kk], bh+2);
            }
        }
        // ---- online softmax (log2 domain, raw-score max) ----
        float mxA=-1e30f, mxB=-1e30f;
        #pragma unroll
        for(int t=0;t<16;t++){
            mxA=fmaxf(mxA,fmaxf(sa[t][0],sa[t][1]));
            mxB=fmaxf(mxB,fmaxf(sa[t][2],sa[t][3]));
        }
        mxA=fmaxf(mxA,__shfl_xor_sync(0xffffffffu,mxA,1));
        mxA=fmaxf(mxA,__shfl_xor_sync(0xffffffffu,mxA,2));
        mxB=fmaxf(mxB,__shfl_xor_sync(0xffffffffu,mxB,1));
        mxB=fmaxf(mxB,__shfl_xor_sync(0xffffffffu,mxB,2));
        float mAn=fmaxf(mA,mxA), mBn=fmaxf(mB,mxB);
        float scA=ex2((mA-mAn)*C), scB=ex2((mB-mBn)*C);
        mA=mAn; mB=mBn;
        float cA=mA*C, cB=mB*C;
        lA*=scA; lB*=scB;
        #pragma unroll
        for(int t=0;t<16;t++){
            sa[t][0]=ex2(fmaf(sa[t][0],C,-cA)); sa[t][1]=ex2(fmaf(sa[t][1],C,-cA));
            sa[t][2]=ex2(fmaf(sa[t][2],C,-cB)); sa[t][3]=ex2(fmaf(sa[t][3],C,-cB));
            lA+=sa[t][0]+sa[t][1]; lB+=sa[t][2]+sa[t][3];
        }
        #pragma unroll
        for(int t=0;t<8;t++){ o[t][0]*=scA; o[t][1]*=scA; o[t][2]*=scB; o[t][3]*=scB; }
        // ---- O += P V^T, P split in registers (acc layout == A layout) ----
        #pragma unroll
        for(int kk=0;kk<8;kk++){
            u32 pah[4],pal[4];
            pksplit(sa[2*kk][0],   sa[2*kk][1],   pah[0], pal[0]);
            pksplit(sa[2*kk][2],   sa[2*kk][3],   pah[1], pal[1]);
            pksplit(sa[2*kk+1][0], sa[2*kk+1][1], pah[2], pal[2]);
            pksplit(sa[2*kk+1][2], sa[2*kk+1][3], pah[3], pal[3]);
            #pragma unroll
            for(int hp=0;hp<4;hp++){
                u32 vh[4],vl[4];
                u32 rb=(hp*16+brow)*VSTR+(kk*16+bkc)*2;
                ldsm_x4(vh,sV+rb); ldsm_x4(vl,sVl+rb);
                mma16816(o[2*hp],   pah, vh+0);
                mma16816(o[2*hp],   pah, vl+0);
                mma16816(o[2*hp],   pal, vh+0);
                mma16816(o[2*hp+1], pah, vh+2);
                mma16816(o[2*hp+1], pah, vl+2);
                mma16816(o[2*hp+1], pal, vh+2);
            }
        }
        __syncthreads();
    }
    lA+=__shfl_xor_sync(0xffffffffu,lA,1); lA+=__shfl_xor_sync(0xffffffffu,lA,2);
    lB+=__shfl_xor_sync(0xffffffffu,lB,1); lB+=__shfl_xor_sync(0xffffffffu,lB,2);
    float iA=1.f/lA, iB=1.f/lB;
    int rowA=qblk*128+w*16+g, rowB=rowA+8;
    bf16* Oh=g_ath+((size_t)b*NN)*DD;
    bf16* Ol=g_atl+((size_t)b*NN)*DD;
    #pragma unroll
    for(int t=0;t<8;t++){
        int col=h*64+t*8+2*t4;
        u32 hp, lp;
        pksplit(o[t][0]*iA, o[t][1]*iA, hp, lp);
        *(u32*)(Oh+(size_t)rowA*DD+col)=hp;
        *(u32*)(Ol+(size_t)rowA*DD+col)=lp;
        pksplit(o[t][2]*iB, o[t][3]*iB, hp, lp);
        *(u32*)(Oh+(size_t)rowB*DD+col)=hp;
        *(u32*)(Ol+(size_t)rowB*DD+col)=lp;
    }
}

// ------------------------------ prep / misc ----------------------------------
__global__ void copy_coords(const float* __restrict__ pts, float* __restrict__ outp){
    int i = blockIdx.x*blockDim.x + threadIdx.x;
    if (i < BB*3*NN){
        int b = i / (3*NN), r = i % (3*NN);
        outp[(size_t)b*CH*NN + r] = pts[(size_t)b*CH*NN + r];
    }
}
__global__ void prep_kernel(const float* __restrict__ knn_w, const float* __restrict__ knn_b){
    int i = blockIdx.x*blockDim.x + threadIdx.x;
    if (i < DD*2*DD){
        int r = i / (2*DD), c = i % (2*DD);
        float v;
        if (c < DD) v = knn_w[r*DD + c];
        else { int cc = c - DD; v = knn_w[(DD + r)*DD + cc] - knn_w[r*DD + cc]; }
        g_wc[i] = v;
    }
    if (i < 2*DD) g_kbias[i] = (i < DD) ? 0.f : knn_b[i-DD];
}
__global__ void sq_kernel(const float* __restrict__ pts){
    int i = blockIdx.x*blockDim.x + threadIdx.x;
    if (i < ROWS){
        int b = i >> 12, n = i & 4095;
        const float* base = pts + (size_t)b*CH*NN;
        float x = base[n], y = base[NN+n], z = base[2*NN+n];
        g_sq[i] = x*x + y*y + z*z;
    }
}
__global__ void wt_conv(const float* __restrict__ W, int K, int N,
                        bf16* __restrict__ oh, bf16* __restrict__ ol){
    __shared__ float t[32][33];
    int k0 = blockIdx.x*32, n0 = blockIdx.y*32;
    for (int r = threadIdx.y; r < 32; r += 8)
        t[r][threadIdx.x] = W[(size_t)(k0+r)*N + n0 + threadIdx.x];
    __syncthreads();
    for (int r = threadIdx.y; r < 32; r += 8){
        float v = t[threadIdx.x][r];
        bf16 h,l; split2(v,h,l);
        size_t o = (size_t)(n0+r)*K + k0 + threadIdx.x;
        oh[o] = h; ol[o] = l;
    }
}
__global__ void vt_conv(void){
    __shared__ bf16 th[32][33], tl[32][33];
    int z = blockIdx.z, b = z / HH, h = z % HH;
    int n0 = blockIdx.x*32, f0 = blockIdx.y*32;
    for (int r = threadIdx.y; r < 32; r += 8){
        size_t src = (size_t)(b*NN + n0 + r)*(3*DD) + 2*DD + h*64 + f0 + threadIdx.x;
        th[r][threadIdx.x] = g_qh[src];
        tl[r][threadIdx.x] = g_ql[src];
    }
    __syncthreads();
    for (int r = threadIdx.y; r < 32; r += 8){
        size_t dst = ((size_t)z*64 + f0 + r)*NN + n0 + threadIdx.x;
        g_vth[dst] = th[threadIdx.x][r];
        g_vtl[dst] = tl[threadIdx.x][r];
    }
}
__global__ void transpose_in(const float* __restrict__ pts, float* __restrict__ dst){
    __shared__ float tile[32][33];
    int b = blockIdx.z, n0 = blockIdx.x*32, d0 = blockIdx.y*32;
    const float* src = pts + (size_t)b*CH*NN;
    for (int r = threadIdx.y; r < 32; r += 8)
        tile[r][threadIdx.x] = src[(size_t)(3+d0+r)*NN + n0 + threadIdx.x];
    __syncthreads();
    float* o = dst + (size_t)b*NN*DD;
    for (int r = threadIdx.y; r < 32; r += 8)
        o[(size_t)(n0+r)*DD + d0 + threadIdx.x] = tile[threadIdx.x][r];
}
__global__ void transpose_out(const float* __restrict__ fin, float* __restrict__ outp){
    __shared__ float tile[32][33];
    int b = blockIdx.z, n0 = blockIdx.x*32, d0 = blockIdx.y*32;
    const float* src = fin + (size_t)b*NN*DD;
    for (int r = threadIdx.y; r < 32; r += 8)
        tile[r][threadIdx.x] = src[(size_t)(n0+r)*DD + d0 + threadIdx.x];
    __syncthreads();
    float* dst = outp + (size_t)b*CH*NN;
    for (int r = threadIdx.y; r < 32; r += 8)
        dst[(size_t)(3+d0+r)*NN + n0 + threadIdx.x] = tile[threadIdx.x][r];
}
__global__ void ln_rows(const float* __restrict__ in,
                        const float* __restrict__ gam, const float* __restrict__ bet,
                        float* __restrict__ outf,
                        bf16* __restrict__ outh, bf16* __restrict__ outl){
    __shared__ float sb[8];
    int row = blockIdx.x, tid = threadIdx.x;
    const float* x = in + (size_t)row*DD;
    float v[3]; float s = 0.f;
    #pragma unroll
    for (int i=0;i<3;i++){ v[i] = x[tid + i*128]; s += v[i]; }
    s = block_sum(s, sb);
    float mean = s * (1.0f/DD), q = 0.f;
    #pragma unroll
    for (int i=0;i<3;i++){ float c = v[i]-mean; q += c*c; }
    q = block_sum(q, sb);
    float rinv = rsqrtf(q*(1.0f/DD) + 1e-5f);
    #pragma unroll
    for (int i=0;i<3;i++){
        int d = tid + i*128;
        float o = (v[i]-mean)*rinv*gam[d] + bet[d];
        size_t idx = (size_t)row*DD + d;
        if (outf) outf[idx] = o;
        if (outh){ bf16 h,l; split2(o,h,l); outh[idx]=h; outl[idx]=l; }
    }
}
// ------------------------------ KNN (top-8) ----------------------------------
__global__ void __launch_bounds__(256)
knn_kernel(const float* __restrict__ pts){
    __shared__ u64 sk[256*KNN];
    int row = blockIdx.x;
    int b = row >> 12, n = row & 4095;
    const float* base = pts + (size_t)b*CH*NN;
    float qx = base[n], qy = base[NN+n], qz = base[2*NN+n];
    float sqn = g_sq[row];
    const float* sqb = g_sq + (size_t)b*NN;

    u64 key[KNN];
    #pragma unroll
    for (int j=0;j<KNN;j++) key[j] = ~0ull;

    for (int m = threadIdx.x; m < NN; m += 256){
        float d2 = sqn + sqb[m]
                 - 2.0f*(qx*base[m] + qy*base[NN+m] + qz*base[2*NN+m]);
        d2 = fmaxf(d2, 0.0f);
        u64 kk = ((u64)__float_as_uint(d2) << 32) | (unsigned)m;
        if (kk < key[KNN-1]){
            key[KNN-1] = kk;
            #pragma unroll
            for (int j=KNN-1;j>0;j--){
                u64 a = key[j-1], c = key[j];
                key[j-1] = (c < a) ? c : a;
                key[j]   = (c < a) ? a : c;
            }
        }
    }
    #pragma unroll
    for (int j=0;j<KNN;j++) sk[threadIdx.x*KNN+j] = key[j];

    for (int s=128; s>0; s>>=1){
        __syncthreads();
        if ((int)threadIdx.x < s){
            int pa = threadIdx.x*KNN, pb = (threadIdx.x+s)*KNN;
            u64 outk[KNN]; int ia=0, ib=0;
            #pragma unroll
            for (int r=0;r<KNN;r++){
                u64 va = sk[pa+ia], vb = sk[pb+ib];
                if (va <= vb){ outk[r]=va; ia++; } else { outk[r]=vb; ib++; }
            }
            #pragma unroll
            for (int r=0;r<KNN;r++) sk[pa+r] = outk[r];
        }
    }
    __syncthreads();
    if (threadIdx.x < KNN)
        g_idx[(size_t)row*KNN + threadIdx.x] = (int)(unsigned)(sk[threadIdx.x] & 0xffffffffu);
}
// ------------------------- gather + lrelu + max ------------------------------
__global__ void __launch_bounds__(128) geom_kernel(void){
    __shared__ int sidx[KNN];
    int row = blockIdx.x, tid = threadIdx.x;
    int gb = row >> 12;
    if (tid < KNN) sidx[tid] = gb*NN + g_idx[(size_t)row*KNN + tid];
    __syncthreads();
    #pragma unroll
    for (int i=0;i<3;i++){
        int d = tid + i*128;
        float c = g_ka[(size_t)row*(2*DD) + DD + d];
        float mx = -FLT_MAX;
        #pragma unroll
        for (int k=0;k<KNN;k++){
            float v = g_ka[(size_t)sidx[k]*(2*DD) + d] + c;
            v = (v > 0.f) ? v : 0.2f*v;
            mx = fmaxf(mx, v);
        }
        bf16 h,l; split2(mx,h,l);
        g_gh[(size_t)row*DD + d] = h;
        g_gl[(size_t)row*DD + d] = l;
    }
}

// ------------------------------ launch ---------------------------------------
extern "C" void kernel_launch(void* const* d_in, const int* in_sizes, int n_in,
                              void* d_out, int out_size) {
    const float* pts        = (const float*)d_in[0];
    const float* ln1_g      = (const float*)d_in[1];
    const float* ln1_b      = (const float*)d_in[2];
    const float* qkv_w      = (const float*)d_in[3];
    const float* attn_out_w = (const float*)d_in[4];
    const float* attn_out_b = (const float*)d_in[5];
    const float* knn_w      = (const float*)d_in[6];
    const float* knn_b      = (const float*)d_in[7];
    const float* merge_w    = (const float*)d_in[8];
    const float* merge_b    = (const float*)d_in[9];
    const float* ln2_g      = (const float*)d_in[10];
    const float* ln2_b      = (const float*)d_in[11];
    const float* ff1_w      = (const float*)d_in[12];
    const float* ff1_b      = (const float*)d_in[13];
    const float* ff2_w      = (const float*)d_in[14];
    const float* ff2_b      = (const float*)d_in[15];
    float* outp = (float*)d_out;

    #define GSA(v,s) cudaGetSymbolAddress((void**)&v, s)
    float *p_tmp,*p_attnp,*p_ka,*p_m,*p_y,*p_fout,*p_wc,*p_kb;
    bf16 *p_nfh,*p_nfl,*p_qh,*p_ql,*p_vth,*p_vtl,*p_ath,*p_atl;
    bf16 *p_aph,*p_apl,*p_gh,*p_gl,*p_yh,*p_yl,*p_hh,*p_hl;
    bf16 *p_wqh,*p_wql,*p_woh,*p_wol,*p_wch,*p_wcl,*p_wmh,*p_wml,*p_w1h,*p_w1l,*p_w2h,*p_w2l;
    GSA(p_tmp,g_tmp); GSA(p_attnp,g_attnp); GSA(p_ka,g_ka);
    GSA(p_m,g_m); GSA(p_y,g_y); GSA(p_fout,g_fout); GSA(p_wc,g_wc); GSA(p_kb,g_kbias);
    GSA(p_nfh,g_nfh); GSA(p_nfl,g_nfl); GSA(p_qh,g_qh); GSA(p_ql,g_ql);
    GSA(p_vth,g_vth); GSA(p_vtl,g_vtl);
    GSA(p_ath,g_ath); GSA(p_atl,g_atl); GSA(p_aph,g_aph); GSA(p_apl,g_apl);
    GSA(p_gh,g_gh); GSA(p_gl,g_gl); GSA(p_yh,g_yh); GSA(p_yl,g_yl);
    GSA(p_hh,g_hh); GSA(p_hl,g_hl);
    GSA(p_wqh,g_wqh); GSA(p_wql,g_wql); GSA(p_woh,g_woh); GSA(p_wol,g_wol);
    GSA(p_wch,g_wch); GSA(p_wcl,g_wcl); GSA(p_wmh,g_wmh); GSA(p_wml,g_wml);
    GSA(p_w1h,g_w1h); GSA(p_w1l,g_w1l); GSA(p_w2h,g_w2h); GSA(p_w2l,g_w2l);

    const int SM128 = 2*(2*128*80 + 2*128*80);     // 81920
    const int SMFL  = 2*(2*128*144 + 2*64*272);    // 143360
    cudaFuncSetAttribute(hgemm<128,0,false,true>,  cudaFuncAttributeMaxDynamicSharedMemorySize, SM128);
    cudaFuncSetAttribute(hgemm<128,1,true ,true>,  cudaFuncAttributeMaxDynamicSharedMemorySize, SM128);
    cudaFuncSetAttribute(hgemm<128,1,true ,false>, cudaFuncAttributeMaxDynamicSharedMemorySize, SM128);
    cudaFuncSetAttribute(hgemm<128,3,true ,false>, cudaFuncAttributeMaxDynamicSharedMemorySize, SM128);
    cudaFuncSetAttribute(hgemm<128,2,false,true>,  cudaFuncAttributeMaxDynamicSharedMemorySize, SM128);
    cudaFuncSetAttribute(flash_attn, cudaFuncAttributeMaxDynamicSharedMemorySize, SMFL);

    // side streams + fork/join events (created+destroyed every call; capture-safe)
    cudaStream_t s2, s3;
    cudaStreamCreateWithFlags(&s2, cudaStreamNonBlocking);
    cudaStreamCreateWithFlags(&s3, cudaStreamNonBlocking);
    cudaEvent_t eRoot, eNf, eGeom, eW;
    cudaEventCreateWithFlags(&eRoot, cudaEventDisableTiming);
    cudaEventCreateWithFlags(&eNf,   cudaEventDisableTiming);
    cudaEventCreateWithFlags(&eGeom, cudaEventDisableTiming);
    cudaEventCreateWithFlags(&eW,    cudaEventDisableTiming);

    dim3 t328(32,8);
    // ---- main chain (stream 0) ----
    transpose_in<<<dim3(NN/32, DD/32, BB), t328>>>(pts, p_tmp);           // 0
    cudaEventRecord(eRoot, 0);
    ln_rows<<<ROWS,128>>>(p_tmp, ln1_g, ln1_b, nullptr, p_nfh, p_nfl);    // 1
    cudaEventRecord(eNf, 0);
    wt_conv<<<dim3(DD/32, 3*DD/32), t328>>>(qkv_w, DD, 3*DD, p_wqh, p_wql); // 2
    hgemm<128,0,false,true><<<dim3(9,64,1),256,SM128>>>(                  // 3: QKV
        p_nfh,p_nfl,p_nfh,p_nfl, DD, DD, DD,
        p_wqh,p_wql, DD,
        nullptr, p_qh,p_ql, 3*DD, nullptr,nullptr,
        DD, 1, 0,0, 0,0, 0,0, 1.0f);
    vt_conv<<<dim3(NN/32, 2, BB*HH), t328>>>();                           // 4
    flash_attn<<<dim3(NN/128, BB*HH),256,SMFL>>>();                       // 5 (ncu slot)

    // ---- s3: weight-plane converts (overlap with flash) ----
    cudaStreamWaitEvent(s3, eRoot, 0);
    wt_conv<<<dim3(DD/32, DD/32),   t328, 0, s3>>>(attn_out_w, DD, DD,   p_woh, p_wol);
    wt_conv<<<dim3(2*DD/32, DD/32), t328, 0, s3>>>(merge_w,  2*DD, DD,   p_wmh, p_wml);
    wt_conv<<<dim3(DD/32, 2*DD/32), t328, 0, s3>>>(ff1_w,      DD, 2*DD, p_w1h, p_w1l);
    wt_conv<<<dim3(2*DD/32, DD/32), t328, 0, s3>>>(ff2_w,    2*DD, DD,   p_w2h, p_w2l);
    cudaEventRecord(eW, s3);

    // ---- s2: KNN branch (overlap with flash) ----
    cudaStreamWaitEvent(s2, eRoot, 0);
    prep_kernel<<<(DD*2*DD+255)/256,256,0,s2>>>(knn_w, knn_b);
    wt_conv<<<dim3(DD/32, 2*DD/32), t328, 0, s2>>>(p_wc, DD, 2*DD, p_wch, p_wcl);
    sq_kernel<<<(ROWS+255)/256,256,0,s2>>>(pts);
    knn_kernel<<<ROWS,256,0,s2>>>(pts);
    cudaStreamWaitEvent(s2, eNf, 0);
    hgemm<128,1,true,false><<<dim3(6,64,1),256,SM128,s2>>>(
        p_nfh,p_nfl,p_nfh,p_nfl, DD, DD, DD,
        p_wch,p_wcl, DD,
        p_ka, nullptr,nullptr, 2*DD, p_kb,nullptr,
        DD, 1, 0,0, 0,0, 0,0, 1.0f);
    geom_kernel<<<ROWS,128,0,s2>>>();
    cudaEventRecord(eGeom, s2);

    // ---- main chain continues ----
    cudaStreamWaitEvent(0, eW, 0);
    hgemm<128,1,true,true><<<dim3(3,64,1),256,SM128>>>(                   // proj
        p_ath,p_atl,p_ath,p_atl, DD, DD, DD,
        p_woh,p_wol, DD,
        p_attnp, p_aph,p_apl, DD, attn_out_b,nullptr,
        DD, 1, 0,0, 0,0, 0,0, 1.0f);
    cudaStreamWaitEvent(0, eGeom, 0);
    hgemm<128,3,true,false><<<dim3(3,64,1),256,SM128>>>(                  // merge
        p_aph,p_apl, p_gh,p_gl, DD, DD, DD,
        p_wmh,p_wml, 2*DD,
        p_m, nullptr,nullptr, DD, merge_b, p_attnp,
        2*DD, 1, 0,0, 0,0, 0,0, 1.0f);
    ln_rows<<<ROWS,128>>>(p_m, ln2_g, ln2_b, p_y, p_yh, p_yl);
    hgemm<128,2,false,true><<<dim3(6,64,1),256,SM128>>>(                  // ff1
        p_yh,p_yl,p_yh,p_yl, DD, DD, DD,
        p_w1h,p_w1l, DD,
        nullptr, p_hh,p_hl, 2*DD, ff1_b,nullptr,
        DD, 1, 0,0, 0,0, 0,0, 1.0f);
    hgemm<128,3,true,false><<<dim3(3,64,1),256,SM128>>>(                  // ff2
        p_hh,p_hl,p_hh,p_hl, 2*DD, 2*DD, 2*DD,
        p_w2h,p_w2l, 2*DD,
        p_fout, nullptr,nullptr, DD, ff2_b, p_y,
        2*DD, 1, 0,0, 0,0, 0,0, 1.0f);

    copy_coords<<<(BB*3*NN+255)/256,256>>>(pts, outp);
    transpose_out<<<dim3(NN/32, DD/32, BB), t328>>>(p_fout, outp);

    cudaEventDestroy(eRoot); cudaEventDestroy(eNf);
    cudaEventDestroy(eGeom); cudaEventDestroy(eW);
    cudaStreamDestroy(s2); cudaStreamDestroy(s3);
}

// round 13
// speedup vs baseline: 2.7911x; 1.0152x over previous
#include <cuda_runtime.h>
#include <cuda_bf16.h>
#include <float.h>
#include <math.h>
#include <stdint.h>

#define BB   2
#define NN   4096
#define DD   384
#define HH   6
#define KNN  8
#define CH   387
#define ROWS (BB*NN)

typedef unsigned long long u64;
typedef unsigned int u32;
typedef __nv_bfloat16 bf16;

// ------------------------- scratch (static device mem) ----------------------
__device__ float g_tmp  [ROWS*DD];
__device__ bf16  g_nfh  [ROWS*DD];
__device__ bf16  g_nfl  [ROWS*DD];
__device__ bf16  g_qh   [ROWS*3*DD];
__device__ bf16  g_ql   [ROWS*3*DD];
__device__ bf16  g_vth  [BB*HH*64*NN];
__device__ bf16  g_vtl  [BB*HH*64*NN];
__device__ bf16  g_ath  [ROWS*DD];
__device__ bf16  g_atl  [ROWS*DD];
__device__ float g_attnp[ROWS*DD];
__device__ bf16  g_aph  [ROWS*DD];
__device__ bf16  g_apl  [ROWS*DD];
__device__ float g_ka   [ROWS*2*DD];
__device__ bf16  g_gh   [ROWS*DD];
__device__ bf16  g_gl   [ROWS*DD];
__device__ float g_m    [ROWS*DD];
__device__ float g_y    [ROWS*DD];
__device__ bf16  g_yh   [ROWS*DD];
__device__ bf16  g_yl   [ROWS*DD];
__device__ bf16  g_hh   [ROWS*2*DD];
__device__ bf16  g_hl   [ROWS*2*DD];
__device__ float g_fout [ROWS*DD];
__device__ float g_wc   [DD*2*DD];
__device__ float g_kbias[2*DD];
__device__ float g_sq   [ROWS];
__device__ int   g_idx  [ROWS*KNN];
// transposed+split weights ([n][k] planes)
__device__ bf16  g_wqh[3*DD*DD], g_wql[3*DD*DD];
__device__ bf16  g_woh[DD*DD],   g_wol[DD*DD];
__device__ bf16  g_wch[2*DD*DD], g_wcl[2*DD*DD];
__device__ bf16  g_wmh[2*DD*DD], g_wml[2*DD*DD];
__device__ bf16  g_w1h[2*DD*DD], g_w1l[2*DD*DD];
__device__ bf16  g_w2h[2*DD*DD], g_w2l[2*DD*DD];

// ------------------------------ helpers -------------------------------------
__device__ __forceinline__ void split2(float v, bf16& h, bf16& l){
    h = __float2bfloat16(v);
    l = __float2bfloat16(v - __bfloat162float(h));
}
__device__ __forceinline__ u32 pk(bf16 a, bf16 b){
    return ((u32)__bfloat16_as_ushort(b) << 16) | (u32)__bfloat16_as_ushort(a);
}
__device__ __forceinline__ void pksplit(float f0, float f1, u32& hp, u32& lp){
    asm("cvt.rn.bf16x2.f32 %0, %1, %2;" : "=r"(hp) : "f"(f1), "f"(f0));
    float h0 = __uint_as_float(hp << 16);
    float h1 = __uint_as_float(hp & 0xffff0000u);
    asm("cvt.rn.bf16x2.f32 %0, %1, %2;" : "=r"(lp) : "f"(f1 - h1), "f"(f0 - h0));
}
__device__ __forceinline__ float ex2(float x){
    float r; asm("ex2.approx.f32 %0, %1;" : "=f"(r) : "f"(x)); return r;
}
__device__ __forceinline__ float block_sum(float v, float* sb){
    #pragma unroll
    for (int o=16;o>0;o>>=1) v += __shfl_xor_sync(0xffffffffu, v, o);
    int lane = threadIdx.x & 31, w = threadIdx.x >> 5, nw = blockDim.x >> 5;
    if (lane==0) sb[w] = v;
    __syncthreads();
    if (w==0){
        float x = (lane < nw) ? sb[lane] : 0.f;
        #pragma unroll
        for (int o=16;o>0;o>>=1) x += __shfl_xor_sync(0xffffffffu, x, o);
        if (lane==0) sb[0] = x;
    }
    __syncthreads();
    float r = sb[0]; __syncthreads(); return r;
}
__device__ __forceinline__ u32 smem_u32(const void* p){
    u32 a;
    asm("{ .reg .u64 t; cvta.to.shared.u64 t, %1; cvt.u32.u64 %0, t; }" : "=r"(a) : "l"(p));
    return a;
}
__device__ __forceinline__ void mma16816(float* c, const u32* a, const u32* b){
    asm volatile(
        "mma.sync.aligned.m16n8k16.row.col.f32.bf16.bf16.f32 "
        "{%0,%1,%2,%3}, {%4,%5,%6,%7}, {%8,%9}, {%0,%1,%2,%3};"
        : "+f"(c[0]), "+f"(c[1]), "+f"(c[2]), "+f"(c[3])
        : "r"(a[0]), "r"(a[1]), "r"(a[2]), "r"(a[3]), "r"(b[0]), "r"(b[1]));
}
__device__ __forceinline__ void ldsm_x4(u32* r, u32 addr){
    asm volatile("ldmatrix.sync.aligned.m8n8.x4.shared.b16 {%0,%1,%2,%3}, [%4];"
        : "=r"(r[0]), "=r"(r[1]), "=r"(r[2]), "=r"(r[3]) : "r"(addr));
}
#define CP16(dst,src) asm volatile("cp.async.cg.shared.global [%0], [%1], 16;" :: "r"(dst), "l"(src))
#define CP_COMMIT()   asm volatile("cp.async.commit_group;" ::: "memory")
#define CP_WAIT1()    asm volatile("cp.async.wait_group 1;" ::: "memory")
#define CP_WAIT0()    asm volatile("cp.async.wait_group 0;" ::: "memory")

// --------------- HMMA split-precision GEMM (bf16 planes in, fused epi) -------
template<int BN,int EPI,bool OUTF,bool OUTP>
__global__ void __launch_bounds__(256,2)
hgemm(const bf16* __restrict__ A0h, const bf16* __restrict__ A0l,
      const bf16* __restrict__ A1h, const bf16* __restrict__ A1l,
      int ksplit, int lda0, int lda1,
      const bf16* __restrict__ Bh, const bf16* __restrict__ Bl, int ldb,
      float* __restrict__ Cf,
      bf16* __restrict__ Ph, bf16* __restrict__ Pl, int ldc,
      const float* __restrict__ bias, const float* __restrict__ res,
      int Kk, int Hdiv,
      long long zaB, long long zaH, long long zbB, long long zbH,
      long long zcB, long long zcH, float scale)
{
    constexpr int BM = 128, BK = 32;
    constexpr int STR = 80;
    constexpr int ASZ = BM*STR, BSZ = BN*STR;
    constexpr int STAGE = 2*ASZ + 2*BSZ;
    constexpr int TWN = BN/2, FN = TWN/8;

    extern __shared__ char sm[];
    int tid = threadIdx.x, lane = tid & 31, warp = tid >> 5;
    int wm = warp & 3, wn = warp >> 2;
    int g = lane >> 2, t4 = lane & 3;

    int z = blockIdx.z, zb = z / Hdiv, zh = z - zb*Hdiv;
    long long aoff = zb*zaB + zh*zaH, boff = zb*zbB + zh*zbH, coff = zb*zcB + zh*zcH;
    A0h += aoff; A0l += aoff; A1h += aoff; A1l += aoff;
    Bh  += boff; Bl  += boff;
    if (OUTF) Cf += coff;
    if (OUTP){ Ph += coff; Pl += coff; }
    if (EPI == 3) res += coff;
    int m0 = blockIdx.y*BM, n0 = blockIdx.x*BN;

    int arow = ((lane>>3)&1)*8 + (lane&7);
    int akc  = (lane>>4)*8;
    int brow = (lane>>4)*8 + (lane&7);
    int bkc  = ((lane>>3)&1)*8;

    float acc[2][FN][4];
    #pragma unroll
    for (int i=0;i<2;i++)
        #pragma unroll
        for (int j=0;j<FN;j++)
            #pragma unroll
            for (int q=0;q<4;q++) acc[i][j][q] = 0.f;

    u32 smbase = smem_u32(sm);
    int nch = Kk / BK;

    auto load_stage = [&](int ch, int s){
        int kg = ch*BK;
        const bf16 *pAh, *pAl; long long la;
        if (kg < ksplit){ pAh = A0h + (size_t)m0*lda0 + kg;          pAl = A0l + (size_t)m0*lda0 + kg;          la = lda0; }
        else            { pAh = A1h + (size_t)m0*lda1 + (kg-ksplit); pAl = A1l + (size_t)m0*lda1 + (kg-ksplit); la = lda1; }
        u32 sa = smbase + s*STAGE;
        #pragma unroll
        for (int it=0; it<BM*4/256; it++){
            int idx = it*256 + tid, r = idx>>2, c = idx&3;
            CP16(sa + r*STR + c*16,        pAh + (size_t)r*la + c*8);
            CP16(sa + ASZ + r*STR + c*16,  pAl + (size_t)r*la + c*8);
        }
        u32 sb = sa + 2*ASZ;
        const bf16* pBh = Bh + (size_t)n0*ldb + kg;
        const bf16* pBl = Bl + (size_t)n0*ldb + kg;
        #pragma unroll
        for (int it=0; it<BN*4/256 || it<1; it++){
            int idx = it*256 + tid, r = idx>>2, c = idx&3;
            if (BN*4 >= 256 || idx < BN*4){
                CP16(sb + r*STR + c*16,        pBh + (size_t)r*ldb + c*8);
                CP16(sb + BSZ + r*STR + c*16,  pBl + (size_t)r*ldb + c*8);
            }
        }
    };

    load_stage(0, 0); CP_COMMIT();

    for (int ch = 0; ch < nch; ch++){
        int s = ch & 1;
        if (ch+1 < nch){ load_stage(ch+1, (ch+1)&1); CP_COMMIT(); CP_WAIT1(); }
        else CP_WAIT0();
        __syncthreads();

        u32 sa = smbase + s*STAGE;
        u32 sAh = sa, sAl = sa + ASZ, sBh = sa + 2*ASZ, sBl = sa + 2*ASZ + BSZ;
        #pragma unroll
        for (int kk=0; kk<BK; kk+=16){
            u32 ah[2][4], al[2][4], bh[FN][2], bl[FN][2];
            #pragma unroll
            for (int fm=0; fm<2; fm++){
                u32 ra = (wm*32 + fm*16 + arow)*STR + (kk + akc)*2;
                ldsm_x4(ah[fm], sAh + ra);
                ldsm_x4(al[fm], sAl + ra);
            }
            #pragma unroll
            for (int fp=0; fp<FN/2; fp++){
                u32 rb = (wn*TWN + fp*16 + brow)*STR + (kk + bkc)*2;
                u32 t[4];
                ldsm_x4(t, sBh + rb);
                bh[2*fp][0]=t[0]; bh[2*fp][1]=t[1]; bh[2*fp+1][0]=t[2]; bh[2*fp+1][1]=t[3];
                ldsm_x4(t, sBl + rb);
                bl[2*fp][0]=t[0]; bl[2*fp][1]=t[1]; bl[2*fp+1][0]=t[2]; bl[2*fp+1][1]=t[3];
            }
            #pragma unroll
            for (int fm=0; fm<2; fm++)
                #pragma unroll
                for (int fn=0; fn<FN; fn++){
                    mma16816(acc[fm][fn], ah[fm], bh[fn]);
                    mma16816(acc[fm][fn], ah[fm], bl[fn]);
                    mma16816(acc[fm][fn], al[fm], bh[fn]);
                }
        }
        __syncthreads();
    }

    #pragma unroll
    for (int fm=0; fm<2; fm++){
        #pragma unroll
        for (int fn=0; fn<FN; fn++){
            int col = n0 + wn*TWN + fn*8 + 2*t4;
            #pragma unroll
            for (int half=0; half<2; half++){
                int row = m0 + wm*32 + fm*16 + g + half*8;
                float v0 = acc[fm][fn][2*half+0]*scale;
                float v1 = acc[fm][fn][2*half+1]*scale;
                if (EPI >= 1){ v0 += bias[col]; v1 += bias[col+1]; }
                if (EPI == 2){
                    v0 = 0.5f*v0*(1.0f + erff(v0*0.70710678118654752f));
                    v1 = 0.5f*v1*(1.0f + erff(v1*0.70710678118654752f));
                }
                if (EPI == 3){
                    float2 rr = *(const float2*)(res + (size_t)row*ldc + col);
                    v0 += rr.x; v1 += rr.y;
                }
                if (OUTF){ float2 o; o.x=v0; o.y=v1; *(float2*)(Cf + (size_t)row*ldc + col) = o; }
                if (OUTP){
                    u32 hp, lp; pksplit(v0, v1, hp, lp);
                    *(u32*)(Ph + (size_t)row*ldc + col) = hp;
                    *(u32*)(Pl + (size_t)row*ldc + col) = lp;
                }
            }
        }
    }
}

// ------------------------- flash attention (fused) ---------------------------
// Per CTA: one (b,h), 128 query rows, 8 warps x 16 rows. 64-key chunks so the
// double-buffered stage fits 2 CTAs/SM (73.7 KB total). Online softmax in
// log2 domain: p = 2^((s-m)*C), C = log2(e)/8.
__global__ void __launch_bounds__(256,2)
flash_attn(void){
    constexpr int KSTR=144, VSTR=144;
    constexpr int KSZ=64*KSTR, VSZ=64*VSTR;   // 9216 each
    constexpr int QSZ=128*KSTR;               // 18432 (staging only)
    constexpr int STAGE=2*KSZ+2*VSZ;          // 36864
    const float C = 0.18033688011112042f;     // log2(e)/8
    extern __shared__ char sm[];
    int tid=threadIdx.x, lane=tid&31, w=tid>>5;
    int g=lane>>2, t4=lane&3;
    int arow=((lane>>3)&1)*8+(lane&7), akc=(lane>>4)*8;
    int brow=(lane>>4)*8+(lane&7),     bkc=((lane>>3)&1)*8;
    int qblk=blockIdx.x, z=blockIdx.y;
    int b=z/HH, h=z-b*HH;
    const bf16* Qh=g_qh+((size_t)(b*NN+qblk*128))*(3*DD)+h*64;
    const bf16* Ql=g_ql+((size_t)(b*NN+qblk*128))*(3*DD)+h*64;
    const bf16* Kh=g_qh+((size_t)b*NN)*(3*DD)+DD+h*64;
    const bf16* Kl=g_ql+((size_t)b*NN)*(3*DD)+DD+h*64;
    const bf16* Vh=g_vth+(size_t)z*64*NN;
    const bf16* Vl=g_vtl+(size_t)z*64*NN;
    u32 smb=smem_u32(sm);

    // ---- load Q tile (128 rows x 128 B) into smem transiently, to regs ----
    #pragma unroll
    for(int it=0; it<4; it++){
        int idx=it*256+tid, r=idx>>3, c=idx&7;
        CP16(smb + r*KSTR + c*16,       Qh + (size_t)r*(3*DD) + c*8);
        CP16(smb + QSZ + r*KSTR + c*16, Ql + (size_t)r*(3*DD) + c*8);
    }
    CP_COMMIT(); CP_WAIT0(); __syncthreads();
    u32 qha[4][4], qla[4][4];
    #pragma unroll
    for(int kk=0;kk<4;kk++){
        u32 ra=(w*16+arow)*KSTR+(kk*16+akc)*2;
        ldsm_x4(qha[kk], smb+ra);
        ldsm_x4(qla[kk], smb+QSZ+ra);
    }
    __syncthreads();

    auto load_kv=[&](int kt,int s){
        u32 sa=smb+(u32)s*STAGE;
        #pragma unroll
        for(int it=0;it<2;it++){
            int idx=it*256+tid, r=idx>>3, c=idx&7;
            CP16(sa + r*KSTR + c*16,       Kh + (size_t)(kt*64+r)*(3*DD) + c*8);
            CP16(sa + KSZ + r*KSTR + c*16, Kl + (size_t)(kt*64+r)*(3*DD) + c*8);
        }
        u32 sv=sa+2*KSZ;
        #pragma unroll
        for(int it=0;it<2;it++){
            int idx=it*256+tid, r=idx>>3, c=idx&7;
            CP16(sv + r*VSTR + c*16,       Vh + (size_t)r*NN + kt*64 + c*8);
            CP16(sv + VSZ + r*VSTR + c*16, Vl + (size_t)r*NN + kt*64 + c*8);
        }
    };

    float o[8][4];
    #pragma unroll
    for(int t=0;t<8;t++){ o[t][0]=0.f; o[t][1]=0.f; o[t][2]=0.f; o[t][3]=0.f; }
    float mA=-1e30f, mB=-1e30f, lA=0.f, lB=0.f;

    load_kv(0,0); CP_COMMIT();

    for(int kt=0; kt<NN/64; kt++){
        int s=kt&1;
        if(kt+1<NN/64){ load_kv(kt+1,s^1); CP_COMMIT(); CP_WAIT1(); } else CP_WAIT0();
        __syncthreads();
        u32 sK=smb+(u32)s*STAGE, sKl=sK+KSZ, sV=sK+2*KSZ, sVl=sV+VSZ;

        // ---- S = Q K^T (64 keys), 3-term split ----
        float sa2[8][4];
        #pragma unroll
        for(int t=0;t<8;t++){ sa2[t][0]=0.f; sa2[t][1]=0.f; sa2[t][2]=0.f; sa2[t][3]=0.f; }
        #pragma unroll
        for(int np=0;np<4;np++){
            #pragma unroll
            for(int kk=0;kk<4;kk++){
                u32 bh[4],bl[4];
                u32 rb=(np*16+brow)*KSTR+(kk*16+bkc)*2;
                ldsm_x4(bh,sK+rb); ldsm_x4(bl,sKl+rb);
                mma16816(sa2[2*np],   qha[kk], bh+0);
                mma16816(sa2[2*np],   qha[kk], bl+0);
                mma16816(sa2[2*np],   qla[kk], bh+0);
                mma16816(sa2[2*np+1], qha[kk], bh+2);
                mma16816(sa2[2*np+1], qha[kk], bl+2);
                mma16816(sa2[2*np+1], qla[kk], bh+2);
            }
        }
        // ---- online softmax (log2 domain, raw-score max) ----
        float mxA=-1e30f, mxB=-1e30f;
        #pragma unroll
        for(int t=0;t<8;t++){
            mxA=fmaxf(mxA,fmaxf(sa2[t][0],sa2[t][1]));
            mxB=fmaxf(mxB,fmaxf(sa2[t][2],sa2[t][3]));
        }
        mxA=fmaxf(mxA,__shfl_xor_sync(0xffffffffu,mxA,1));
        mxA=fmaxf(mxA,__shfl_xor_sync(0xffffffffu,mxA,2));
        mxB=fmaxf(mxB,__shfl_xor_sync(0xffffffffu,mxB,1));
        mxB=fmaxf(mxB,__shfl_xor_sync(0xffffffffu,mxB,2));
        float mAn=fmaxf(mA,mxA), mBn=fmaxf(mB,mxB);
        float scA=ex2((mA-mAn)*C), scB=ex2((mB-mBn)*C);
        mA=mAn; mB=mBn;
        float cA=mA*C, cB=mB*C;
        lA*=scA; lB*=scB;
        #pragma unroll
        for(int t=0;t<8;t++){
            sa2[t][0]=ex2(fmaf(sa2[t][0],C,-cA)); sa2[t][1]=ex2(fmaf(sa2[t][1],C,-cA));
            sa2[t][2]=ex2(fmaf(sa2[t][2],C,-cB)); sa2[t][3]=ex2(fmaf(sa2[t][3],C,-cB));
            lA+=sa2[t][0]+sa2[t][1]; lB+=sa2[t][2]+sa2[t][3];
        }
        #pragma unroll
        for(int t=0;t<8;t++){ o[t][0]*=scA; o[t][1]*=scA; o[t][2]*=scB; o[t][3]*=scB; }
        // ---- O += P V^T, P split in registers (acc layout == A layout) ----
        #pragma unroll
        for(int kk=0;kk<4;kk++){
            u32 pah[4],pal[4];
            pksplit(sa2[2*kk][0],   sa2[2*kk][1],   pah[0], pal[0]);
            pksplit(sa2[2*kk][2],   sa2[2*kk][3],   pah[1], pal[1]);
            pksplit(sa2[2*kk+1][0], sa2[2*kk+1][1], pah[2], pal[2]);
            pksplit(sa2[2*kk+1][2], sa2[2*kk+1][3], pah[3], pal[3]);
            #pragma unroll
            for(int hp=0;hp<4;hp++){
                u32 vh[4],vl[4];
                u32 rb=(hp*16+brow)*VSTR+(kk*16+bkc)*2;
                ldsm_x4(vh,sV+rb); ldsm_x4(vl,sVl+rb);
                mma16816(o[2*hp],   pah, vh+0);
                mma16816(o[2*hp],   pah, vl+0);
                mma16816(o[2*hp],   pal, vh+0);
                mma16816(o[2*hp+1], pah, vh+2);
                mma16816(o[2*hp+1], pah, vl+2);
                mma16816(o[2*hp+1], pal, vh+2);
            }
        }
        __syncthreads();
    }
    lA+=__shfl_xor_sync(0xffffffffu,lA,1); lA+=__shfl_xor_sync(0xffffffffu,lA,2);
    lB+=__shfl_xor_sync(0xffffffffu,lB,1); lB+=__shfl_xor_sync(0xffffffffu,lB,2);
    float iA=1.f/lA, iB=1.f/lB;
    int rowA=qblk*128+w*16+g, rowB=rowA+8;
    bf16* Oh=g_ath+((size_t)b*NN)*DD;
    bf16* Ol=g_atl+((size_t)b*NN)*DD;
    #pragma unroll
    for(int t=0;t<8;t++){
        int col=h*64+t*8+2*t4;
        u32 hp, lp;
        pksplit(o[t][0]*iA, o[t][1]*iA, hp, lp);
        *(u32*)(Oh+(size_t)rowA*DD+col)=hp;
        *(u32*)(Ol+(size_t)rowA*DD+col)=lp;
        pksplit(o[t][2]*iB, o[t][3]*iB, hp, lp);
        *(u32*)(Oh+(size_t)rowB*DD+col)=hp;
        *(u32*)(Ol+(size_t)rowB*DD+col)=lp;
    }
}

// ------------------------------ prep / misc ----------------------------------
__global__ void copy_coords(const float* __restrict__ pts, float* __restrict__ outp){
    int i = blockIdx.x*blockDim.x + threadIdx.x;
    if (i < BB*3*NN){
        int b = i / (3*NN), r = i % (3*NN);
        outp[(size_t)b*CH*NN + r] = pts[(size_t)b*CH*NN + r];
    }
}
__global__ void prep_kernel(const float* __restrict__ knn_w, const float* __restrict__ knn_b){
    int i = blockIdx.x*blockDim.x + threadIdx.x;
    if (i < DD*2*DD){
        int r = i / (2*DD), c = i % (2*DD);
        float v;
        if (c < DD) v = knn_w[r*DD + c];
        else { int cc = c - DD; v = knn_w[(DD + r)*DD + cc] - knn_w[r*DD + cc]; }
        g_wc[i] = v;
    }
    if (i < 2*DD) g_kbias[i] = (i < DD) ? 0.f : knn_b[i-DD];
}
__global__ void sq_kernel(const float* __restrict__ pts){
    int i = blockIdx.x*blockDim.x + threadIdx.x;
    if (i < ROWS){
        int b = i >> 12, n = i & 4095;
        const float* base = pts + (size_t)b*CH*NN;
        float x = base[n], y = base[NN+n], z = base[2*NN+n];
        g_sq[i] = x*x + y*y + z*z;
    }
}
__global__ void wt_conv(const float* __restrict__ W, int K, int N,
                        bf16* __restrict__ oh, bf16* __restrict__ ol){
    __shared__ float t[32][33];
    int k0 = blockIdx.x*32, n0 = blockIdx.y*32;
    for (int r = threadIdx.y; r < 32; r += 8)
        t[r][threadIdx.x] = W[(size_t)(k0+r)*N + n0 + threadIdx.x];
    __syncthreads();
    for (int r = threadIdx.y; r < 32; r += 8){
        float v = t[threadIdx.x][r];
        bf16 h,l; split2(v,h,l);
        size_t o = (size_t)(n0+r)*K + k0 + threadIdx.x;
        oh[o] = h; ol[o] = l;
    }
}
__global__ void vt_conv(void){
    __shared__ bf16 th[32][33], tl[32][33];
    int z = blockIdx.z, b = z / HH, h = z % HH;
    int n0 = blockIdx.x*32, f0 = blockIdx.y*32;
    for (int r = threadIdx.y; r < 32; r += 8){
        size_t src = (size_t)(b*NN + n0 + r)*(3*DD) + 2*DD + h*64 + f0 + threadIdx.x;
        th[r][threadIdx.x] = g_qh[src];
        tl[r][threadIdx.x] = g_ql[src];
    }
    __syncthreads();
    for (int r = threadIdx.y; r < 32; r += 8){
        size_t dst = ((size_t)z*64 + f0 + r)*NN + n0 + threadIdx.x;
        g_vth[dst] = th[threadIdx.x][r];
        g_vtl[dst] = tl[threadIdx.x][r];
    }
}
__global__ void transpose_in(const float* __restrict__ pts, float* __restrict__ dst){
    __shared__ float tile[32][33];
    int b = blockIdx.z, n0 = blockIdx.x*32, d0 = blockIdx.y*32;
    const float* src = pts + (size_t)b*CH*NN;
    for (int r = threadIdx.y; r < 32; r += 8)
        tile[r][threadIdx.x] = src[(size_t)(3+d0+r)*NN + n0 + threadIdx.x];
    __syncthreads();
    float* o = dst + (size_t)b*NN*DD;
    for (int r = threadIdx.y; r < 32; r += 8)
        o[(size_t)(n0+r)*DD + d0 + threadIdx.x] = tile[threadIdx.x][r];
}
__global__ void transpose_out(const float* __restrict__ fin, float* __restrict__ outp){
    __shared__ float tile[32][33];
    int b = blockIdx.z, n0 = blockIdx.x*32, d0 = blockIdx.y*32;
    const float* src = fin + (size_t)b*NN*DD;
    for (int r = threadIdx.y; r < 32; r += 8)
        tile[r][threadIdx.x] = src[(size_t)(n0+r)*DD + d0 + threadIdx.x];
    __syncthreads();
    float* dst = outp + (size_t)b*CH*NN;
    for (int r = threadIdx.y; r < 32; r += 8)
        dst[(size_t)(3+d0+r)*NN + n0 + threadIdx.x] = tile[threadIdx.x][r];
}
__global__ void ln_rows(const float* __restrict__ in,
                        const float* __restrict__ gam, const float* __restrict__ bet,
                        float* __restrict__ outf,
                        bf16* __restrict__ outh, bf16* __restrict__ outl){
    __shared__ float sb[8];
    int row = blockIdx.x, tid = threadIdx.x;
    const float* x = in + (size_t)row*DD;
    float v[3]; float s = 0.f;
    #pragma unroll
    for (int i=0;i<3;i++){ v[i] = x[tid + i*128]; s += v[i]; }
    s = block_sum(s, sb);
    float mean = s * (1.0f/DD), q = 0.f;
    #pragma unroll
    for (int i=0;i<3;i++){ float c = v[i]-mean; q += c*c; }
    q = block_sum(q, sb);
    float rinv = rsqrtf(q*(1.0f/DD) + 1e-5f);
    #pragma unroll
    for (int i=0;i<3;i++){
        int d = tid + i*128;
        float o = (v[i]-mean)*rinv*gam[d] + bet[d];
        size_t idx = (size_t)row*DD + d;
        if (outf) outf[idx] = o;
        if (outh){ bf16 h,l; split2(o,h,l); outh[idx]=h; outl[idx]=l; }
    }
}
// ------------------------------ KNN (top-8) ----------------------------------
__global__ void __launch_bounds__(256)
knn_kernel(const float* __restrict__ pts){
    __shared__ u64 sk[256*KNN];
    int row = blockIdx.x;
    int b = row >> 12, n = row & 4095;
    const float* base = pts + (size_t)b*CH*NN;
    float qx = base[n], qy = base[NN+n], qz = base[2*NN+n];
    float sqn = g_sq[row];
    const float* sqb = g_sq + (size_t)b*NN;

    u64 key[KNN];
    #pragma unroll
    for (int j=0;j<KNN;j++) key[j] = ~0ull;

    for (int m = threadIdx.x; m < NN; m += 256){
        float d2 = sqn + sqb[m]
                 - 2.0f*(qx*base[m] + qy*base[NN+m] + qz*base[2*NN+m]);
        d2 = fmaxf(d2, 0.0f);
        u64 kk = ((u64)__float_as_uint(d2) << 32) | (unsigned)m;
        if (kk < key[KNN-1]){
            key[KNN-1] = kk;
            #pragma unroll
            for (int j=KNN-1;j>0;j--){
                u64 a = key[j-1], c = key[j];
                key[j-1] = (c < a) ? c : a;
                key[j]   = (c < a) ? a : c;
            }
        }
    }
    #pragma unroll
    for (int j=0;j<KNN;j++) sk[threadIdx.x*KNN+j] = key[j];

    for (int s=128; s>0; s>>=1){
        __syncthreads();
        if ((int)threadIdx.x < s){
            int pa = threadIdx.x*KNN, pb = (threadIdx.x+s)*KNN;
            u64 outk[KNN]; int ia=0, ib=0;
            #pragma unroll
            for (int r=0;r<KNN;r++){
                u64 va = sk[pa+ia], vb = sk[pb+ib];
                if (va <= vb){ outk[r]=va; ia++; } else { outk[r]=vb; ib++; }
            }
            #pragma unroll
            for (int r=0;r<KNN;r++) sk[pa+r] = outk[r];
        }
    }
    __syncthreads();
    if (threadIdx.x < KNN)
        g_idx[(size_t)row*KNN + threadIdx.x] = (int)(unsigned)(sk[threadIdx.x] & 0xffffffffu);
}
// ------------------------- gather + lrelu + max ------------------------------
__global__ void __launch_bounds__(128) geom_kernel(void){
    __shared__ int sidx[KNN];
    int row = blockIdx.x, tid = threadIdx.x;
    int gb = row >> 12;
    if (tid < KNN) sidx[tid] = gb*NN + g_idx[(size_t)row*KNN + tid];
    __syncthreads();
    #pragma unroll
    for (int i=0;i<3;i++){
        int d = tid + i*128;
        float c = g_ka[(size_t)row*(2*DD) + DD + d];
        float mx = -FLT_MAX;
        #pragma unroll
        for (int k=0;k<KNN;k++){
            float v = g_ka[(size_t)sidx[k]*(2*DD) + d] + c;
            v = (v > 0.f) ? v : 0.2f*v;
            mx = fmaxf(mx, v);
        }
        bf16 h,l; split2(mx,h,l);
        g_gh[(size_t)row*DD + d] = h;
        g_gl[(size_t)row*DD + d] = l;
    }
}

// ------------------------------ launch ---------------------------------------
extern "C" void kernel_launch(void* const* d_in, const int* in_sizes, int n_in,
                              void* d_out, int out_size) {
    const float* pts        = (const float*)d_in[0];
    const float* ln1_g      = (const float*)d_in[1];
    const float* ln1_b      = (const float*)d_in[2];
    const float* qkv_w      = (const float*)d_in[3];
    const float* attn_out_w = (const float*)d_in[4];
    const float* attn_out_b = (const float*)d_in[5];
    const float* knn_w      = (const float*)d_in[6];
    const float* knn_b      = (const float*)d_in[7];
    const float* merge_w    = (const float*)d_in[8];
    const float* merge_b    = (const float*)d_in[9];
    const float* ln2_g      = (const float*)d_in[10];
    const float* ln2_b      = (const float*)d_in[11];
    const float* ff1_w      = (const float*)d_in[12];
    const float* ff1_b      = (const float*)d_in[13];
    const float* ff2_w      = (const float*)d_in[14];
    const float* ff2_b      = (const float*)d_in[15];
    float* outp = (float*)d_out;

    #define GSA(v,s) cudaGetSymbolAddress((void**)&v, s)
    float *p_tmp,*p_attnp,*p_ka,*p_m,*p_y,*p_fout,*p_wc,*p_kb;
    bf16 *p_nfh,*p_nfl,*p_qh,*p_ql,*p_vth,*p_vtl,*p_ath,*p_atl;
    bf16 *p_aph,*p_apl,*p_gh,*p_gl,*p_yh,*p_yl,*p_hh,*p_hl;
    bf16 *p_wqh,*p_wql,*p_woh,*p_wol,*p_wch,*p_wcl,*p_wmh,*p_wml,*p_w1h,*p_w1l,*p_w2h,*p_w2l;
    GSA(p_tmp,g_tmp); GSA(p_attnp,g_attnp); GSA(p_ka,g_ka);
    GSA(p_m,g_m); GSA(p_y,g_y); GSA(p_fout,g_fout); GSA(p_wc,g_wc); GSA(p_kb,g_kbias);
    GSA(p_nfh,g_nfh); GSA(p_nfl,g_nfl); GSA(p_qh,g_qh); GSA(p_ql,g_ql);
    GSA(p_vth,g_vth); GSA(p_vtl,g_vtl);
    GSA(p_ath,g_ath); GSA(p_atl,g_atl); GSA(p_aph,g_aph); GSA(p_apl,g_apl);
    GSA(p_gh,g_gh); GSA(p_gl,g_gl); GSA(p_yh,g_yh); GSA(p_yl,g_yl);
    GSA(p_hh,g_hh); GSA(p_hl,g_hl);
    GSA(p_wqh,g_wqh); GSA(p_wql,g_wql); GSA(p_woh,g_woh); GSA(p_wol,g_wol);
    GSA(p_wch,g_wch); GSA(p_wcl,g_wcl); GSA(p_wmh,g_wmh); GSA(p_wml,g_wml);
    GSA(p_w1h,g_w1h); GSA(p_w1l,g_w1l); GSA(p_w2h,g_w2h); GSA(p_w2l,g_w2l);

    const int SM128 = 2*(2*128*80 + 2*128*80);   // 81920
    const int SMFL  = 2*(2*64*144 + 2*64*144);   // 73728
    cudaFuncSetAttribute(hgemm<128,0,false,true>,  cudaFuncAttributeMaxDynamicSharedMemorySize, SM128);
    cudaFuncSetAttribute(hgemm<128,1,true ,true>,  cudaFuncAttributeMaxDynamicSharedMemorySize, SM128);
    cudaFuncSetAttribute(hgemm<128,1,true ,false>, cudaFuncAttributeMaxDynamicSharedMemorySize, SM128);
    cudaFuncSetAttribute(hgemm<128,3,true ,false>, cudaFuncAttributeMaxDynamicSharedMemorySize, SM128);
    cudaFuncSetAttribute(hgemm<128,2,false,true>,  cudaFuncAttributeMaxDynamicSharedMemorySize, SM128);
    cudaFuncSetAttribute(flash_attn, cudaFuncAttributeMaxDynamicSharedMemorySize, SMFL);

    // side streams + fork/join events (created+destroyed every call; capture-safe)
    cudaStream_t s2, s3;
    cudaStreamCreateWithFlags(&s2, cudaStreamNonBlocking);
    cudaStreamCreateWithFlags(&s3, cudaStreamNonBlocking);
    cudaEvent_t eRoot, eNf, eGeom, eW;
    cudaEventCreateWithFlags(&eRoot, cudaEventDisableTiming);
    cudaEventCreateWithFlags(&eNf,   cudaEventDisableTiming);
    cudaEventCreateWithFlags(&eGeom, cudaEventDisableTiming);
    cudaEventCreateWithFlags(&eW,    cudaEventDisableTiming);

    dim3 t328(32,8);
    // ---- main chain (stream 0) ----
    transpose_in<<<dim3(NN/32, DD/32, BB), t328>>>(pts, p_tmp);
    cudaEventRecord(eRoot, 0);
    ln_rows<<<ROWS,128>>>(p_tmp, ln1_g, ln1_b, nullptr, p_nfh, p_nfl);
    cudaEventRecord(eNf, 0);
    wt_conv<<<dim3(DD/32, 3*DD/32), t328>>>(qkv_w, DD, 3*DD, p_wqh, p_wql);
    hgemm<128,0,false,true><<<dim3(9,64,1),256,SM128>>>(                  // QKV
        p_nfh,p_nfl,p_nfh,p_nfl, DD, DD, DD,
        p_wqh,p_wql, DD,
        nullptr, p_qh,p_ql, 3*DD, nullptr,nullptr,
        DD, 1, 0,0, 0,0, 0,0, 1.0f);
    vt_conv<<<dim3(NN/32, 2, BB*HH), t328>>>();
    flash_attn<<<dim3(NN/128, BB*HH),256,SMFL>>>();

    // ---- s3: weight-plane converts (overlap with flash) ----
    cudaStreamWaitEvent(s3, eRoot, 0);
    wt_conv<<<dim3(DD/32, DD/32),   t328, 0, s3>>>(attn_out_w, DD, DD,   p_woh, p_wol);
    wt_conv<<<dim3(2*DD/32, DD/32), t328, 0, s3>>>(merge_w,  2*DD, DD,   p_wmh, p_wml);
    wt_conv<<<dim3(DD/32, 2*DD/32), t328, 0, s3>>>(ff1_w,      DD, 2*DD, p_w1h, p_w1l);
    wt_conv<<<dim3(2*DD/32, DD/32), t328, 0, s3>>>(ff2_w,    2*DD, DD,   p_w2h, p_w2l);
    cudaEventRecord(eW, s3);

    // ---- s2: KNN branch (overlap with flash) ----
    cudaStreamWaitEvent(s2, eRoot, 0);
    prep_kernel<<<(DD*2*DD+255)/256,256,0,s2>>>(knn_w, knn_b);
    wt_conv<<<dim3(DD/32, 2*DD/32), t328, 0, s2>>>(p_wc, DD, 2*DD, p_wch, p_wcl);
    sq_kernel<<<(ROWS+255)/256,256,0,s2>>>(pts);
    knn_kernel<<<ROWS,256,0,s2>>>(pts);
    cudaStreamWaitEvent(s2, eNf, 0);
    hgemm<128,1,true,false><<<dim3(6,64,1),256,SM128,s2>>>(
        p_nfh,p_nfl,p_nfh,p_nfl, DD, DD, DD,
        p_wch,p_wcl, DD,
        p_ka, nullptr,nullptr, 2*DD, p_kb,nullptr,
        DD, 1, 0,0, 0,0, 0,0, 1.0f);
    geom_kernel<<<ROWS,128,0,s2>>>();
    cudaEventRecord(eGeom, s2);

    // ---- main chain continues ----
    cudaStreamWaitEvent(0, eW, 0);
    hgemm<128,1,true,true><<<dim3(3,64,1),256,SM128>>>(                   // proj
        p_ath,p_atl,p_ath,p_atl, DD, DD, DD,
        p_woh,p_wol, DD,
        p_attnp, p_aph,p_apl, DD, attn_out_b,nullptr,
        DD, 1, 0,0, 0,0, 0,0, 1.0f);
    cudaStreamWaitEvent(0, eGeom, 0);
    hgemm<128,3,true,false><<<dim3(3,64,1),256,SM128>>>(                  // merge
        p_aph,p_apl, p_gh,p_gl, DD, DD, DD,
        p_wmh,p_wml, 2*DD,
        p_m, nullptr,nullptr, DD, merge_b, p_attnp,
        2*DD, 1, 0,0, 0,0, 0,0, 1.0f);
    ln_rows<<<ROWS,128>>>(p_m, ln2_g, ln2_b, p_y, p_yh, p_yl);
    hgemm<128,2,false,true><<<dim3(6,64,1),256,SM128>>>(                  // ff1
        p_yh,p_yl,p_yh,p_yl, DD, DD, DD,
        p_w1h,p_w1l, DD,
        nullptr, p_hh,p_hl, 2*DD, ff1_b,nullptr,
        DD, 1, 0,0, 0,0, 0,0, 1.0f);
    hgemm<128,3,true,false><<<dim3(3,64,1),256,SM128>>>(                  // ff2
        p_hh,p_hl,p_hh,p_hl, 2*DD, 2*DD, 2*DD,
        p_w2h,p_w2l, 2*DD,
        p_fout, nullptr,nullptr, DD, ff2_b, p_y,
        2*DD, 1, 0,0, 0,0, 0,0, 1.0f);

    copy_coords<<<(BB*3*NN+255)/256,256>>>(pts, outp);
    transpose_out<<<dim3(NN/32, DD/32, BB), t328>>>(p_fout, outp);

    cudaEventDestroy(eRoot); cudaEventDestroy(eNf);
    cudaEventDestroy(eGeom); cudaEventDestroy(eW);
    cudaStreamDestroy(s2); cudaStreamDestroy(s3);
}

// round 14
// speedup vs baseline: 2.8076x; 1.0059x over previous
#include <cuda_runtime.h>
#include <cuda_bf16.h>
#include <float.h>
#include <math.h>
#include <stdint.h>

#define BB   2
#define NN   4096
#define DD   384
#define HH   6
#define KNN  8
#define CH   387
#define ROWS (BB*NN)

typedef unsigned long long u64;
typedef unsigned int u32;
typedef __nv_bfloat16 bf16;

// ------------------------- scratch (static device mem) ----------------------
__device__ float g_tmp  [ROWS*DD];
__device__ bf16  g_nfh  [ROWS*DD];
__device__ bf16  g_nfl  [ROWS*DD];
__device__ bf16  g_qh   [ROWS*3*DD];
__device__ bf16  g_ql   [ROWS*3*DD];
__device__ bf16  g_vth  [BB*HH*64*NN];
__device__ bf16  g_vtl  [BB*HH*64*NN];
__device__ bf16  g_ath  [ROWS*DD];
__device__ bf16  g_atl  [ROWS*DD];
__device__ float g_attnp[ROWS*DD];
__device__ bf16  g_aph  [ROWS*DD];
__device__ bf16  g_apl  [ROWS*DD];
__device__ float g_ka   [ROWS*2*DD];
__device__ bf16  g_gh   [ROWS*DD];
__device__ bf16  g_gl   [ROWS*DD];
__device__ float g_m    [ROWS*DD];
__device__ float g_y    [ROWS*DD];
__device__ bf16  g_yh   [ROWS*DD];
__device__ bf16  g_yl   [ROWS*DD];
__device__ bf16  g_hh   [ROWS*2*DD];
__device__ bf16  g_hl   [ROWS*2*DD];
__device__ float g_fout [ROWS*DD];
__device__ float g_wc   [DD*2*DD];
__device__ float g_kbias[2*DD];
__device__ float g_sq   [ROWS];
__device__ int   g_idx  [ROWS*KNN];
// transposed+split weights ([n][k] planes)
__device__ bf16  g_wqh[3*DD*DD], g_wql[3*DD*DD];
__device__ bf16  g_woh[DD*DD],   g_wol[DD*DD];
__device__ bf16  g_wch[2*DD*DD], g_wcl[2*DD*DD];
__device__ bf16  g_wmh[2*DD*DD], g_wml[2*DD*DD];
__device__ bf16  g_w1h[2*DD*DD], g_w1l[2*DD*DD];
__device__ bf16  g_w2h[2*DD*DD], g_w2l[2*DD*DD];

// ------------------------------ helpers -------------------------------------
__device__ __forceinline__ void split2(float v, bf16& h, bf16& l){
    h = __float2bfloat16(v);
    l = __float2bfloat16(v - __bfloat162float(h));
}
__device__ __forceinline__ u32 pk(bf16 a, bf16 b){
    return ((u32)__bfloat16_as_ushort(b) << 16) | (u32)__bfloat16_as_ushort(a);
}
__device__ __forceinline__ void pksplit(float f0, float f1, u32& hp, u32& lp){
    asm("cvt.rn.bf16x2.f32 %0, %1, %2;" : "=r"(hp) : "f"(f1), "f"(f0));
    float h0 = __uint_as_float(hp << 16);
    float h1 = __uint_as_float(hp & 0xffff0000u);
    asm("cvt.rn.bf16x2.f32 %0, %1, %2;" : "=r"(lp) : "f"(f1 - h1), "f"(f0 - h0));
}
__device__ __forceinline__ float ex2(float x){
    float r; asm("ex2.approx.f32 %0, %1;" : "=f"(r) : "f"(x)); return r;
}
__device__ __forceinline__ float block_sum(float v, float* sb){
    #pragma unroll
    for (int o=16;o>0;o>>=1) v += __shfl_xor_sync(0xffffffffu, v, o);
    int lane = threadIdx.x & 31, w = threadIdx.x >> 5, nw = blockDim.x >> 5;
    if (lane==0) sb[w] = v;
    __syncthreads();
    if (w==0){
        float x = (lane < nw) ? sb[lane] : 0.f;
        #pragma unroll
        for (int o=16;o>0;o>>=1) x += __shfl_xor_sync(0xffffffffu, x, o);
        if (lane==0) sb[0] = x;
    }
    __syncthreads();
    float r = sb[0]; __syncthreads(); return r;
}
__device__ __forceinline__ u32 smem_u32(const void* p){
    u32 a;
    asm("{ .reg .u64 t; cvta.to.shared.u64 t, %1; cvt.u32.u64 %0, t; }" : "=r"(a) : "l"(p));
    return a;
}
__device__ __forceinline__ void mma16816(float* c, const u32* a, const u32* b){
    asm volatile(
        "mma.sync.aligned.m16n8k16.row.col.f32.bf16.bf16.f32 "
        "{%0,%1,%2,%3}, {%4,%5,%6,%7}, {%8,%9}, {%0,%1,%2,%3};"
        : "+f"(c[0]), "+f"(c[1]), "+f"(c[2]), "+f"(c[3])
        : "r"(a[0]), "r"(a[1]), "r"(a[2]), "r"(a[3]), "r"(b[0]), "r"(b[1]));
}
__device__ __forceinline__ void ldsm_x4(u32* r, u32 addr){
    asm volatile("ldmatrix.sync.aligned.m8n8.x4.shared.b16 {%0,%1,%2,%3}, [%4];"
        : "=r"(r[0]), "=r"(r[1]), "=r"(r[2]), "=r"(r[3]) : "r"(addr));
}
#define CP16(dst,src) asm volatile("cp.async.cg.shared.global [%0], [%1], 16;" :: "r"(dst), "l"(src))
#define CP_COMMIT()   asm volatile("cp.async.commit_group;" ::: "memory")
#define CP_WAIT1()    asm volatile("cp.async.wait_group 1;" ::: "memory")
#define CP_WAIT0()    asm volatile("cp.async.wait_group 0;" ::: "memory")

// --------------- HMMA split-precision GEMM (bf16 planes in, fused epi) -------
template<int BN,int EPI,bool OUTF,bool OUTP>
__global__ void __launch_bounds__(256,2)
hgemm(const bf16* __restrict__ A0h, const bf16* __restrict__ A0l,
      const bf16* __restrict__ A1h, const bf16* __restrict__ A1l,
      int ksplit, int lda0, int lda1,
      const bf16* __restrict__ Bh, const bf16* __restrict__ Bl, int ldb,
      float* __restrict__ Cf,
      bf16* __restrict__ Ph, bf16* __restrict__ Pl, int ldc,
      const float* __restrict__ bias, const float* __restrict__ res,
      int Kk, int Hdiv,
      long long zaB, long long zaH, long long zbB, long long zbH,
      long long zcB, long long zcH, float scale)
{
    constexpr int BM = 128, BK = 32;
    constexpr int STR = 80;
    constexpr int ASZ = BM*STR, BSZ = BN*STR;
    constexpr int STAGE = 2*ASZ + 2*BSZ;
    constexpr int TWN = BN/2, FN = TWN/8;

    extern __shared__ char sm[];
    int tid = threadIdx.x, lane = tid & 31, warp = tid >> 5;
    int wm = warp & 3, wn = warp >> 2;
    int g = lane >> 2, t4 = lane & 3;

    int z = blockIdx.z, zb = z / Hdiv, zh = z - zb*Hdiv;
    long long aoff = zb*zaB + zh*zaH, boff = zb*zbB + zh*zbH, coff = zb*zcB + zh*zcH;
    A0h += aoff; A0l += aoff; A1h += aoff; A1l += aoff;
    Bh  += boff; Bl  += boff;
    if (OUTF) Cf += coff;
    if (OUTP){ Ph += coff; Pl += coff; }
    if (EPI == 3) res += coff;
    int m0 = blockIdx.y*BM, n0 = blockIdx.x*BN;

    int arow = ((lane>>3)&1)*8 + (lane&7);
    int akc  = (lane>>4)*8;
    int brow = (lane>>4)*8 + (lane&7);
    int bkc  = ((lane>>3)&1)*8;

    float acc[2][FN][4];
    #pragma unroll
    for (int i=0;i<2;i++)
        #pragma unroll
        for (int j=0;j<FN;j++)
            #pragma unroll
            for (int q=0;q<4;q++) acc[i][j][q] = 0.f;

    u32 smbase = smem_u32(sm);
    int nch = Kk / BK;

    auto load_stage = [&](int ch, int s){
        int kg = ch*BK;
        const bf16 *pAh, *pAl; long long la;
        if (kg < ksplit){ pAh = A0h + (size_t)m0*lda0 + kg;          pAl = A0l + (size_t)m0*lda0 + kg;          la = lda0; }
        else            { pAh = A1h + (size_t)m0*lda1 + (kg-ksplit); pAl = A1l + (size_t)m0*lda1 + (kg-ksplit); la = lda1; }
        u32 sa = smbase + s*STAGE;
        #pragma unroll
        for (int it=0; it<BM*4/256; it++){
            int idx = it*256 + tid, r = idx>>2, c = idx&3;
            CP16(sa + r*STR + c*16,        pAh + (size_t)r*la + c*8);
            CP16(sa + ASZ + r*STR + c*16,  pAl + (size_t)r*la + c*8);
        }
        u32 sb = sa + 2*ASZ;
        const bf16* pBh = Bh + (size_t)n0*ldb + kg;
        const bf16* pBl = Bl + (size_t)n0*ldb + kg;
        #pragma unroll
        for (int it=0; it<BN*4/256 || it<1; it++){
            int idx = it*256 + tid, r = idx>>2, c = idx&3;
            if (BN*4 >= 256 || idx < BN*4){
                CP16(sb + r*STR + c*16,        pBh + (size_t)r*ldb + c*8);
                CP16(sb + BSZ + r*STR + c*16,  pBl + (size_t)r*ldb + c*8);
            }
        }
    };

    load_stage(0, 0); CP_COMMIT();

    for (int ch = 0; ch < nch; ch++){
        int s = ch & 1;
        if (ch+1 < nch){ load_stage(ch+1, (ch+1)&1); CP_COMMIT(); CP_WAIT1(); }
        else CP_WAIT0();
        __syncthreads();

        u32 sa = smbase + s*STAGE;
        u32 sAh = sa, sAl = sa + ASZ, sBh = sa + 2*ASZ, sBl = sa + 2*ASZ + BSZ;
        #pragma unroll
        for (int kk=0; kk<BK; kk+=16){
            u32 ah[2][4], al[2][4], bh[FN][2], bl[FN][2];
            #pragma unroll
            for (int fm=0; fm<2; fm++){
                u32 ra = (wm*32 + fm*16 + arow)*STR + (kk + akc)*2;
                ldsm_x4(ah[fm], sAh + ra);
                ldsm_x4(al[fm], sAl + ra);
            }
            #pragma unroll
            for (int fp=0; fp<FN/2; fp++){
                u32 rb = (wn*TWN + fp*16 + brow)*STR + (kk + bkc)*2;
                u32 t[4];
                ldsm_x4(t, sBh + rb);
                bh[2*fp][0]=t[0]; bh[2*fp][1]=t[1]; bh[2*fp+1][0]=t[2]; bh[2*fp+1][1]=t[3];
                ldsm_x4(t, sBl + rb);
                bl[2*fp][0]=t[0]; bl[2*fp][1]=t[1]; bl[2*fp+1][0]=t[2]; bl[2*fp+1][1]=t[3];
            }
            #pragma unroll
            for (int fm=0; fm<2; fm++)
                #pragma unroll
                for (int fn=0; fn<FN; fn++){
                    mma16816(acc[fm][fn], ah[fm], bh[fn]);
                    mma16816(acc[fm][fn], ah[fm], bl[fn]);
                    mma16816(acc[fm][fn], al[fm], bh[fn]);
                }
        }
        __syncthreads();
    }

    #pragma unroll
    for (int fm=0; fm<2; fm++){
        #pragma unroll
        for (int fn=0; fn<FN; fn++){
            int col = n0 + wn*TWN + fn*8 + 2*t4;
            #pragma unroll
            for (int half=0; half<2; half++){
                int row = m0 + wm*32 + fm*16 + g + half*8;
                float v0 = acc[fm][fn][2*half+0]*scale;
                float v1 = acc[fm][fn][2*half+1]*scale;
                if (EPI >= 1){ v0 += bias[col]; v1 += bias[col+1]; }
                if (EPI == 2){
                    v0 = 0.5f*v0*(1.0f + erff(v0*0.70710678118654752f));
                    v1 = 0.5f*v1*(1.0f + erff(v1*0.70710678118654752f));
                }
                if (EPI == 3){
                    float2 rr = *(const float2*)(res + (size_t)row*ldc + col);
                    v0 += rr.x; v1 += rr.y;
                }
                if (OUTF){ float2 o; o.x=v0; o.y=v1; *(float2*)(Cf + (size_t)row*ldc + col) = o; }
                if (OUTP){
                    u32 hp, lp; pksplit(v0, v1, hp, lp);
                    *(u32*)(Ph + (size_t)row*ldc + col) = hp;
                    *(u32*)(Pl + (size_t)row*ldc + col) = lp;
                }
            }
        }
    }
}

// ------------------------- flash attention (fused) ---------------------------
// Per CTA: one (b,h), 64 query rows, 4 warps x 16 rows, 128 threads.
// 64-key double-buffered chunks; 3 CTAs/SM (smem 3x73.7KB = 221KB).
// Grid (64, 12) = 768 CTAs -> 1.73 waves at 444 capacity (86.5% tail eff
// vs 65% for the old 384-CTA config). Online softmax in log2 domain.
__global__ void __launch_bounds__(128,3)
flash_attn(void){
    constexpr int KSTR=144, VSTR=144;
    constexpr int KSZ=64*KSTR, VSZ=64*VSTR;   // 9216 each
    constexpr int QSZ=64*KSTR;                // 9216 (staging only)
    constexpr int STAGE=2*KSZ+2*VSZ;          // 36864
    const float C = 0.18033688011112042f;     // log2(e)/8
    extern __shared__ char sm[];
    int tid=threadIdx.x, lane=tid&31, w=tid>>5;          // w in 0..3
    int g=lane>>2, t4=lane&3;
    int arow=((lane>>3)&1)*8+(lane&7), akc=(lane>>4)*8;
    int brow=(lane>>4)*8+(lane&7),     bkc=((lane>>3)&1)*8;
    int qblk=blockIdx.x, z=blockIdx.y;
    int b=z/HH, h=z-b*HH;
    const bf16* Qh=g_qh+((size_t)(b*NN+qblk*64))*(3*DD)+h*64;
    const bf16* Ql=g_ql+((size_t)(b*NN+qblk*64))*(3*DD)+h*64;
    const bf16* Kh=g_qh+((size_t)b*NN)*(3*DD)+DD+h*64;
    const bf16* Kl=g_ql+((size_t)b*NN)*(3*DD)+DD+h*64;
    const bf16* Vh=g_vth+(size_t)z*64*NN;
    const bf16* Vl=g_vtl+(size_t)z*64*NN;
    u32 smb=smem_u32(sm);

    // ---- load Q tile (64 rows x 128 B) into smem transiently, to regs ----
    #pragma unroll
    for(int it=0; it<4; it++){
        int idx=it*128+tid, r=idx>>3, c=idx&7;
        CP16(smb + r*KSTR + c*16,       Qh + (size_t)r*(3*DD) + c*8);
        CP16(smb + QSZ + r*KSTR + c*16, Ql + (size_t)r*(3*DD) + c*8);
    }
    CP_COMMIT(); CP_WAIT0(); __syncthreads();
    u32 qha[4][4], qla[4][4];
    #pragma unroll
    for(int kk=0;kk<4;kk++){
        u32 ra=(w*16+arow)*KSTR+(kk*16+akc)*2;
        ldsm_x4(qha[kk], smb+ra);
        ldsm_x4(qla[kk], smb+QSZ+ra);
    }
    __syncthreads();

    auto load_kv=[&](int kt,int s){
        u32 sa=smb+(u32)s*STAGE;
        #pragma unroll
        for(int it=0;it<4;it++){
            int idx=it*128+tid, r=idx>>3, c=idx&7;
            CP16(sa + r*KSTR + c*16,       Kh + (size_t)(kt*64+r)*(3*DD) + c*8);
            CP16(sa + KSZ + r*KSTR + c*16, Kl + (size_t)(kt*64+r)*(3*DD) + c*8);
        }
        u32 sv=sa+2*KSZ;
        #pragma unroll
        for(int it=0;it<4;it++){
            int idx=it*128+tid, r=idx>>3, c=idx&7;
            CP16(sv + r*VSTR + c*16,       Vh + (size_t)r*NN + kt*64 + c*8);
            CP16(sv + VSZ + r*VSTR + c*16, Vl + (size_t)r*NN + kt*64 + c*8);
        }
    };

    float o[8][4];
    #pragma unroll
    for(int t=0;t<8;t++){ o[t][0]=0.f; o[t][1]=0.f; o[t][2]=0.f; o[t][3]=0.f; }
    float mA=-1e30f, mB=-1e30f, lA=0.f, lB=0.f;

    load_kv(0,0); CP_COMMIT();

    for(int kt=0; kt<NN/64; kt++){
        int s=kt&1;
        if(kt+1<NN/64){ load_kv(kt+1,s^1); CP_COMMIT(); CP_WAIT1(); } else CP_WAIT0();
        __syncthreads();
        u32 sK=smb+(u32)s*STAGE, sKl=sK+KSZ, sV=sK+2*KSZ, sVl=sV+VSZ;

        // ---- S = Q K^T (64 keys), 3-term split ----
        float sa2[8][4];
        #pragma unroll
        for(int t=0;t<8;t++){ sa2[t][0]=0.f; sa2[t][1]=0.f; sa2[t][2]=0.f; sa2[t][3]=0.f; }
        #pragma unroll
        for(int np=0;np<4;np++){
            #pragma unroll
            for(int kk=0;kk<4;kk++){
                u32 bh[4],bl[4];
                u32 rb=(np*16+brow)*KSTR+(kk*16+bkc)*2;
                ldsm_x4(bh,sK+rb); ldsm_x4(bl,sKl+rb);
                mma16816(sa2[2*np],   qha[kk], bh+0);
                mma16816(sa2[2*np],   qha[kk], bl+0);
                mma16816(sa2[2*np],   qla[kk], bh+0);
                mma16816(sa2[2*np+1], qha[kk], bh+2);
                mma16816(sa2[2*np+1], qha[kk], bl+2);
                mma16816(sa2[2*np+1], qla[kk], bh+2);
            }
        }
        // ---- online softmax (log2 domain, raw-score max) ----
        float mxA=-1e30f, mxB=-1e30f;
        #pragma unroll
        for(int t=0;t<8;t++){
            mxA=fmaxf(mxA,fmaxf(sa2[t][0],sa2[t][1]));
            mxB=fmaxf(mxB,fmaxf(sa2[t][2],sa2[t][3]));
        }
        mxA=fmaxf(mxA,__shfl_xor_sync(0xffffffffu,mxA,1));
        mxA=fmaxf(mxA,__shfl_xor_sync(0xffffffffu,mxA,2));
        mxB=fmaxf(mxB,__shfl_xor_sync(0xffffffffu,mxB,1));
        mxB=fmaxf(mxB,__shfl_xor_sync(0xffffffffu,mxB,2));
        float mAn=fmaxf(mA,mxA), mBn=fmaxf(mB,mxB);
        if (mAn > mA || mBn > mB){
            float scA=ex2((mA-mAn)*C), scB=ex2((mB-mBn)*C);
            lA*=scA; lB*=scB;
            #pragma unroll
            for(int t=0;t<8;t++){ o[t][0]*=scA; o[t][1]*=scA; o[t][2]*=scB; o[t][3]*=scB; }
            mA=mAn; mB=mBn;
        }
        float cA=mA*C, cB=mB*C;
        #pragma unroll
        for(int t=0;t<8;t++){
            sa2[t][0]=ex2(fmaf(sa2[t][0],C,-cA)); sa2[t][1]=ex2(fmaf(sa2[t][1],C,-cA));
            sa2[t][2]=ex2(fmaf(sa2[t][2],C,-cB)); sa2[t][3]=ex2(fmaf(sa2[t][3],C,-cB));
            lA+=sa2[t][0]+sa2[t][1]; lB+=sa2[t][2]+sa2[t][3];
        }
        // ---- O += P V^T, P split in registers (acc layout == A layout) ----
        #pragma unroll
        for(int kk=0;kk<4;kk++){
            u32 pah[4],pal[4];
            pksplit(sa2[2*kk][0],   sa2[2*kk][1],   pah[0], pal[0]);
            pksplit(sa2[2*kk][2],   sa2[2*kk][3],   pah[1], pal[1]);
            pksplit(sa2[2*kk+1][0], sa2[2*kk+1][1], pah[2], pal[2]);
            pksplit(sa2[2*kk+1][2], sa2[2*kk+1][3], pah[3], pal[3]);
            #pragma unroll
            for(int hp=0;hp<4;hp++){
                u32 vh[4],vl[4];
                u32 rb=(hp*16+brow)*VSTR+(kk*16+bkc)*2;
                ldsm_x4(vh,sV+rb); ldsm_x4(vl,sVl+rb);
                mma16816(o[2*hp],   pah, vh+0);
                mma16816(o[2*hp],   pah, vl+0);
                mma16816(o[2*hp],   pal, vh+0);
                mma16816(o[2*hp+1], pah, vh+2);
                mma16816(o[2*hp+1], pah, vl+2);
                mma16816(o[2*hp+1], pal, vh+2);
            }
        }
        __syncthreads();
    }
    lA+=__shfl_xor_sync(0xffffffffu,lA,1); lA+=__shfl_xor_sync(0xffffffffu,lA,2);
    lB+=__shfl_xor_sync(0xffffffffu,lB,1); lB+=__shfl_xor_sync(0xffffffffu,lB,2);
    float iA=1.f/lA, iB=1.f/lB;
    int rowA=qblk*64+w*16+g, rowB=rowA+8;
    bf16* Oh=g_ath+((size_t)b*NN)*DD;
    bf16* Ol=g_atl+((size_t)b*NN)*DD;
    #pragma unroll
    for(int t=0;t<8;t++){
        int col=h*64+t*8+2*t4;
        u32 hp, lp;
        pksplit(o[t][0]*iA, o[t][1]*iA, hp, lp);
        *(u32*)(Oh+(size_t)rowA*DD+col)=hp;
        *(u32*)(Ol+(size_t)rowA*DD+col)=lp;
        pksplit(o[t][2]*iB, o[t][3]*iB, hp, lp);
        *(u32*)(Oh+(size_t)rowB*DD+col)=hp;
        *(u32*)(Ol+(size_t)rowB*DD+col)=lp;
    }
}

// ------------------------------ prep / misc ----------------------------------
__global__ void copy_coords(const float* __restrict__ pts, float* __restrict__ outp){
    int i = blockIdx.x*blockDim.x + threadIdx.x;
    if (i < BB*3*NN){
        int b = i / (3*NN), r = i % (3*NN);
        outp[(size_t)b*CH*NN + r] = pts[(size_t)b*CH*NN + r];
    }
}
__global__ void prep_kernel(const float* __restrict__ knn_w, const float* __restrict__ knn_b){
    int i = blockIdx.x*blockDim.x + threadIdx.x;
    if (i < DD*2*DD){
        int r = i / (2*DD), c = i % (2*DD);
        float v;
        if (c < DD) v = knn_w[r*DD + c];
        else { int cc = c - DD; v = knn_w[(DD + r)*DD + cc] - knn_w[r*DD + cc]; }
        g_wc[i] = v;
    }
    if (i < 2*DD) g_kbias[i] = (i < DD) ? 0.f : knn_b[i-DD];
}
__global__ void sq_kernel(const float* __restrict__ pts){
    int i = blockIdx.x*blockDim.x + threadIdx.x;
    if (i < ROWS){
        int b = i >> 12, n = i & 4095;
        const float* base = pts + (size_t)b*CH*NN;
        float x = base[n], y = base[NN+n], z = base[2*NN+n];
        g_sq[i] = x*x + y*y + z*z;
    }
}
__global__ void wt_conv(const float* __restrict__ W, int K, int N,
                        bf16* __restrict__ oh, bf16* __restrict__ ol){
    __shared__ float t[32][33];
    int k0 = blockIdx.x*32, n0 = blockIdx.y*32;
    for (int r = threadIdx.y; r < 32; r += 8)
        t[r][threadIdx.x] = W[(size_t)(k0+r)*N + n0 + threadIdx.x];
    __syncthreads();
    for (int r = threadIdx.y; r < 32; r += 8){
        float v = t[threadIdx.x][r];
        bf16 h,l; split2(v,h,l);
        size_t o = (size_t)(n0+r)*K + k0 + threadIdx.x;
        oh[o] = h; ol[o] = l;
    }
}
__global__ void vt_conv(void){
    __shared__ bf16 th[32][33], tl[32][33];
    int z = blockIdx.z, b = z / HH, h = z % HH;
    int n0 = blockIdx.x*32, f0 = blockIdx.y*32;
    for (int r = threadIdx.y; r < 32; r += 8){
        size_t src = (size_t)(b*NN + n0 + r)*(3*DD) + 2*DD + h*64 + f0 + threadIdx.x;
        th[r][threadIdx.x] = g_qh[src];
        tl[r][threadIdx.x] = g_ql[src];
    }
    __syncthreads();
    for (int r = threadIdx.y; r < 32; r += 8){
        size_t dst = ((size_t)z*64 + f0 + r)*NN + n0 + threadIdx.x;
        g_vth[dst] = th[threadIdx.x][r];
        g_vtl[dst] = tl[threadIdx.x][r];
    }
}
__global__ void transpose_in(const float* __restrict__ pts, float* __restrict__ dst){
    __shared__ float tile[32][33];
    int b = blockIdx.z, n0 = blockIdx.x*32, d0 = blockIdx.y*32;
    const float* src = pts + (size_t)b*CH*NN;
    for (int r = threadIdx.y; r < 32; r += 8)
        tile[r][threadIdx.x] = src[(size_t)(3+d0+r)*NN + n0 + threadIdx.x];
    __syncthreads();
    float* o = dst + (size_t)b*NN*DD;
    for (int r = threadIdx.y; r < 32; r += 8)
        o[(size_t)(n0+r)*DD + d0 + threadIdx.x] = tile[threadIdx.x][r];
}
__global__ void transpose_out(const float* __restrict__ fin, float* __restrict__ outp){
    __shared__ float tile[32][33];
    int b = blockIdx.z, n0 = blockIdx.x*32, d0 = blockIdx.y*32;
    const float* src = fin + (size_t)b*NN*DD;
    for (int r = threadIdx.y; r < 32; r += 8)
        tile[r][threadIdx.x] = src[(size_t)(n0+r)*DD + d0 + threadIdx.x];
    __syncthreads();
    float* dst = outp + (size_t)b*CH*NN;
    for (int r = threadIdx.y; r < 32; r += 8)
        dst[(size_t)(3+d0+r)*NN + n0 + threadIdx.x] = tile[threadIdx.x][r];
}
__global__ void ln_rows(const float* __restrict__ in,
                        const float* __restrict__ gam, const float* __restrict__ bet,
                        float* __restrict__ outf,
                        bf16* __restrict__ outh, bf16* __restrict__ outl){
    __shared__ float sb[8];
    int row = blockIdx.x, tid = threadIdx.x;
    const float* x = in + (size_t)row*DD;
    float v[3]; float s = 0.f;
    #pragma unroll
    for (int i=0;i<3;i++){ v[i] = x[tid + i*128]; s += v[i]; }
    s = block_sum(s, sb);
    float mean = s * (1.0f/DD), q = 0.f;
    #pragma unroll
    for (int i=0;i<3;i++){ float c = v[i]-mean; q += c*c; }
    q = block_sum(q, sb);
    float rinv = rsqrtf(q*(1.0f/DD) + 1e-5f);
    #pragma unroll
    for (int i=0;i<3;i++){
        int d = tid + i*128;
        float o = (v[i]-mean)*rinv*gam[d] + bet[d];
        size_t idx = (size_t)row*DD + d;
        if (outf) outf[idx] = o;
        if (outh){ bf16 h,l; split2(o,h,l); outh[idx]=h; outl[idx]=l; }
    }
}
// ------------------------------ KNN (top-8) ----------------------------------
__global__ void __launch_bounds__(256)
knn_kernel(const float* __restrict__ pts){
    __shared__ u64 sk[256*KNN];
    int row = blockIdx.x;
    int b = row >> 12, n = row & 4095;
    const float* base = pts + (size_t)b*CH*NN;
    float qx = base[n], qy = base[NN+n], qz = base[2*NN+n];
    float sqn = g_sq[row];
    const float* sqb = g_sq + (size_t)b*NN;

    u64 key[KNN];
    #pragma unroll
    for (int j=0;j<KNN;j++) key[j] = ~0ull;

    for (int m = threadIdx.x; m < NN; m += 256){
        float d2 = sqn + sqb[m]
                 - 2.0f*(qx*base[m] + qy*base[NN+m] + qz*base[2*NN+m]);
        d2 = fmaxf(d2, 0.0f);
        u64 kk = ((u64)__float_as_uint(d2) << 32) | (unsigned)m;
        if (kk < key[KNN-1]){
            key[KNN-1] = kk;
            #pragma unroll
            for (int j=KNN-1;j>0;j--){
                u64 a = key[j-1], c = key[j];
                key[j-1] = (c < a) ? c : a;
                key[j]   = (c < a) ? a : c;
            }
        }
    }
    #pragma unroll
    for (int j=0;j<KNN;j++) sk[threadIdx.x*KNN+j] = key[j];

    for (int s=128; s>0; s>>=1){
        __syncthreads();
        if ((int)threadIdx.x < s){
            int pa = threadIdx.x*KNN, pb = (threadIdx.x+s)*KNN;
            u64 outk[KNN]; int ia=0, ib=0;
            #pragma unroll
            for (int r=0;r<KNN;r++){
                u64 va = sk[pa+ia], vb = sk[pb+ib];
                if (va <= vb){ outk[r]=va; ia++; } else { outk[r]=vb; ib++; }
            }
            #pragma unroll
            for (int r=0;r<KNN;r++) sk[pa+r] = outk[r];
        }
    }
    __syncthreads();
    if (threadIdx.x < KNN)
        g_idx[(size_t)row*KNN + threadIdx.x] = (int)(unsigned)(sk[threadIdx.x] & 0xffffffffu);
}
// ------------------------- gather + lrelu + max ------------------------------
__global__ void __launch_bounds__(128) geom_kernel(void){
    __shared__ int sidx[KNN];
    int row = blockIdx.x, tid = threadIdx.x;
    int gb = row >> 12;
    if (tid < KNN) sidx[tid] = gb*NN + g_idx[(size_t)row*KNN + tid];
    __syncthreads();
    #pragma unroll
    for (int i=0;i<3;i++){
        int d = tid + i*128;
        float c = g_ka[(size_t)row*(2*DD) + DD + d];
        float mx = -FLT_MAX;
        #pragma unroll
        for (int k=0;k<KNN;k++){
            float v = g_ka[(size_t)sidx[k]*(2*DD) + d] + c;
            v = (v > 0.f) ? v : 0.2f*v;
            mx = fmaxf(mx, v);
        }
        bf16 h,l; split2(mx,h,l);
        g_gh[(size_t)row*DD + d] = h;
        g_gl[(size_t)row*DD + d] = l;
    }
}

// ------------------------------ launch ---------------------------------------
extern "C" void kernel_launch(void* const* d_in, const int* in_sizes, int n_in,
                              void* d_out, int out_size) {
    const float* pts        = (const float*)d_in[0];
    const float* ln1_g      = (const float*)d_in[1];
    const float* ln1_b      = (const float*)d_in[2];
    const float* qkv_w      = (const float*)d_in[3];
    const float* attn_out_w = (const float*)d_in[4];
    const float* attn_out_b = (const float*)d_in[5];
    const float* knn_w      = (const float*)d_in[6];
    const float* knn_b      = (const float*)d_in[7];
    const float* merge_w    = (const float*)d_in[8];
    const float* merge_b    = (const float*)d_in[9];
    const float* ln2_g      = (const float*)d_in[10];
    const float* ln2_b      = (const float*)d_in[11];
    const float* ff1_w      = (const float*)d_in[12];
    const float* ff1_b      = (const float*)d_in[13];
    const float* ff2_w      = (const float*)d_in[14];
    const float* ff2_b      = (const float*)d_in[15];
    float* outp = (float*)d_out;

    #define GSA(v,s) cudaGetSymbolAddress((void**)&v, s)
    float *p_tmp,*p_attnp,*p_ka,*p_m,*p_y,*p_fout,*p_wc,*p_kb;
    bf16 *p_nfh,*p_nfl,*p_qh,*p_ql,*p_vth,*p_vtl,*p_ath,*p_atl;
    bf16 *p_aph,*p_apl,*p_gh,*p_gl,*p_yh,*p_yl,*p_hh,*p_hl;
    bf16 *p_wqh,*p_wql,*p_woh,*p_wol,*p_wch,*p_wcl,*p_wmh,*p_wml,*p_w1h,*p_w1l,*p_w2h,*p_w2l;
    GSA(p_tmp,g_tmp); GSA(p_attnp,g_attnp); GSA(p_ka,g_ka);
    GSA(p_m,g_m); GSA(p_y,g_y); GSA(p_fout,g_fout); GSA(p_wc,g_wc); GSA(p_kb,g_kbias);
    GSA(p_nfh,g_nfh); GSA(p_nfl,g_nfl); GSA(p_qh,g_qh); GSA(p_ql,g_ql);
    GSA(p_vth,g_vth); GSA(p_vtl,g_vtl);
    GSA(p_ath,g_ath); GSA(p_atl,g_atl); GSA(p_aph,g_aph); GSA(p_apl,g_apl);
    GSA(p_gh,g_gh); GSA(p_gl,g_gl); GSA(p_yh,g_yh); GSA(p_yl,g_yl);
    GSA(p_hh,g_hh); GSA(p_hl,g_hl);
    GSA(p_wqh,g_wqh); GSA(p_wql,g_wql); GSA(p_woh,g_woh); GSA(p_wol,g_wol);
    GSA(p_wch,g_wch); GSA(p_wcl,g_wcl); GSA(p_wmh,g_wmh); GSA(p_wml,g_wml);
    GSA(p_w1h,g_w1h); GSA(p_w1l,g_w1l); GSA(p_w2h,g_w2h); GSA(p_w2l,g_w2l);

    const int SM128 = 2*(2*128*80 + 2*128*80);   // 81920
    const int SMFL  = 2*(2*64*144 + 2*64*144);   // 73728
    cudaFuncSetAttribute(hgemm<128,0,false,true>,  cudaFuncAttributeMaxDynamicSharedMemorySize, SM128);
    cudaFuncSetAttribute(hgemm<128,1,true ,true>,  cudaFuncAttributeMaxDynamicSharedMemorySize, SM128);
    cudaFuncSetAttribute(hgemm<128,1,true ,false>, cudaFuncAttributeMaxDynamicSharedMemorySize, SM128);
    cudaFuncSetAttribute(hgemm<128,3,true ,false>, cudaFuncAttributeMaxDynamicSharedMemorySize, SM128);
    cudaFuncSetAttribute(hgemm<128,2,false,true>,  cudaFuncAttributeMaxDynamicSharedMemorySize, SM128);
    cudaFuncSetAttribute(flash_attn, cudaFuncAttributeMaxDynamicSharedMemorySize, SMFL);

    // side streams + fork/join events (created+destroyed every call; capture-safe)
    cudaStream_t s2, s3;
    cudaStreamCreateWithFlags(&s2, cudaStreamNonBlocking);
    cudaStreamCreateWithFlags(&s3, cudaStreamNonBlocking);
    cudaEvent_t eRoot, eNf, eGeom, eW;
    cudaEventCreateWithFlags(&eRoot, cudaEventDisableTiming);
    cudaEventCreateWithFlags(&eNf,   cudaEventDisableTiming);
    cudaEventCreateWithFlags(&eGeom, cudaEventDisableTiming);
    cudaEventCreateWithFlags(&eW,    cudaEventDisableTiming);

    dim3 t328(32,8);
    // ---- main chain (stream 0) ----
    transpose_in<<<dim3(NN/32, DD/32, BB), t328>>>(pts, p_tmp);
    cudaEventRecord(eRoot, 0);
    ln_rows<<<ROWS,128>>>(p_tmp, ln1_g, ln1_b, nullptr, p_nfh, p_nfl);
    cudaEventRecord(eNf, 0);
    wt_conv<<<dim3(DD/32, 3*DD/32), t328>>>(qkv_w, DD, 3*DD, p_wqh, p_wql);
    hgemm<128,0,false,true><<<dim3(9,64,1),256,SM128>>>(                  // QKV
        p_nfh,p_nfl,p_nfh,p_nfl, DD, DD, DD,
        p_wqh,p_wql, DD,
        nullptr, p_qh,p_ql, 3*DD, nullptr,nullptr,
        DD, 1, 0,0, 0,0, 0,0, 1.0f);
    vt_conv<<<dim3(NN/32, 2, BB*HH), t328>>>();
    flash_attn<<<dim3(NN/64, BB*HH),128,SMFL>>>();

    // ---- s3: weight-plane converts (overlap with flash) ----
    cudaStreamWaitEvent(s3, eRoot, 0);
    wt_conv<<<dim3(DD/32, DD/32),   t328, 0, s3>>>(attn_out_w, DD, DD,   p_woh, p_wol);
    wt_conv<<<dim3(2*DD/32, DD/32), t328, 0, s3>>>(merge_w,  2*DD, DD,   p_wmh, p_wml);
    wt_conv<<<dim3(DD/32, 2*DD/32), t328, 0, s3>>>(ff1_w,      DD, 2*DD, p_w1h, p_w1l);
    wt_conv<<<dim3(2*DD/32, DD/32), t328, 0, s3>>>(ff2_w,    2*DD, DD,   p_w2h, p_w2l);
    cudaEventRecord(eW, s3);

    // ---- s2: KNN branch (overlap with flash) ----
    cudaStreamWaitEvent(s2, eRoot, 0);
    prep_kernel<<<(DD*2*DD+255)/256,256,0,s2>>>(knn_w, knn_b);
    wt_conv<<<dim3(DD/32, 2*DD/32), t328, 0, s2>>>(p_wc, DD, 2*DD, p_wch, p_wcl);
    sq_kernel<<<(ROWS+255)/256,256,0,s2>>>(pts);
    knn_kernel<<<ROWS,256,0,s2>>>(pts);
    cudaStreamWaitEvent(s2, eNf, 0);
    hgemm<128,1,true,false><<<dim3(6,64,1),256,SM128,s2>>>(
        p_nfh,p_nfl,p_nfh,p_nfl, DD, DD, DD,
        p_wch,p_wcl, DD,
        p_ka, nullptr,nullptr, 2*DD, p_kb,nullptr,
        DD, 1, 0,0, 0,0, 0,0, 1.0f);
    geom_kernel<<<ROWS,128,0,s2>>>();
    cudaEventRecord(eGeom, s2);

    // ---- main chain continues ----
    cudaStreamWaitEvent(0, eW, 0);
    hgemm<128,1,true,true><<<dim3(3,64,1),256,SM128>>>(                   // proj
        p_ath,p_atl,p_ath,p_atl, DD, DD, DD,
        p_woh,p_wol, DD,
        p_attnp, p_aph,p_apl, DD, attn_out_b,nullptr,
        DD, 1, 0,0, 0,0, 0,0, 1.0f);
    cudaStreamWaitEvent(0, eGeom, 0);
    hgemm<128,3,true,false><<<dim3(3,64,1),256,SM128>>>(                  // merge
        p_aph,p_apl, p_gh,p_gl, DD, DD, DD,
        p_wmh,p_wml, 2*DD,
        p_m, nullptr,nullptr, DD, merge_b, p_attnp,
        2*DD, 1, 0,0, 0,0, 0,0, 1.0f);
    ln_rows<<<ROWS,128>>>(p_m, ln2_g, ln2_b, p_y, p_yh, p_yl);
    hgemm<128,2,false,true><<<dim3(6,64,1),256,SM128>>>(                  // ff1
        p_yh,p_yl,p_yh,p_yl, DD, DD, DD,
        p_w1h,p_w1l, DD,
        nullptr, p_hh,p_hl, 2*DD, ff1_b,nullptr,
        DD, 1, 0,0, 0,0, 0,0, 1.0f);
    hgemm<128,3,true,false><<<dim3(3,64,1),256,SM128>>>(                  // ff2
        p_hh,p_hl,p_hh,p_hl, 2*DD, 2*DD, 2*DD,
        p_w2h,p_w2l, 2*DD,
        p_fout, nullptr,nullptr, DD, ff2_b, p_y,
        2*DD, 1, 0,0, 0,0, 0,0, 1.0f);

    copy_coords<<<(BB*3*NN+255)/256,256>>>(pts, outp);
    transpose_out<<<dim3(NN/32, DD/32, BB), t328>>>(p_fout, outp);

    cudaEventDestroy(eRoot); cudaEventDestroy(eNf);
    cudaEventDestroy(eGeom); cudaEventDestroy(eW);
    cudaStreamDestroy(s2); cudaStreamDestroy(s3);
}

// round 16
// speedup vs baseline: 3.0845x; 1.0986x over previous
#include <cuda_runtime.h>
#include <cuda_bf16.h>
#include <float.h>
#include <math.h>
#include <stdint.h>

#define BB   2
#define NN   4096
#define DD   384
#define HH   6
#define KNN  8
#define CH   387
#define ROWS (BB*NN)

typedef unsigned long long u64;
typedef unsigned int u32;
typedef __nv_bfloat16 bf16;

// ------------------------- scratch (static device mem) ----------------------
__device__ float g_tmp  [ROWS*DD];
__device__ bf16  g_nfh  [ROWS*DD];
__device__ bf16  g_nfl  [ROWS*DD];
__device__ bf16  g_qh   [ROWS*3*DD];
__device__ bf16  g_ql   [ROWS*3*DD];
__device__ bf16  g_ath  [ROWS*DD];
__device__ bf16  g_atl  [ROWS*DD];
__device__ float g_ka   [ROWS*2*DD];
__device__ bf16  g_gh   [ROWS*DD];
__device__ bf16  g_gl   [ROWS*DD];
__device__ float g_m    [ROWS*DD];
__device__ float g_y    [ROWS*DD];
__device__ bf16  g_yh   [ROWS*DD];
__device__ bf16  g_yl   [ROWS*DD];
__device__ bf16  g_hh   [ROWS*2*DD];
__device__ bf16  g_hl   [ROWS*2*DD];
__device__ float g_fout [ROWS*DD];
__device__ float g_wc   [DD*2*DD];
__device__ float g_kbias[2*DD];
__device__ float g_b1   [DD];
__device__ float g_sq   [ROWS];
__device__ int   g_idx  [ROWS*KNN];
// split weights
__device__ bf16  g_wqh[3*DD*DD], g_wql[3*DD*DD];
__device__ bf16  g_woh[DD*DD],   g_wol[DD*DD];     // Wo planes, NON-transposed [k][j]
__device__ bf16  g_wih[DD*DD],   g_wil[DD*DD];     // (Wm_top + I)^T planes
__device__ bf16  g_wch[2*DD*DD], g_wcl[2*DD*DD];
__device__ bf16  g_wmh[2*DD*DD], g_wml[2*DD*DD];   // fused merge B: [W1' ; Wm_bot]^T planes
__device__ bf16  g_w1h[2*DD*DD], g_w1l[2*DD*DD];
__device__ bf16  g_w2h[2*DD*DD], g_w2l[2*DD*DD];

// ------------------------------ helpers -------------------------------------
__device__ __forceinline__ void split2(float v, bf16& h, bf16& l){
    h = __float2bfloat16(v);
    l = __float2bfloat16(v - __bfloat162float(h));
}
__device__ __forceinline__ u32 pk(bf16 a, bf16 b){
    return ((u32)__bfloat16_as_ushort(b) << 16) | (u32)__bfloat16_as_ushort(a);
}
__device__ __forceinline__ void pksplit(float f0, float f1, u32& hp, u32& lp){
    asm("cvt.rn.bf16x2.f32 %0, %1, %2;" : "=r"(hp) : "f"(f1), "f"(f0));
    float h0 = __uint_as_float(hp << 16);
    float h1 = __uint_as_float(hp & 0xffff0000u);
    asm("cvt.rn.bf16x2.f32 %0, %1, %2;" : "=r"(lp) : "f"(f1 - h1), "f"(f0 - h0));
}
__device__ __forceinline__ float ex2(float x){
    float r; asm("ex2.approx.f32 %0, %1;" : "=f"(r) : "f"(x)); return r;
}
__device__ __forceinline__ float block_sum(float v, float* sb){
    #pragma unroll
    for (int o=16;o>0;o>>=1) v += __shfl_xor_sync(0xffffffffu, v, o);
    int lane = threadIdx.x & 31, w = threadIdx.x >> 5, nw = blockDim.x >> 5;
    if (lane==0) sb[w] = v;
    __syncthreads();
    if (w==0){
        float x = (lane < nw) ? sb[lane] : 0.f;
        #pragma unroll
        for (int o=16;o>0;o>>=1) x += __shfl_xor_sync(0xffffffffu, x, o);
        if (lane==0) sb[0] = x;
    }
    __syncthreads();
    float r = sb[0]; __syncthreads(); return r;
}
__device__ __forceinline__ u32 smem_u32(const void* p){
    u32 a;
    asm("{ .reg .u64 t; cvta.to.shared.u64 t, %1; cvt.u32.u64 %0, t; }" : "=r"(a) : "l"(p));
    return a;
}
__device__ __forceinline__ void mma16816(float* c, const u32* a, const u32* b){
    asm volatile(
        "mma.sync.aligned.m16n8k16.row.col.f32.bf16.bf16.f32 "
        "{%0,%1,%2,%3}, {%4,%5,%6,%7}, {%8,%9}, {%0,%1,%2,%3};"
        : "+f"(c[0]), "+f"(c[1]), "+f"(c[2]), "+f"(c[3])
        : "r"(a[0]), "r"(a[1]), "r"(a[2]), "r"(a[3]), "r"(b[0]), "r"(b[1]));
}
__device__ __forceinline__ void ldsm_x4(u32* r, u32 addr){
    asm volatile("ldmatrix.sync.aligned.m8n8.x4.shared.b16 {%0,%1,%2,%3}, [%4];"
        : "=r"(r[0]), "=r"(r[1]), "=r"(r[2]), "=r"(r[3]) : "r"(addr));
}
__device__ __forceinline__ void ldsm_x4t(u32* r, u32 addr){
    asm volatile("ldmatrix.sync.aligned.m8n8.x4.trans.shared.b16 {%0,%1,%2,%3}, [%4];"
        : "=r"(r[0]), "=r"(r[1]), "=r"(r[2]), "=r"(r[3]) : "r"(addr));
}
#define CP16(dst,src) asm volatile("cp.async.cg.shared.global [%0], [%1], 16;" :: "r"(dst), "l"(src))
#define CP_COMMIT()   asm volatile("cp.async.commit_group;" ::: "memory")
#define CP_WAIT1()    asm volatile("cp.async.wait_group 1;" ::: "memory")
#define CP_WAIT0()    asm volatile("cp.async.wait_group 0;" ::: "memory")

// --------------- HMMA split-precision GEMM (bf16 planes in, fused epi) -------
template<int BN,int EPI,bool OUTF,bool OUTP>
__global__ void __launch_bounds__(256,2)
hgemm(const bf16* __restrict__ A0h, const bf16* __restrict__ A0l,
      const bf16* __restrict__ A1h, const bf16* __restrict__ A1l,
      int ksplit, int lda0, int lda1,
      const bf16* __restrict__ Bh, const bf16* __restrict__ Bl, int ldb,
      float* __restrict__ Cf,
      bf16* __restrict__ Ph, bf16* __restrict__ Pl, int ldc,
      const float* __restrict__ bias, const float* __restrict__ res,
      int Kk, int Hdiv,
      long long zaB, long long zaH, long long zbB, long long zbH,
      long long zcB, long long zcH, float scale)
{
    constexpr int BM = 128, BK = 32;
    constexpr int STR = 80;
    constexpr int ASZ = BM*STR, BSZ = BN*STR;
    constexpr int STAGE = 2*ASZ + 2*BSZ;
    constexpr int TWN = BN/2, FN = TWN/8;

    extern __shared__ char sm[];
    int tid = threadIdx.x, lane = tid & 31, warp = tid >> 5;
    int wm = warp & 3, wn = warp >> 2;
    int g = lane >> 2, t4 = lane & 3;

    int z = blockIdx.z, zb = z / Hdiv, zh = z - zb*Hdiv;
    long long aoff = zb*zaB + zh*zaH, boff = zb*zbB + zh*zbH, coff = zb*zcB + zh*zcH;
    A0h += aoff; A0l += aoff; A1h += aoff; A1l += aoff;
    Bh  += boff; Bl  += boff;
    if (OUTF) Cf += coff;
    if (OUTP){ Ph += coff; Pl += coff; }
    if (EPI == 3) res += coff;
    int m0 = blockIdx.y*BM, n0 = blockIdx.x*BN;

    int arow = ((lane>>3)&1)*8 + (lane&7);
    int akc  = (lane>>4)*8;
    int brow = (lane>>4)*8 + (lane&7);
    int bkc  = ((lane>>3)&1)*8;

    float acc[2][FN][4];
    #pragma unroll
    for (int i=0;i<2;i++)
        #pragma unroll
        for (int j=0;j<FN;j++)
            #pragma unroll
            for (int q=0;q<4;q++) acc[i][j][q] = 0.f;

    u32 smbase = smem_u32(sm);
    int nch = Kk / BK;

    auto load_stage = [&](int ch, int s){
        int kg = ch*BK;
        const bf16 *pAh, *pAl; long long la;
        if (kg < ksplit){ pAh = A0h + (size_t)m0*lda0 + kg;          pAl = A0l + (size_t)m0*lda0 + kg;          la = lda0; }
        else            { pAh = A1h + (size_t)m0*lda1 + (kg-ksplit); pAl = A1l + (size_t)m0*lda1 + (kg-ksplit); la = lda1; }
        u32 sa = smbase + s*STAGE;
        #pragma unroll
        for (int it=0; it<BM*4/256; it++){
            int idx = it*256 + tid, r = idx>>2, c = idx&3;
            CP16(sa + r*STR + c*16,        pAh + (size_t)r*la + c*8);
            CP16(sa + ASZ + r*STR + c*16,  pAl + (size_t)r*la + c*8);
        }
        u32 sb = sa + 2*ASZ;
        const bf16* pBh = Bh + (size_t)n0*ldb + kg;
        const bf16* pBl = Bl + (size_t)n0*ldb + kg;
        #pragma unroll
        for (int it=0; it<BN*4/256 || it<1; it++){
            int idx = it*256 + tid, r = idx>>2, c = idx&3;
            if (BN*4 >= 256 || idx < BN*4){
                CP16(sb + r*STR + c*16,        pBh + (size_t)r*ldb + c*8);
                CP16(sb + BSZ + r*STR + c*16,  pBl + (size_t)r*ldb + c*8);
            }
        }
    };

    load_stage(0, 0); CP_COMMIT();

    for (int ch = 0; ch < nch; ch++){
        int s = ch & 1;
        if (ch+1 < nch){ load_stage(ch+1, (ch+1)&1); CP_COMMIT(); CP_WAIT1(); }
        else CP_WAIT0();
        __syncthreads();

        u32 sa = smbase + s*STAGE;
        u32 sAh = sa, sAl = sa + ASZ, sBh = sa + 2*ASZ, sBl = sa + 2*ASZ + BSZ;
        #pragma unroll
        for (int kk=0; kk<BK; kk+=16){
            u32 ah[2][4], al[2][4], bh[FN][2], bl[FN][2];
            #pragma unroll
            for (int fm=0; fm<2; fm++){
                u32 ra = (wm*32 + fm*16 + arow)*STR + (kk + akc)*2;
                ldsm_x4(ah[fm], sAh + ra);
                ldsm_x4(al[fm], sAl + ra);
            }
            #pragma unroll
            for (int fp=0; fp<FN/2; fp++){
                u32 rb = (wn*TWN + fp*16 + brow)*STR + (kk + bkc)*2;
                u32 t[4];
                ldsm_x4(t, sBh + rb);
                bh[2*fp][0]=t[0]; bh[2*fp][1]=t[1]; bh[2*fp+1][0]=t[2]; bh[2*fp+1][1]=t[3];
                ldsm_x4(t, sBl + rb);
                bl[2*fp][0]=t[0]; bl[2*fp][1]=t[1]; bl[2*fp+1][0]=t[2]; bl[2*fp+1][1]=t[3];
            }
            #pragma unroll
            for (int fm=0; fm<2; fm++)
                #pragma unroll
                for (int fn=0; fn<FN; fn++){
                    mma16816(acc[fm][fn], ah[fm], bh[fn]);
                    mma16816(acc[fm][fn], ah[fm], bl[fn]);
                    mma16816(acc[fm][fn], al[fm], bh[fn]);
                }
        }
        __syncthreads();
    }

    #pragma unroll
    for (int fm=0; fm<2; fm++){
        #pragma unroll
        for (int fn=0; fn<FN; fn++){
            int col = n0 + wn*TWN + fn*8 + 2*t4;
            #pragma unroll
            for (int half=0; half<2; half++){
                int row = m0 + wm*32 + fm*16 + g + half*8;
                float v0 = acc[fm][fn][2*half+0]*scale;
                float v1 = acc[fm][fn][2*half+1]*scale;
                if (EPI >= 1){ v0 += bias[col]; v1 += bias[col+1]; }
                if (EPI == 2){
                    v0 = 0.5f*v0*(1.0f + erff(v0*0.70710678118654752f));
                    v1 = 0.5f*v1*(1.0f + erff(v1*0.70710678118654752f));
                }
                if (EPI == 3){
                    float2 rr = *(const float2*)(res + (size_t)row*ldc + col);
                    v0 += rr.x; v1 += rr.y;
                }
                if (OUTF){ float2 o; o.x=v0; o.y=v1; *(float2*)(Cf + (size_t)row*ldc + col) = o; }
                if (OUTP){
                    u32 hp, lp; pksplit(v0, v1, hp, lp);
                    *(u32*)(Ph + (size_t)row*ldc + col) = hp;
                    *(u32*)(Pl + (size_t)row*ldc + col) = lp;
                }
            }
        }
    }
}

// ------------------------- flash attention (fused) ---------------------------
// Per CTA: one (b,h), 64 query rows, 4 warps x 16 rows, 128 threads, 3 CTAs/SM.
// V read row-major straight from qkv planes; PV B-fragments via ldmatrix.trans.
__global__ void __launch_bounds__(128,3)
flash_attn(void){
    constexpr int KSTR=144, VSTR=144;
    constexpr int KSZ=64*KSTR, VSZ=64*VSTR;   // 9216 each
    constexpr int QSZ=64*KSTR;                // staging only
    constexpr int STAGE=2*KSZ+2*VSZ;          // 36864
    const float C = 0.18033688011112042f;     // log2(e)/8
    extern __shared__ char sm[];
    int tid=threadIdx.x, lane=tid&31, w=tid>>5;
    int g=lane>>2, t4=lane&3;
    int arow=((lane>>3)&1)*8+(lane&7), akc=(lane>>4)*8;
    int brow=(lane>>4)*8+(lane&7),     bkc=((lane>>3)&1)*8;
    int krow=((lane>>3)&1)*8+(lane&7), ncol8=(lane>>4)*8;   // trans-ldsm lane map
    int qblk=blockIdx.x, z=blockIdx.y;
    int b=z/HH, h=z-b*HH;
    const bf16* Qh=g_qh+((size_t)(b*NN+qblk*64))*(3*DD)+h*64;
    const bf16* Ql=g_ql+((size_t)(b*NN+qblk*64))*(3*DD)+h*64;
    const bf16* Kh=g_qh+((size_t)b*NN)*(3*DD)+DD+h*64;
    const bf16* Kl=g_ql+((size_t)b*NN)*(3*DD)+DD+h*64;
    const bf16* Vh=g_qh+((size_t)b*NN)*(3*DD)+2*DD+h*64;
    const bf16* Vl=g_ql+((size_t)b*NN)*(3*DD)+2*DD+h*64;
    u32 smb=smem_u32(sm);

    // ---- load Q tile (64 rows x 128 B) into smem transiently, to regs ----
    #pragma unroll
    for(int it=0; it<4; it++){
        int idx=it*128+tid, r=idx>>3, c=idx&7;
        CP16(smb + r*KSTR + c*16,       Qh + (size_t)r*(3*DD) + c*8);
        CP16(smb + QSZ + r*KSTR + c*16, Ql + (size_t)r*(3*DD) + c*8);
    }
    CP_COMMIT(); CP_WAIT0(); __syncthreads();
    u32 qha[4][4], qla[4][4];
    #pragma unroll
    for(int kk=0;kk<4;kk++){
        u32 ra=(w*16+arow)*KSTR+(kk*16+akc)*2;
        ldsm_x4(qha[kk], smb+ra);
        ldsm_x4(qla[kk], smb+QSZ+ra);
    }
    __syncthreads();

    auto load_kv=[&](int kt,int s){
        u32 sa=smb+(u32)s*STAGE;
        #pragma unroll
        for(int it=0;it<4;it++){
            int idx=it*128+tid, r=idx>>3, c=idx&7;
            CP16(sa + r*KSTR + c*16,       Kh + (size_t)(kt*64+r)*(3*DD) + c*8);
            CP16(sa + KSZ + r*KSTR + c*16, Kl + (size_t)(kt*64+r)*(3*DD) + c*8);
        }
        u32 sv=sa+2*KSZ;
        #pragma unroll
        for(int it=0;it<4;it++){
            int idx=it*128+tid, r=idx>>3, c=idx&7;
            CP16(sv + r*VSTR + c*16,       Vh + (size_t)(kt*64+r)*(3*DD) + c*8);
            CP16(sv + VSZ + r*VSTR + c*16, Vl + (size_t)(kt*64+r)*(3*DD) + c*8);
        }
    };

    float o[8][4];
    #pragma unroll
    for(int t=0;t<8;t++){ o[t][0]=0.f; o[t][1]=0.f; o[t][2]=0.f; o[t][3]=0.f; }
    float mA=-1e30f, mB=-1e30f, lA=0.f, lB=0.f;

    load_kv(0,0); CP_COMMIT();

    for(int kt=0; kt<NN/64; kt++){
        int s=kt&1;
        if(kt+1<NN/64){ load_kv(kt+1,s^1); CP_COMMIT(); CP_WAIT1(); } else CP_WAIT0();
        __syncthreads();
        u32 sK=smb+(u32)s*STAGE, sKl=sK+KSZ, sV=sK+2*KSZ, sVl=sV+VSZ;

        // ---- S = Q K^T (64 keys), 3-term split ----
        float sa2[8][4];
        #pragma unroll
        for(int t=0;t<8;t++){ sa2[t][0]=0.f; sa2[t][1]=0.f; sa2[t][2]=0.f; sa2[t][3]=0.f; }
        #pragma unroll
        for(int np=0;np<4;np++){
            #pragma unroll
            for(int kk=0;kk<4;kk++){
                u32 bh[4],bl[4];
                u32 rb=(np*16+brow)*KSTR+(kk*16+bkc)*2;
                ldsm_x4(bh,sK+rb); ldsm_x4(bl,sKl+rb);
                mma16816(sa2[2*np],   qha[kk], bh+0);
                mma16816(sa2[2*np],   qha[kk], bl+0);
                mma16816(sa2[2*np],   qla[kk], bh+0);
                mma16816(sa2[2*np+1], qha[kk], bh+2);
                mma16816(sa2[2*np+1], qha[kk], bl+2);
                mma16816(sa2[2*np+1], qla[kk], bh+2);
            }
        }
        // ---- online softmax (log2 domain, raw-score max) ----
        float mxA=-1e30f, mxB=-1e30f;
        #pragma unroll
        for(int t=0;t<8;t++){
            mxA=fmaxf(mxA,fmaxf(sa2[t][0],sa2[t][1]));
            mxB=fmaxf(mxB,fmaxf(sa2[t][2],sa2[t][3]));
        }
        mxA=fmaxf(mxA,__shfl_xor_sync(0xffffffffu,mxA,1));
        mxA=fmaxf(mxA,__shfl_xor_sync(0xffffffffu,mxA,2));
        mxB=fmaxf(mxB,__shfl_xor_sync(0xffffffffu,mxB,1));
        mxB=fmaxf(mxB,__shfl_xor_sync(0xffffffffu,mxB,2));
        float mAn=fmaxf(mA,mxA), mBn=fmaxf(mB,mxB);
        if (mAn > mA || mBn > mB){
            float scA=ex2((mA-mAn)*C), scB=ex2((mB-mBn)*C);
            lA*=scA; lB*=scB;
            #pragma unroll
            for(int t=0;t<8;t++){ o[t][0]*=scA; o[t][1]*=scA; o[t][2]*=scB; o[t][3]*=scB; }
            mA=mAn; mB=mBn;
        }
        float cA=mA*C, cB=mB*C;
        #pragma unroll
        for(int t=0;t<8;t++){
            sa2[t][0]=ex2(fmaf(sa2[t][0],C,-cA)); sa2[t][1]=ex2(fmaf(sa2[t][1],C,-cA));
            sa2[t][2]=ex2(fmaf(sa2[t][2],C,-cB)); sa2[t][3]=ex2(fmaf(sa2[t][3],C,-cB));
            lA+=sa2[t][0]+sa2[t][1]; lB+=sa2[t][2]+sa2[t][3];
        }
        // ---- O += P V^T, V fragments via ldmatrix.trans on row-major V ----
        #pragma unroll
        for(int kk=0;kk<4;kk++){
            u32 pah[4],pal[4];
            pksplit(sa2[2*kk][0],   sa2[2*kk][1],   pah[0], pal[0]);
            pksplit(sa2[2*kk][2],   sa2[2*kk][3],   pah[1], pal[1]);
            pksplit(sa2[2*kk+1][0], sa2[2*kk+1][1], pah[2], pal[2]);
            pksplit(sa2[2*kk+1][2], sa2[2*kk+1][3], pah[3], pal[3]);
            #pragma unroll
            for(int hp=0;hp<4;hp++){
                u32 vh[4],vl[4];
                u32 rb=(kk*16+krow)*VSTR+(hp*16+ncol8)*2;
                ldsm_x4t(vh,sV+rb); ldsm_x4t(vl,sVl+rb);
                mma16816(o[2*hp],   pah, vh+0);
                mma16816(o[2*hp],   pah, vl+0);
                mma16816(o[2*hp],   pal, vh+0);
                mma16816(o[2*hp+1], pah, vh+2);
                mma16816(o[2*hp+1], pah, vl+2);
                mma16816(o[2*hp+1], pal, vh+2);
            }
        }
        __syncthreads();
    }
    lA+=__shfl_xor_sync(0xffffffffu,lA,1); lA+=__shfl_xor_sync(0xffffffffu,lA,2);
    lB+=__shfl_xor_sync(0xffffffffu,lB,1); lB+=__shfl_xor_sync(0xffffffffu,lB,2);
    float iA=1.f/lA, iB=1.f/lB;
    int rowA=qblk*64+w*16+g, rowB=rowA+8;
    bf16* Oh=g_ath+((size_t)b*NN)*DD;
    bf16* Ol=g_atl+((size_t)b*NN)*DD;
    #pragma unroll
    for(int t=0;t<8;t++){
        int col=h*64+t*8+2*t4;
        u32 hp, lp;
        pksplit(o[t][0]*iA, o[t][1]*iA, hp, lp);
        *(u32*)(Oh+(size_t)rowA*DD+col)=hp;
        *(u32*)(Ol+(size_t)rowA*DD+col)=lp;
        pksplit(o[t][2]*iB, o[t][3]*iB, hp, lp);
        *(u32*)(Oh+(size_t)rowB*DD+col)=hp;
        *(u32*)(Ol+(size_t)rowB*DD+col)=lp;
    }
}

// ------------------------------ prep / misc ----------------------------------
__global__ void copy_coords(const float* __restrict__ pts, float* __restrict__ outp){
    int i = blockIdx.x*blockDim.x + threadIdx.x;
    if (i < BB*3*NN){
        int b = i / (3*NN), r = i % (3*NN);
        outp[(size_t)b*CH*NN + r] = pts[(size_t)b*CH*NN + r];
    }
}
__global__ void prep_kernel(const float* __restrict__ knn_w, const float* __restrict__ knn_b){
    int i = blockIdx.x*blockDim.x + threadIdx.x;
    if (i < DD*2*DD){
        int r = i / (2*DD), c = i % (2*DD);
        float v;
        if (c < DD) v = knn_w[r*DD + c];
        else { int cc = c - DD; v = knn_w[(DD + r)*DD + cc] - knn_w[r*DD + cc]; }
        g_wc[i] = v;
    }
    if (i < 2*DD) g_kbias[i] = (i < DD) ? 0.f : knn_b[i-DD];
}
__global__ void sq_kernel(const float* __restrict__ pts){
    int i = blockIdx.x*blockDim.x + threadIdx.x;
    if (i < ROWS){
        int b = i >> 12, n = i & 4095;
        const float* base = pts + (size_t)b*CH*NN;
        float x = base[n], y = base[NN+n], z = base[2*NN+n];
        g_sq[i] = x*x + y*y + z*z;
    }
}
__global__ void wt_conv(const float* __restrict__ W, int K, int N,
                        bf16* __restrict__ oh, bf16* __restrict__ ol){
    __shared__ float t[32][33];
    int k0 = blockIdx.x*32, n0 = blockIdx.y*32;
    for (int r = threadIdx.y; r < 32; r += 8)
        t[r][threadIdx.x] = W[(size_t)(k0+r)*N + n0 + threadIdx.x];
    __syncthreads();
    for (int r = threadIdx.y; r < 32; r += 8){
        float v = t[threadIdx.x][r];
        bf16 h,l; split2(v,h,l);
        size_t o = (size_t)(n0+r)*K + k0 + threadIdx.x;
        oh[o] = h; ol[o] = l;
    }
}
// elementwise split, NO transpose: out[i] = split(W[i])  (for fusion B = Wo[k][j])
__global__ void wnt_conv(const float* __restrict__ W, int total,
                         bf16* __restrict__ oh, bf16* __restrict__ ol){
    int i = blockIdx.x*blockDim.x + threadIdx.x;
    if (i < total){
        bf16 h,l; split2(W[i],h,l);
        oh[i] = h; ol[i] = l;
    }
}
// (Wm_top + I)^T planes: out[n][k] = Wm[k][n] + (k==n), k,n < 384
__global__ void wtI_conv(const float* __restrict__ W,
                         bf16* __restrict__ oh, bf16* __restrict__ ol){
    __shared__ float t[32][33];
    int k0 = blockIdx.x*32, n0 = blockIdx.y*32;
    for (int r = threadIdx.y; r < 32; r += 8)
        t[r][threadIdx.x] = W[(size_t)(k0+r)*DD + n0 + threadIdx.x];
    __syncthreads();
    for (int r = threadIdx.y; r < 32; r += 8){
        float v = t[threadIdx.x][r];
        if (k0 + (int)threadIdx.x == n0 + r) v += 1.0f;
        bf16 h,l; split2(v,h,l);
        size_t o = (size_t)(n0+r)*DD + k0 + threadIdx.x;
        oh[o] = h; ol[o] = l;
    }
}
// b1'[j] = sum_k bo[k]*Wm[k][j] + bo[j] + bm[j]
__global__ void b1_kernel(const float* __restrict__ bo, const float* __restrict__ bm,
                          const float* __restrict__ Wm){
    int j = blockIdx.x*blockDim.x + threadIdx.x;
    if (j < DD){
        float s = bo[j] + bm[j];
        for (int k = 0; k < DD; k++) s += bo[k] * Wm[(size_t)k*DD + j];
        g_b1[j] = s;
    }
}
__global__ void transpose_in(const float* __restrict__ pts, float* __restrict__ dst){
    __shared__ float tile[32][33];
    int b = blockIdx.z, n0 = blockIdx.x*32, d0 = blockIdx.y*32;
    const float* src = pts + (size_t)b*CH*NN;
    for (int r = threadIdx.y; r < 32; r += 8)
        tile[r][threadIdx.x] = src[(size_t)(3+d0+r)*NN + n0 + threadIdx.x];
    __syncthreads();
    float* o = dst + (size_t)b*NN*DD;
    for (int r = threadIdx.y; r < 32; r += 8)
        o[(size_t)(n0+r)*DD + d0 + threadIdx.x] = tile[threadIdx.x][r];
}
__global__ void transpose_out(const float* __restrict__ fin, float* __restrict__ outp){
    __shared__ float tile[32][33];
    int b = blockIdx.z, n0 = blockIdx.x*32, d0 = blockIdx.y*32;
    const float* src = fin + (size_t)b*NN*DD;
    for (int r = threadIdx.y; r < 32; r += 8)
        tile[r][threadIdx.x] = src[(size_t)(n0+r)*DD + d0 + threadIdx.x];
    __syncthreads();
    float* dst = outp + (size_t)b*CH*NN;
    for (int r = threadIdx.y; r < 32; r += 8)
        dst[(size_t)(3+d0+r)*NN + n0 + threadIdx.x] = tile[threadIdx.x][r];
}
__global__ void ln_rows(const float* __restrict__ in,
                        const float* __restrict__ gam, const float* __restrict__ bet,
                        float* __restrict__ outf,
                        bf16* __restrict__ outh, bf16* __restrict__ outl){
    __shared__ float sb[8];
    int row = blockIdx.x, tid = threadIdx.x;
    const float* x = in + (size_t)row*DD;
    float v[3]; float s = 0.f;
    #pragma unroll
    for (int i=0;i<3;i++){ v[i] = x[tid + i*128]; s += v[i]; }
    s = block_sum(s, sb);
    float mean = s * (1.0f/DD), q = 0.f;
    #pragma unroll
    for (int i=0;i<3;i++){ float c = v[i]-mean; q += c*c; }
    q = block_sum(q, sb);
    float rinv = rsqrtf(q*(1.0f/DD) + 1e-5f);
    #pragma unroll
    for (int i=0;i<3;i++){
        int d = tid + i*128;
        float o = (v[i]-mean)*rinv*gam[d] + bet[d];
        size_t idx = (size_t)row*DD + d;
        if (outf) outf[idx] = o;
        if (outh){ bf16 h,l; split2(o,h,l); outh[idx]=h; outl[idx]=l; }
    }
}
// ------------------------------ KNN (top-8) ----------------------------------
__global__ void __launch_bounds__(256)
knn_kernel(const float* __restrict__ pts){
    __shared__ u64 sk[256*KNN];
    int row = blockIdx.x;
    int b = row >> 12, n = row & 4095;
    const float* base = pts + (size_t)b*CH*NN;
    float qx = base[n], qy = base[NN+n], qz = base[2*NN+n];
    float sqn = g_sq[row];
    const float* sqb = g_sq + (size_t)b*NN;

    u64 key[KNN];
    #pragma unroll
    for (int j=0;j<KNN;j++) key[j] = ~0ull;

    for (int m = threadIdx.x; m < NN; m += 256){
        float d2 = sqn + sqb[m]
                 - 2.0f*(qx*base[m] + qy*base[NN+m] + qz*base[2*NN+m]);
        d2 = fmaxf(d2, 0.0f);
        u64 kk = ((u64)__float_as_uint(d2) << 32) | (unsigned)m;
        if (kk < key[KNN-1]){
            key[KNN-1] = kk;
            #pragma unroll
            for (int j=KNN-1;j>0;j--){
                u64 a = key[j-1], c = key[j];
                key[j-1] = (c < a) ? c : a;
                key[j]   = (c < a) ? a : c;
            }
        }
    }
    #pragma unroll
    for (int j=0;j<KNN;j++) sk[threadIdx.x*KNN+j] = key[j];

    for (int s=128; s>0; s>>=1){
        __syncthreads();
        if ((int)threadIdx.x < s){
            int pa = threadIdx.x*KNN, pb = (threadIdx.x+s)*KNN;
            u64 outk[KNN]; int ia=0, ib=0;
            #pragma unroll
            for (int r=0;r<KNN;r++){
                u64 va = sk[pa+ia], vb = sk[pb+ib];
                if (va <= vb){ outk[r]=va; ia++; } else { outk[r]=vb; ib++; }
            }
            #pragma unroll
            for (int r=0;r<KNN;r++) sk[pa+r] = outk[r];
        }
    }
    __syncthreads();
    if (threadIdx.x < KNN)
        g_idx[(size_t)row*KNN + threadIdx.x] = (int)(unsigned)(sk[threadIdx.x] & 0xffffffffu);
}
// ------------------------- gather + lrelu + max ------------------------------
__global__ void __launch_bounds__(128) geom_kernel(void){
    __shared__ int sidx[KNN];
    int row = blockIdx.x, tid = threadIdx.x;
    int gb = row >> 12;
    if (tid < KNN) sidx[tid] = gb*NN + g_idx[(size_t)row*KNN + tid];
    __syncthreads();
    #pragma unroll
    for (int i=0;i<3;i++){
        int d = tid + i*128;
        float c = g_ka[(size_t)row*(2*DD) + DD + d];
        float mx = -FLT_MAX;
        #pragma unroll
        for (int k=0;k<KNN;k++){
            float v = g_ka[(size_t)sidx[k]*(2*DD) + d] + c;
            v = (v > 0.f) ? v : 0.2f*v;
            mx = fmaxf(mx, v);
        }
        bf16 h,l; split2(mx,h,l);
        g_gh[(size_t)row*DD + d] = h;
        g_gl[(size_t)row*DD + d] = l;
    }
}

// ------------------------------ launch ---------------------------------------
extern "C" void kernel_launch(void* const* d_in, const int* in_sizes, int n_in,
                              void* d_out, int out_size) {
    const float* pts        = (const float*)d_in[0];
    const float* ln1_g      = (const float*)d_in[1];
    const float* ln1_b      = (const float*)d_in[2];
    const float* qkv_w      = (const float*)d_in[3];
    const float* attn_out_w = (const float*)d_in[4];
    const float* attn_out_b = (const float*)d_in[5];
    const float* knn_w      = (const float*)d_in[6];
    const float* knn_b      = (const float*)d_in[7];
    const float* merge_w    = (const float*)d_in[8];
    const float* merge_b    = (const float*)d_in[9];
    const float* ln2_g      = (const float*)d_in[10];
    const float* ln2_b      = (const float*)d_in[11];
    const float* ff1_w      = (const float*)d_in[12];
    const float* ff1_b      = (const float*)d_in[13];
    const float* ff2_w      = (const float*)d_in[14];
    const float* ff2_b      = (const float*)d_in[15];
    float* outp = (float*)d_out;

    #define GSA(v,s) cudaGetSymbolAddress((void**)&v, s)
    float *p_tmp,*p_ka,*p_m,*p_y,*p_fout,*p_wc,*p_kb,*p_b1;
    bf16 *p_nfh,*p_nfl,*p_qh,*p_ql,*p_ath,*p_atl;
    bf16 *p_gh,*p_gl,*p_yh,*p_yl,*p_hh,*p_hl;
    bf16 *p_wqh,*p_wql,*p_woh,*p_wol,*p_wih,*p_wil,*p_wch,*p_wcl,*p_wmh,*p_wml,*p_w1h,*p_w1l,*p_w2h,*p_w2l;
    GSA(p_tmp,g_tmp); GSA(p_ka,g_ka);
    GSA(p_m,g_m); GSA(p_y,g_y); GSA(p_fout,g_fout); GSA(p_wc,g_wc); GSA(p_kb,g_kbias);
    GSA(p_b1,g_b1);
    GSA(p_nfh,g_nfh); GSA(p_nfl,g_nfl); GSA(p_qh,g_qh); GSA(p_ql,g_ql);
    GSA(p_ath,g_ath); GSA(p_atl,g_atl);
    GSA(p_gh,g_gh); GSA(p_gl,g_gl); GSA(p_yh,g_yh); GSA(p_yl,g_yl);
    GSA(p_hh,g_hh); GSA(p_hl,g_hl);
    GSA(p_wqh,g_wqh); GSA(p_wql,g_wql); GSA(p_woh,g_woh); GSA(p_wol,g_wol);
    GSA(p_wih,g_wih); GSA(p_wil,g_wil);
    GSA(p_wch,g_wch); GSA(p_wcl,g_wcl); GSA(p_wmh,g_wmh); GSA(p_wml,g_wml);
    GSA(p_w1h,g_w1h); GSA(p_w1l,g_w1l); GSA(p_w2h,g_w2h); GSA(p_w2l,g_w2l);

    const int SM128 = 2*(2*128*80 + 2*128*80);   // 81920
    const int SMFL  = 2*(2*64*144 + 2*64*144);   // 73728
    cudaFuncSetAttribute(hgemm<128,0,false,true>,  cudaFuncAttributeMaxDynamicSharedMemorySize, SM128);
    cudaFuncSetAttribute(hgemm<128,1,true ,false>, cudaFuncAttributeMaxDynamicSharedMemorySize, SM128);
    cudaFuncSetAttribute(hgemm<128,3,true ,false>, cudaFuncAttributeMaxDynamicSharedMemorySize, SM128);
    cudaFuncSetAttribute(hgemm<128,2,false,true>,  cudaFuncAttributeMaxDynamicSharedMemorySize, SM128);
    cudaFuncSetAttribute(flash_attn, cudaFuncAttributeMaxDynamicSharedMemorySize, SMFL);

    cudaStream_t s2, s3;
    cudaStreamCreateWithFlags(&s2, cudaStreamNonBlocking);
    cudaStreamCreateWithFlags(&s3, cudaStreamNonBlocking);
    cudaEvent_t eRoot, eNf, eGeom, eW;
    cudaEventCreateWithFlags(&eRoot, cudaEventDisableTiming);
    cudaEventCreateWithFlags(&eNf,   cudaEventDisableTiming);
    cudaEventCreateWithFlags(&eGeom, cudaEventDisableTiming);
    cudaEventCreateWithFlags(&eW,    cudaEventDisableTiming);

    dim3 t328(32,8);
    // ---- main chain (stream 0) ----
    transpose_in<<<dim3(NN/32, DD/32, BB), t328>>>(pts, p_tmp);
    cudaEventRecord(eRoot, 0);
    ln_rows<<<ROWS,128>>>(p_tmp, ln1_g, ln1_b, nullptr, p_nfh, p_nfl);
    cudaEventRecord(eNf, 0);
    wt_conv<<<dim3(DD/32, 3*DD/32), t328>>>(qkv_w, DD, 3*DD, p_wqh, p_wql);
    hgemm<128,0,false,true><<<dim3(9,64,1),256,SM128>>>(                  // QKV
        p_nfh,p_nfl,p_nfh,p_nfl, DD, DD, DD,
        p_wqh,p_wql, DD,
        nullptr, p_qh,p_ql, 3*DD, nullptr,nullptr,
        DD, 1, 0,0, 0,0, 0,0, 1.0f);
    flash_attn<<<dim3(NN/64, BB*HH),128,SMFL>>>();

    // ---- s3: weight preps + proj-merge fusion precompute (overlap w/ flash) ----
    cudaStreamWaitEvent(s3, eRoot, 0);
    wnt_conv<<<(DD*DD+255)/256,256,0,s3>>>(attn_out_w, DD*DD, p_woh, p_wol); // Wo NON-transposed
    wt_conv<<<dim3(2*DD/32, DD/32), t328, 0, s3>>>(merge_w,  2*DD, DD,   p_wmh, p_wml);
    wtI_conv<<<dim3(DD/32, DD/32),  t328, 0, s3>>>(merge_w, p_wih, p_wil);
    b1_kernel<<<3,128,0,s3>>>(attn_out_b, merge_b, merge_w);
    // W1' = Wo*(Wm_top+I): C[m][n] = sum_j (Wm+I)[j][m] * Wo[n][j] = W1'[n][m]
    // stored at wm[n'=m][k'=n] -> wm[n'][k'] = W1'[k'][n']  (correct orientation)
    hgemm<128,0,false,true><<<dim3(3,3,1),256,SM128,s3>>>(
        p_wih,p_wil,p_wih,p_wil, DD, DD, DD,
        p_woh,p_wol, DD,
        nullptr, p_wmh,p_wml, 2*DD, nullptr,nullptr,
        DD, 1, 0,0, 0,0, 0,0, 1.0f);
    wt_conv<<<dim3(DD/32, 2*DD/32), t328, 0, s3>>>(ff1_w,      DD, 2*DD, p_w1h, p_w1l);
    wt_conv<<<dim3(2*DD/32, DD/32), t328, 0, s3>>>(ff2_w,    2*DD, DD,   p_w2h, p_w2l);
    cudaEventRecord(eW, s3);

    // ---- s2: KNN branch (overlap with flash) ----
    cudaStreamWaitEvent(s2, eRoot, 0);
    prep_kernel<<<(DD*2*DD+255)/256,256,0,s2>>>(knn_w, knn_b);
    wt_conv<<<dim3(DD/32, 2*DD/32), t328, 0, s2>>>(p_wc, DD, 2*DD, p_wch, p_wcl);
    sq_kernel<<<(ROWS+255)/256,256,0,s2>>>(pts);
    knn_kernel<<<ROWS,256,0,s2>>>(pts);
    cudaStreamWaitEvent(s2, eNf, 0);
    hgemm<128,1,true,false><<<dim3(6,64,1),256,SM128,s2>>>(
        p_nfh,p_nfl,p_nfh,p_nfl, DD, DD, DD,
        p_wch,p_wcl, DD,
        p_ka, nullptr,nullptr, 2*DD, p_kb,nullptr,
        DD, 1, 0,0, 0,0, 0,0, 1.0f);
    geom_kernel<<<ROWS,128,0,s2>>>();
    cudaEventRecord(eGeom, s2);

    // ---- main chain: fused proj+merge(+residual) in ONE GEMM ----
    cudaStreamWaitEvent(0, eW, 0);
    cudaStreamWaitEvent(0, eGeom, 0);
    hgemm<128,1,true,false><<<dim3(3,64,1),256,SM128>>>(
        p_ath,p_atl, p_gh,p_gl, DD, DD, DD,
        p_wmh,p_wml, 2*DD,
        p_m, nullptr,nullptr, DD, p_b1,nullptr,
        2*DD, 1, 0,0, 0,0, 0,0, 1.0f);
    ln_rows<<<ROWS,128>>>(p_m, ln2_g, ln2_b, p_y, p_yh, p_yl);
    hgemm<128,2,false,true><<<dim3(6,64,1),256,SM128>>>(                  // ff1
        p_yh,p_yl,p_yh,p_yl, DD, DD, DD,
        p_w1h,p_w1l, DD,
        nullptr, p_hh,p_hl, 2*DD, ff1_b,nullptr,
        DD, 1, 0,0, 0,0, 0,0, 1.0f);
    hgemm<128,3,true,false><<<dim3(3,64,1),256,SM128>>>(                  // ff2
        p_hh,p_hl,p_hh,p_hl, 2*DD, 2*DD, 2*DD,
        p_w2h,p_w2l, 2*DD,
        p_fout, nullptr,nullptr, DD, ff2_b, p_y,
        2*DD, 1, 0,0, 0,0, 0,0, 1.0f);

    copy_coords<<<(BB*3*NN+255)/256,256>>>(pts, outp);
    transpose_out<<<dim3(NN/32, DD/32, BB), t328>>>(p_fout, outp);

    cudaEventDestroy(eRoot); cudaEventDestroy(eNf);
    cudaEventDestroy(eGeom); cudaEventDestroy(eW);
    cudaStreamDestroy(s2); cudaStreamDestroy(s3);
}